// round 7
// baseline (speedup 1.0000x reference)
#include <cuda_runtime.h>
#include <cstdint>

#define NT 256          // node kernels: threads per block
#define TS 64           // node tile rows
#define LDA 68          // sA row stride (floats) for SIMT gemm
#define ET 128          // edge tile (edges per block)
#define LDE 68          // edge smem row stride (floats)

typedef unsigned long long u64;

__device__ float g_h [50048 * 64];
__device__ float g_x [50048 * 3];
__device__ float g_Ad[50048 * 64];   // h @ e_w1[0:64]   (dst part)
__device__ float g_As[50048 * 64];   // h @ e_w1[64:128] (src part)
__device__ float g_m [50048 * 64];   // segment-sum of m_ij
__device__ float g_dx[50048 * 3];    // segment-sum of W_ij * x_diff

__device__ __forceinline__ float silu_f(float v) {
    return v / (1.0f + __expf(-v));
}
__device__ __forceinline__ u64 pdup(float x) {
    u64 r; asm("mov.b64 %0, {%1, %1};" : "=l"(r) : "f"(x)); return r;
}
__device__ __forceinline__ void up2(u64 v, float& a, float& b) {
    asm("mov.b64 {%0, %1}, %2;" : "=f"(a), "=f"(b) : "l"(v));
}
__device__ __forceinline__ void fma2(u64& c, u64 a, u64 b) {
    asm("fma.rn.f32x2 %0, %1, %2, %0;" : "+l"(c) : "l"(a), "l"(b));
}
__device__ __forceinline__ void red_add_v4(float* p, float a, float b, float c, float d) {
    asm volatile("red.global.add.v4.f32 [%0], {%1, %2, %3, %4};"
                 :: "l"(p), "f"(a), "f"(b), "f"(c), "f"(d) : "memory");
}
__device__ __forceinline__ float tf32f(float x) {
    uint32_t u; asm("cvt.rna.tf32.f32 %0, %1;" : "=r"(u) : "f"(x));
    return __uint_as_float(u);
}
// D(16x8,f32) += A(16x8,tf32,row) * B(8x8,tf32,col)
__device__ __forceinline__ void mma16n8k8(float c[4], const uint32_t a[4],
                                          uint32_t b0, uint32_t b1) {
    asm volatile(
        "mma.sync.aligned.m16n8k8.row.col.f32.tf32.tf32.f32 "
        "{%0,%1,%2,%3}, {%4,%5,%6,%7}, {%8,%9}, {%0,%1,%2,%3};"
        : "+f"(c[0]), "+f"(c[1]), "+f"(c[2]), "+f"(c[3])
        : "r"(a[0]), "r"(a[1]), "r"(a[2]), "r"(a[3]), "r"(b0), "r"(b1));
}

// ===================== SIMT gemm (node kernels, R4-proven) ==================
__device__ __forceinline__ void gemm_t(const float* __restrict__ sA,
                                       const float* __restrict__ sW,
                                       int tx, int ty, u64 acc[4][2]) {
    const float* aR = sA + ty * 4 * LDA;
    const float* bC = sW + tx * 4;
#pragma unroll
    for (int kb = 0; kb < 64; kb += 4) {
        float4 av[4];
#pragma unroll
        for (int i = 0; i < 4; i++)
            av[i] = *(const float4*)(aR + i * LDA + kb);
#pragma unroll
        for (int kk = 0; kk < 4; kk++) {
            ulonglong2 b = *(const ulonglong2*)(bC + (kb + kk) * 64);
#pragma unroll
            for (int i = 0; i < 4; i++) {
                float a = (kk == 0) ? av[i].x : (kk == 1) ? av[i].y
                        : (kk == 2) ? av[i].z : av[i].w;
                u64 aa = pdup(a);
                fma2(acc[i][0], aa, b.x);
                fma2(acc[i][1], aa, b.y);
            }
        }
    }
}

#define ZERO_ACC(acc)                             \
    _Pragma("unroll") for (int i_ = 0; i_ < 4; i_++) { (acc)[i_][0] = 0ull; (acc)[i_][1] = 0ull; }
#define UNPACK_ROW(acc_row, c)  \
    up2((acc_row)[0], (c)[0], (c)[1]); up2((acc_row)[1], (c)[2], (c)[3]);

// ---------------------------------------------------------------------------
__global__ void init_kernel(const int* __restrict__ an,
                            const float* __restrict__ pos,
                            const float* __restrict__ emb, int N) {
    int p = blockIdx.x * blockDim.x + threadIdx.x;
    int nh = N * 64;
    if (p < nh) {
        int n = p >> 6, j = p & 63;
        g_h[p] = emb[an[n] * 64 + j];
    } else if (p < nh + N * 3) {
        g_x[p - nh] = pos[p - nh];
    }
}

// ---------------------------------------------------------------------------
__global__ __launch_bounds__(NT)
void node_pre_kernel(const float* __restrict__ w1, int N) {
    __shared__ float sA[TS * LDA];
    __shared__ float sW[4096];
    int tid = threadIdx.x;
    int n0 = blockIdx.x * TS;
    int tx = tid & 15, ty = tid >> 4;

    for (int p = tid; p < TS * 16; p += NT) {
        int i = p >> 4, j = (p & 15) * 4;
        int n = n0 + i;
        float4 v = make_float4(0.f, 0.f, 0.f, 0.f);
        if (n < N) {
            v = *(const float4*)&g_h[n * 64 + j];
            *(float4*)&g_m[n * 64 + j] = make_float4(0.f, 0.f, 0.f, 0.f);
        }
        *(float4*)&sA[i * LDA + j] = v;
    }
    if (tid < TS * 3) {
        int idx = n0 * 3 + tid;
        if (idx < N * 3) g_dx[idx] = 0.f;
    }
    for (int p = tid; p < 1024; p += NT)
        *(float4*)&sW[p * 4] = *(const float4*)&w1[p * 4];
    __syncthreads();

    u64 acc[4][2];
    ZERO_ACC(acc);
    gemm_t(sA, sW, tx, ty, acc);

#pragma unroll
    for (int i = 0; i < 4; i++) {
        int n = n0 + ty * 4 + i;
        if (n < N) {
            float c[4];
            UNPACK_ROW(acc[i], c);
            *(float4*)&g_Ad[n * 64 + tx * 4] = make_float4(c[0], c[1], c[2], c[3]);
        }
    }
    __syncthreads();
    for (int p = tid; p < 1024; p += NT)
        *(float4*)&sW[p * 4] = *(const float4*)&w1[4096 + p * 4];
    __syncthreads();

    ZERO_ACC(acc);
    gemm_t(sA, sW, tx, ty, acc);

#pragma unroll
    for (int i = 0; i < 4; i++) {
        int n = n0 + ty * 4 + i;
        if (n < N) {
            float c[4];
            UNPACK_ROW(acc[i], c);
            *(float4*)&g_As[n * 64 + tx * 4] = make_float4(c[0], c[1], c[2], c[3]);
        }
    }
}

// ---------------------------------------------------------------------------
// 3xTF32 edge kernel: 128 edges/block, 128 threads (4 warps x 32 rows).
// Inputs split hi/lo: D = Ah*Bh + Ah*Bl + Al*Bh  (error ~2^-22).
__global__ __launch_bounds__(128)
void edge_kernel_mma(const int* __restrict__ src, const int* __restrict__ dst,
                     const float* __restrict__ w1r, const float* __restrict__ b1,
                     const float* __restrict__ w2,  const float* __restrict__ b2,
                     const float* __restrict__ xw1, const float* __restrict__ xb1,
                     const float* __restrict__ xw2, const float* __restrict__ xb2,
                     int E) {
    extern __shared__ float dyn[];
    float* sAh = dyn;                    // [ET][LDE]
    float* sAl = sAh + ET * LDE;
    float* sBh = sAl + ET * LDE;         // [64][LDE]
    float* sBl = sBh + 64 * LDE;
    __shared__ int   sdst[ET], ssrc[ET];
    __shared__ float sxd[ET * 3], sr[ET], sWe[ET];
    __shared__ float sw1r[64], sb1v[64], sb2v[64], sxb1[64], sxw2[64];

    int tid = threadIdx.x;
    int lane = tid & 31, warp = tid >> 5;
    int gr = lane >> 2, gc = lane & 3;
    int e0 = blockIdx.x * ET;
    int rbase = warp * 32;

    // per-edge metadata
    {
        int eg = e0 + tid;
        int s = 0, d = -1;
        float d0 = 0.f, d1 = 0.f, d2 = 0.f;
        if (eg < E) {
            s = src[eg]; d = dst[eg];
            d0 = g_x[s * 3 + 0] - g_x[d * 3 + 0];
            d1 = g_x[s * 3 + 1] - g_x[d * 3 + 1];
            d2 = g_x[s * 3 + 2] - g_x[d * 3 + 2];
        }
        ssrc[tid] = s; sdst[tid] = d;
        sxd[tid * 3 + 0] = d0; sxd[tid * 3 + 1] = d1; sxd[tid * 3 + 2] = d2;
        sr[tid] = sqrtf(d0 * d0 + d1 * d1 + d2 * d2);
    }
    if (tid < 64) {
        sw1r[tid] = w1r[tid]; sb1v[tid] = b1[tid]; sb2v[tid] = b2[tid];
        sxb1[tid] = xb1[tid]; sxw2[tid] = xw2[tid];
    }
    // w2 -> sBh/sBl (hi/lo split)
    for (int p = tid; p < 1024; p += 128) {
        float4 w = *(const float4*)&w2[p * 4];
        int k = (p * 4) >> 6, n = (p * 4) & 63;
        float4 hi = make_float4(tf32f(w.x), tf32f(w.y), tf32f(w.z), tf32f(w.w));
        float4 lo = make_float4(tf32f(w.x - hi.x), tf32f(w.y - hi.y),
                                tf32f(w.z - hi.z), tf32f(w.w - hi.w));
        *(float4*)&sBh[k * LDE + n] = hi;
        *(float4*)&sBl[k * LDE + n] = lo;
    }
    __syncthreads();

    // stage 1: t1 = silu(Ad[dst]+As[src]+r*w1r+b1) -> sAh/sAl
    for (int p = tid; p < ET * 16; p += 128) {
        int e = p >> 4, j = (p & 15) * 4;
        int d = sdst[e];
        int dd = d < 0 ? 0 : d;
        int s  = ssrc[e];
        float4 ad = *(const float4*)&g_Ad[dd * 64 + j];
        float4 as = *(const float4*)&g_As[s * 64 + j];
        float r = sr[e];
        float4 t;
        t.x = silu_f(ad.x + as.x + r * sw1r[j + 0] + sb1v[j + 0]);
        t.y = silu_f(ad.y + as.y + r * sw1r[j + 1] + sb1v[j + 1]);
        t.z = silu_f(ad.z + as.z + r * sw1r[j + 2] + sb1v[j + 2]);
        t.w = silu_f(ad.w + as.w + r * sw1r[j + 3] + sb1v[j + 3]);
        float4 hi = make_float4(tf32f(t.x), tf32f(t.y), tf32f(t.z), tf32f(t.w));
        float4 lo = make_float4(tf32f(t.x - hi.x), tf32f(t.y - hi.y),
                                tf32f(t.z - hi.z), tf32f(t.w - hi.w));
        *(float4*)&sAh[e * LDE + j] = hi;
        *(float4*)&sAl[e * LDE + j] = lo;
    }
    __syncthreads();

    float acc[2][8][4];
#pragma unroll
    for (int mt = 0; mt < 2; mt++)
#pragma unroll
        for (int nt = 0; nt < 8; nt++)
#pragma unroll
            for (int q = 0; q < 4; q++) acc[mt][nt][q] = 0.f;

    // GEMM1 (3xTF32): D = t1 @ w2
#pragma unroll
    for (int k0 = 0; k0 < 64; k0 += 8) {
        uint32_t ah[2][4], al[2][4];
#pragma unroll
        for (int mt = 0; mt < 2; mt++) {
            int row = (rbase + mt * 16 + gr) * LDE + k0 + gc;
            ah[mt][0] = __float_as_uint(sAh[row]);
            ah[mt][1] = __float_as_uint(sAh[row + 8 * LDE]);
            ah[mt][2] = __float_as_uint(sAh[row + 4]);
            ah[mt][3] = __float_as_uint(sAh[row + 8 * LDE + 4]);
            al[mt][0] = __float_as_uint(sAl[row]);
            al[mt][1] = __float_as_uint(sAl[row + 8 * LDE]);
            al[mt][2] = __float_as_uint(sAl[row + 4]);
            al[mt][3] = __float_as_uint(sAl[row + 8 * LDE + 4]);
        }
#pragma unroll
        for (int nt = 0; nt < 8; nt++) {
            int bo = (k0 + gc) * LDE + nt * 8 + gr;
            uint32_t bh0 = __float_as_uint(sBh[bo]);
            uint32_t bh1 = __float_as_uint(sBh[bo + 4 * LDE]);
            uint32_t bl0 = __float_as_uint(sBl[bo]);
            uint32_t bl1 = __float_as_uint(sBl[bo + 4 * LDE]);
#pragma unroll
            for (int mt = 0; mt < 2; mt++) {
                mma16n8k8(acc[mt][nt], ah[mt], bh0, bh1);
                mma16n8k8(acc[mt][nt], ah[mt], bl0, bl1);
                mma16n8k8(acc[mt][nt], al[mt], bh0, bh1);
            }
        }
    }
    __syncthreads();   // all sA/sB reads done

    // epilogue 1: m = silu(D + b2) -> split hi/lo into sAh/sAl (own rows)
#pragma unroll
    for (int mt = 0; mt < 2; mt++) {
        int ra = rbase + mt * 16 + gr, rb = ra + 8;
#pragma unroll
        for (int nt = 0; nt < 8; nt++) {
            int col = nt * 8 + gc * 2;
            float m00 = silu_f(acc[mt][nt][0] + sb2v[col]);
            float m01 = silu_f(acc[mt][nt][1] + sb2v[col + 1]);
            float m10 = silu_f(acc[mt][nt][2] + sb2v[col]);
            float m11 = silu_f(acc[mt][nt][3] + sb2v[col + 1]);
            float h00 = tf32f(m00), h01 = tf32f(m01);
            float h10 = tf32f(m10), h11 = tf32f(m11);
            *(float2*)&sAh[ra * LDE + col] = make_float2(h00, h01);
            *(float2*)&sAh[rb * LDE + col] = make_float2(h10, h11);
            *(float2*)&sAl[ra * LDE + col] = make_float2(tf32f(m00 - h00), tf32f(m01 - h01));
            *(float2*)&sAl[rb * LDE + col] = make_float2(tf32f(m10 - h10), tf32f(m11 - h11));
        }
    }
    __syncthreads();   // m fully in SMEM

    // scatter m (= hi + lo, exact fp32) with v4 reductions; stage xw1 -> sB
    for (int p = tid; p < ET * 16; p += 128) {
        int e = p >> 4, j = (p & 15) * 4;
        int d = sdst[e];
        if (d >= 0) {
            float4 h4 = *(const float4*)&sAh[e * LDE + j];
            float4 l4 = *(const float4*)&sAl[e * LDE + j];
            red_add_v4(&g_m[d * 64 + j],
                       h4.x + l4.x, h4.y + l4.y, h4.z + l4.z, h4.w + l4.w);
        }
    }
    for (int p = tid; p < 1024; p += 128) {
        float4 w = *(const float4*)&xw1[p * 4];
        int k = (p * 4) >> 6, n = (p * 4) & 63;
        float4 hi = make_float4(tf32f(w.x), tf32f(w.y), tf32f(w.z), tf32f(w.w));
        float4 lo = make_float4(tf32f(w.x - hi.x), tf32f(w.y - hi.y),
                                tf32f(w.z - hi.z), tf32f(w.w - hi.w));
        *(float4*)&sBh[k * LDE + n] = hi;
        *(float4*)&sBl[k * LDE + n] = lo;
    }
    __syncthreads();

#pragma unroll
    for (int mt = 0; mt < 2; mt++)
#pragma unroll
        for (int nt = 0; nt < 8; nt++)
#pragma unroll
            for (int q = 0; q < 4; q++) acc[mt][nt][q] = 0.f;

    // GEMM2 (3xTF32): D = m @ xw1
#pragma unroll
    for (int k0 = 0; k0 < 64; k0 += 8) {
        uint32_t ah[2][4], al[2][4];
#pragma unroll
        for (int mt = 0; mt < 2; mt++) {
            int row = (rbase + mt * 16 + gr) * LDE + k0 + gc;
            ah[mt][0] = __float_as_uint(sAh[row]);
            ah[mt][1] = __float_as_uint(sAh[row + 8 * LDE]);
            ah[mt][2] = __float_as_uint(sAh[row + 4]);
            ah[mt][3] = __float_as_uint(sAh[row + 8 * LDE + 4]);
            al[mt][0] = __float_as_uint(sAl[row]);
            al[mt][1] = __float_as_uint(sAl[row + 8 * LDE]);
            al[mt][2] = __float_as_uint(sAl[row + 4]);
            al[mt][3] = __float_as_uint(sAl[row + 8 * LDE + 4]);
        }
#pragma unroll
        for (int nt = 0; nt < 8; nt++) {
            int bo = (k0 + gc) * LDE + nt * 8 + gr;
            uint32_t bh0 = __float_as_uint(sBh[bo]);
            uint32_t bh1 = __float_as_uint(sBh[bo + 4 * LDE]);
            uint32_t bl0 = __float_as_uint(sBl[bo]);
            uint32_t bl1 = __float_as_uint(sBl[bo + 4 * LDE]);
#pragma unroll
            for (int mt = 0; mt < 2; mt++) {
                mma16n8k8(acc[mt][nt], ah[mt], bh0, bh1);
                mma16n8k8(acc[mt][nt], ah[mt], bl0, bl1);
                mma16n8k8(acc[mt][nt], al[mt], bh0, bh1);
            }
        }
    }

    // epilogue 2: W = silu(D + xb1) . xw2 + xb2
    {
        float Wv[2][2] = {{0.f, 0.f}, {0.f, 0.f}};
#pragma unroll
        for (int mt = 0; mt < 2; mt++)
#pragma unroll
            for (int nt = 0; nt < 8; nt++) {
                int col = nt * 8 + gc * 2;
                Wv[mt][0] += silu_f(acc[mt][nt][0] + sxb1[col]) * sxw2[col]
                           + silu_f(acc[mt][nt][1] + sxb1[col + 1]) * sxw2[col + 1];
                Wv[mt][1] += silu_f(acc[mt][nt][2] + sxb1[col]) * sxw2[col]
                           + silu_f(acc[mt][nt][3] + sxb1[col + 1]) * sxw2[col + 1];
            }
#pragma unroll
        for (int off = 1; off <= 2; off <<= 1) {
            Wv[0][0] += __shfl_xor_sync(0xffffffffu, Wv[0][0], off);
            Wv[0][1] += __shfl_xor_sync(0xffffffffu, Wv[0][1], off);
            Wv[1][0] += __shfl_xor_sync(0xffffffffu, Wv[1][0], off);
            Wv[1][1] += __shfl_xor_sync(0xffffffffu, Wv[1][1], off);
        }
        if (gc == 0) {
            float xb2v = __ldg(xb2);
            sWe[rbase + gr]      = Wv[0][0] + xb2v;
            sWe[rbase + gr + 8]  = Wv[0][1] + xb2v;
            sWe[rbase + gr + 16] = Wv[1][0] + xb2v;
            sWe[rbase + gr + 24] = Wv[1][1] + xb2v;
        }
    }
    __syncthreads();

    for (int p = tid; p < ET * 3; p += 128) {
        int e = p / 3, cc = p - e * 3;
        int d = sdst[e];
        if (d >= 0) atomicAdd(&g_dx[d * 3 + cc], sWe[e] * sxd[e * 3 + cc]);
    }
}

#define EDGE_DYN_BYTES ((2 * ET * LDE + 2 * 64 * LDE) * 4)

// ---------------------------------------------------------------------------
__global__ __launch_bounds__(NT)
void node_update_kernel(const float* __restrict__ hw1, const float* __restrict__ hb1,
                        const float* __restrict__ hw2, const float* __restrict__ hb2,
                        float* __restrict__ outh, float* __restrict__ outx, int N) {
    __shared__ float sA[TS * LDA];
    __shared__ float sW[4096];
    int tid = threadIdx.x;
    int n0 = blockIdx.x * TS;
    int tx = tid & 15, ty = tid >> 4;

    for (int p = tid; p < TS * 16; p += NT) {
        int i = p >> 4, j = (p & 15) * 4;
        int n = n0 + i;
        float4 v = make_float4(0.f, 0.f, 0.f, 0.f);
        if (n < N) v = *(const float4*)&g_h[n * 64 + j];
        *(float4*)&sA[i * LDA + j] = v;
    }
    for (int p = tid; p < 1024; p += NT)
        *(float4*)&sW[p * 4] = *(const float4*)&hw1[p * 4];
    __syncthreads();

    u64 acc[4][2];
    ZERO_ACC(acc);
    gemm_t(sA, sW, tx, ty, acc);
    __syncthreads();

    for (int p = tid; p < TS * 16; p += NT) {
        int i = p >> 4, j = (p & 15) * 4;
        int n = n0 + i;
        float4 v = make_float4(0.f, 0.f, 0.f, 0.f);
        if (n < N) v = *(const float4*)&g_m[n * 64 + j];
        *(float4*)&sA[i * LDA + j] = v;
    }
    for (int p = tid; p < 1024; p += NT)
        *(float4*)&sW[p * 4] = *(const float4*)&hw1[4096 + p * 4];
    __syncthreads();
    gemm_t(sA, sW, tx, ty, acc);
    __syncthreads();

#pragma unroll
    for (int i = 0; i < 4; i++) {
        int e = ty * 4 + i;
        float c[4];
        UNPACK_ROW(acc[i], c);
#pragma unroll
        for (int q = 0; q < 4; q++) c[q] = silu_f(c[q] + hb1[tx * 4 + q]);
        *(float4*)&sA[e * LDA + tx * 4] = make_float4(c[0], c[1], c[2], c[3]);
    }
    for (int p = tid; p < 1024; p += NT)
        *(float4*)&sW[p * 4] = *(const float4*)&hw2[p * 4];
    __syncthreads();

    ZERO_ACC(acc);
    gemm_t(sA, sW, tx, ty, acc);

    float* hdst = outh ? outh : g_h;
#pragma unroll
    for (int i = 0; i < 4; i++) {
        int n = n0 + ty * 4 + i;
        if (n < N) {
            float c[4];
            UNPACK_ROW(acc[i], c);
            float4 o = *(const float4*)&g_h[n * 64 + tx * 4];
            o.x += c[0] + hb2[tx * 4 + 0];
            o.y += c[1] + hb2[tx * 4 + 1];
            o.z += c[2] + hb2[tx * 4 + 2];
            o.w += c[3] + hb2[tx * 4 + 3];
            *(float4*)&hdst[n * 64 + tx * 4] = o;
        }
    }
    float* xdst = outx ? outx : g_x;
    if (tid < TS * 3) {
        int idx = n0 * 3 + tid;
        if (idx < N * 3) xdst[idx] = g_x[idx] + g_dx[idx];
    }
}

// ---------------------------------------------------------------------------
extern "C" void kernel_launch(void* const* d_in, const int* in_sizes, int n_in,
                              void* d_out, int out_size) {
    const int*   an   = (const int*)d_in[0];
    const float* pos  = (const float*)d_in[1];
    const int*   eidx = (const int*)d_in[2];
    // d_in[3] = edge_attr (unused by reference)
    const float* emb  = (const float*)d_in[4];
    const float* e_w1 = (const float*)d_in[5];
    const float* e_b1 = (const float*)d_in[6];
    const float* e_w2 = (const float*)d_in[7];
    const float* e_b2 = (const float*)d_in[8];
    const float* h_w1 = (const float*)d_in[9];
    const float* h_b1 = (const float*)d_in[10];
    const float* h_w2 = (const float*)d_in[11];
    const float* h_b2 = (const float*)d_in[12];
    const float* x_w1 = (const float*)d_in[13];
    const float* x_b1 = (const float*)d_in[14];
    const float* x_w2 = (const float*)d_in[15];
    const float* x_b2 = (const float*)d_in[16];

    int N = in_sizes[0];
    int E = in_sizes[2] / 2;
    float* out = (float*)d_out;

    cudaFuncSetAttribute(edge_kernel_mma,
                         cudaFuncAttributeMaxDynamicSharedMemorySize,
                         EDGE_DYN_BYTES);

    int nodeBlocks = (N + TS - 1) / TS;
    int edgeBlocks = (E + ET - 1) / ET;
    int totBlocks  = (N * 67 + 255) / 256;

    init_kernel<<<totBlocks, 256>>>(an, pos, emb, N);

    for (int l = 0; l < 2; l++) {
        const float* ew1l = e_w1 + l * 129 * 64;
        node_pre_kernel<<<nodeBlocks, NT>>>(ew1l, N);
        edge_kernel_mma<<<edgeBlocks, 128, EDGE_DYN_BYTES>>>(
            eidx, eidx + E,
            ew1l + 128 * 64, e_b1 + l * 64,
            e_w2 + l * 4096, e_b2 + l * 64,
            x_w1 + l * 4096, x_b1 + l * 64,
            x_w2 + l * 64, x_b2 + l,
            E);
        bool last = (l == 1);
        node_update_kernel<<<nodeBlocks, NT>>>(
            h_w1 + l * 128 * 64, h_b1 + l * 64,
            h_w2 + l * 4096, h_b2 + l * 64,
            last ? out : nullptr, last ? out + (size_t)N * 64 : nullptr, N);
    }
}

// round 8
// speedup vs baseline: 1.6545x; 1.6545x over previous
#include <cuda_runtime.h>
#include <cuda_bf16.h>
#include <cstdint>

#define NT 256          // node kernels: threads per block
#define TS 64           // node tile rows
#define LDA 68          // sA row stride (floats) for SIMT gemm
#define ET 256          // edge tile (edges per block)
#define LW 36           // edge smem row stride in u32 (72 bf16)

typedef unsigned long long u64;

__device__ float g_h [50048 * 64];
__device__ float g_x [50048 * 3];
__device__ float g_Ad[50048 * 64];   // h @ e_w1[0:64]   (dst part)
__device__ float g_As[50048 * 64];   // h @ e_w1[64:128] (src part)
__device__ float g_m [50048 * 64];   // segment-sum of m_ij
__device__ float g_dx[50048 * 3];    // segment-sum of W_ij * x_diff

__device__ __forceinline__ float silu_f(float v) {
    return v / (1.0f + __expf(-v));
}
__device__ __forceinline__ u64 pdup(float x) {
    u64 r; asm("mov.b64 %0, {%1, %1};" : "=l"(r) : "f"(x)); return r;
}
__device__ __forceinline__ void up2(u64 v, float& a, float& b) {
    asm("mov.b64 {%0, %1}, %2;" : "=f"(a), "=f"(b) : "l"(v));
}
__device__ __forceinline__ void fma2(u64& c, u64 a, u64 b) {
    asm("fma.rn.f32x2 %0, %1, %2, %0;" : "+l"(c) : "l"(a), "l"(b));
}
__device__ __forceinline__ void red_add_v2(float* p, float a, float b) {
    asm volatile("red.global.add.v2.f32 [%0], {%1, %2};"
                 :: "l"(p), "f"(a), "f"(b) : "memory");
}
__device__ __forceinline__ uint32_t pbf2(float lo, float hi) {
    __nv_bfloat162 t;
    t.x = __float2bfloat16_rn(lo);
    t.y = __float2bfloat16_rn(hi);
    return *reinterpret_cast<uint32_t*>(&t);
}
__device__ __forceinline__ float bfhi(float x) {
    return __bfloat162float(__float2bfloat16_rn(x));
}
// D(16x8,f32) += A(16x16,bf16,row) * B(16x8,bf16,col)
__device__ __forceinline__ void mma_bf16(float c[4], const uint32_t a[4],
                                         uint32_t b0, uint32_t b1) {
    asm volatile(
        "mma.sync.aligned.m16n8k16.row.col.f32.bf16.bf16.f32 "
        "{%0,%1,%2,%3}, {%4,%5,%6,%7}, {%8,%9}, {%0,%1,%2,%3};"
        : "+f"(c[0]), "+f"(c[1]), "+f"(c[2]), "+f"(c[3])
        : "r"(a[0]), "r"(a[1]), "r"(a[2]), "r"(a[3]), "r"(b0), "r"(b1));
}

// 3-term bf16 split GEMM: acc += A @ B with A=Ah+Al, B=Bh+Bl (drop Al*Bl).
__device__ __forceinline__ void gemm_bf3(const uint32_t* __restrict__ sAh,
                                         const uint32_t* __restrict__ sAl,
                                         const uint32_t* __restrict__ sBh,
                                         const uint32_t* __restrict__ sBl,
                                         int rbase, int gr, int gc,
                                         float acc[2][8][4]) {
#pragma unroll
    for (int k0 = 0; k0 < 32; k0 += 8) {   // u32 units: 4 chunks of 16 bf16
        uint32_t ah[2][4], al[2][4];
#pragma unroll
        for (int mt = 0; mt < 2; mt++) {
            int base = (rbase + mt * 16 + gr) * LW + k0 + gc;
            ah[mt][0] = sAh[base];
            ah[mt][1] = sAh[base + 8 * LW];
            ah[mt][2] = sAh[base + 4];
            ah[mt][3] = sAh[base + 8 * LW + 4];
            al[mt][0] = sAl[base];
            al[mt][1] = sAl[base + 8 * LW];
            al[mt][2] = sAl[base + 4];
            al[mt][3] = sAl[base + 8 * LW + 4];
        }
#pragma unroll
        for (int nt = 0; nt < 8; nt++) {
            int bb = (nt * 8 + gr) * LW + k0 + gc;
            uint32_t bh0 = sBh[bb], bh1 = sBh[bb + 4];
            uint32_t bl0 = sBl[bb], bl1 = sBl[bb + 4];
#pragma unroll
            for (int mt = 0; mt < 2; mt++) {
                mma_bf16(acc[mt][nt], ah[mt], bh0, bh1);
                mma_bf16(acc[mt][nt], ah[mt], bl0, bl1);
                mma_bf16(acc[mt][nt], al[mt], bh0, bh1);
            }
        }
    }
}

// ===================== SIMT gemm (node kernels, R4-proven) ==================
__device__ __forceinline__ void gemm_t(const float* __restrict__ sA,
                                       const float* __restrict__ sW,
                                       int tx, int ty, u64 acc[4][2]) {
    const float* aR = sA + ty * 4 * LDA;
    const float* bC = sW + tx * 4;
#pragma unroll
    for (int kb = 0; kb < 64; kb += 4) {
        float4 av[4];
#pragma unroll
        for (int i = 0; i < 4; i++)
            av[i] = *(const float4*)(aR + i * LDA + kb);
#pragma unroll
        for (int kk = 0; kk < 4; kk++) {
            ulonglong2 b = *(const ulonglong2*)(bC + (kb + kk) * 64);
#pragma unroll
            for (int i = 0; i < 4; i++) {
                float a = (kk == 0) ? av[i].x : (kk == 1) ? av[i].y
                        : (kk == 2) ? av[i].z : av[i].w;
                u64 aa = pdup(a);
                fma2(acc[i][0], aa, b.x);
                fma2(acc[i][1], aa, b.y);
            }
        }
    }
}

#define ZERO_ACC(acc)                             \
    _Pragma("unroll") for (int i_ = 0; i_ < 4; i_++) { (acc)[i_][0] = 0ull; (acc)[i_][1] = 0ull; }
#define UNPACK_ROW(acc_row, c)  \
    up2((acc_row)[0], (c)[0], (c)[1]); up2((acc_row)[1], (c)[2], (c)[3]);

// ---------------------------------------------------------------------------
// Fused init + node_pre (layer 0): h = emb[an]; x = pos; Ad/As; zero m/dx.
__global__ __launch_bounds__(NT)
void init_pre_kernel(const int* __restrict__ an, const float* __restrict__ emb,
                     const float* __restrict__ pos, const float* __restrict__ w1,
                     int N) {
    __shared__ float sA[TS * LDA];
    __shared__ float sW[4096];
    int tid = threadIdx.x;
    int n0 = blockIdx.x * TS;
    int tx = tid & 15, ty = tid >> 4;

    for (int p = tid; p < TS * 16; p += NT) {
        int i = p >> 4, j = (p & 15) * 4;
        int n = n0 + i;
        float4 v = make_float4(0.f, 0.f, 0.f, 0.f);
        if (n < N) {
            v = *(const float4*)&emb[an[n] * 64 + j];
            *(float4*)&g_h[n * 64 + j] = v;
            *(float4*)&g_m[n * 64 + j] = make_float4(0.f, 0.f, 0.f, 0.f);
        }
        *(float4*)&sA[i * LDA + j] = v;
    }
    if (tid < TS * 3) {
        int idx = n0 * 3 + tid;
        if (idx < N * 3) { g_x[idx] = pos[idx]; g_dx[idx] = 0.f; }
    }
    for (int p = tid; p < 1024; p += NT)
        *(float4*)&sW[p * 4] = *(const float4*)&w1[p * 4];
    __syncthreads();

    u64 acc[4][2];
    ZERO_ACC(acc);
    gemm_t(sA, sW, tx, ty, acc);
#pragma unroll
    for (int i = 0; i < 4; i++) {
        int n = n0 + ty * 4 + i;
        if (n < N) {
            float c[4]; UNPACK_ROW(acc[i], c);
            *(float4*)&g_Ad[n * 64 + tx * 4] = make_float4(c[0], c[1], c[2], c[3]);
        }
    }
    __syncthreads();
    for (int p = tid; p < 1024; p += NT)
        *(float4*)&sW[p * 4] = *(const float4*)&w1[4096 + p * 4];
    __syncthreads();
    ZERO_ACC(acc);
    gemm_t(sA, sW, tx, ty, acc);
#pragma unroll
    for (int i = 0; i < 4; i++) {
        int n = n0 + ty * 4 + i;
        if (n < N) {
            float c[4]; UNPACK_ROW(acc[i], c);
            *(float4*)&g_As[n * 64 + tx * 4] = make_float4(c[0], c[1], c[2], c[3]);
        }
    }
}

// ---------------------------------------------------------------------------
// 3xBF16 edge kernel: 256 edges/block, 256 threads (8 warps x 32 rows).
__global__ __launch_bounds__(256, 2)
void edge_kernel_bf3(const int* __restrict__ src, const int* __restrict__ dst,
                     const float* __restrict__ w1r, const float* __restrict__ b1,
                     const float* __restrict__ w2,  const float* __restrict__ b2,
                     const float* __restrict__ xw1, const float* __restrict__ xb1,
                     const float* __restrict__ xw2, const float* __restrict__ xb2,
                     int E) {
    extern __shared__ uint32_t dynu[];
    uint32_t* sAh = dynu;                   // [ET][LW]
    uint32_t* sAl = sAh + ET * LW;
    uint32_t* sBh = sAl + ET * LW;          // [64][LW]
    uint32_t* sBl = sBh + 64 * LW;
    __shared__ int   sdst[ET], ssrc[ET];
    __shared__ float sxd[ET * 3], sr[ET], sWe[ET];
    __shared__ float sw1r[64], sb1v[64], sb2v[64], sxb1[64], sxw2[64];

    int tid = threadIdx.x;
    int lane = tid & 31, warp = tid >> 5;
    int gr = lane >> 2, gc = lane & 3;
    int e0 = blockIdx.x * ET;
    int rbase = warp * 32;

    // per-edge metadata (one edge per thread)
    {
        int eg = e0 + tid;
        int s = 0, d = -1;
        float d0 = 0.f, d1 = 0.f, d2 = 0.f;
        if (eg < E) {
            s = src[eg]; d = dst[eg];
            d0 = g_x[s * 3 + 0] - g_x[d * 3 + 0];
            d1 = g_x[s * 3 + 1] - g_x[d * 3 + 1];
            d2 = g_x[s * 3 + 2] - g_x[d * 3 + 2];
        }
        ssrc[tid] = s; sdst[tid] = d;
        sxd[tid * 3 + 0] = d0; sxd[tid * 3 + 1] = d1; sxd[tid * 3 + 2] = d2;
        sr[tid] = sqrtf(d0 * d0 + d1 * d1 + d2 * d2);
    }
    if (tid < 64) {
        sw1r[tid] = w1r[tid]; sb1v[tid] = b1[tid]; sb2v[tid] = b2[tid];
        sxb1[tid] = xb1[tid]; sxw2[tid] = xw2[tid];
    }
    // stage w2^T (n-major) hi/lo bf16
    for (int p = tid; p < 2048; p += 256) {
        int k2 = p >> 6, n = p & 63;
        float w0 = w2[(k2 * 2) * 64 + n];
        float w1_ = w2[(k2 * 2 + 1) * 64 + n];
        float h0 = bfhi(w0), h1 = bfhi(w1_);
        sBh[n * LW + k2] = pbf2(h0, h1);
        sBl[n * LW + k2] = pbf2(w0 - h0, w1_ - h1);
    }
    __syncthreads();

    // stage t1 = silu(Ad[dst]+As[src]+r*w1r+b1) split hi/lo
    for (int p = tid; p < ET * 16; p += 256) {
        int e = p >> 4, j = (p & 15) * 4;
        int d = sdst[e];
        int dd = d < 0 ? 0 : d;
        int s  = ssrc[e];
        float4 ad = *(const float4*)&g_Ad[dd * 64 + j];
        float4 as = *(const float4*)&g_As[s * 64 + j];
        float r = sr[e];
        float t0 = silu_f(ad.x + as.x + r * sw1r[j + 0] + sb1v[j + 0]);
        float t1 = silu_f(ad.y + as.y + r * sw1r[j + 1] + sb1v[j + 1]);
        float t2 = silu_f(ad.z + as.z + r * sw1r[j + 2] + sb1v[j + 2]);
        float t3 = silu_f(ad.w + as.w + r * sw1r[j + 3] + sb1v[j + 3]);
        float h0 = bfhi(t0), h1 = bfhi(t1), h2 = bfhi(t2), h3 = bfhi(t3);
        int o = e * LW + (j >> 1);
        sAh[o]     = pbf2(h0, h1);
        sAh[o + 1] = pbf2(h2, h3);
        sAl[o]     = pbf2(t0 - h0, t1 - h1);
        sAl[o + 1] = pbf2(t2 - h2, t3 - h3);
    }
    __syncthreads();

    float acc[2][8][4];
#pragma unroll
    for (int mt = 0; mt < 2; mt++)
#pragma unroll
        for (int nt = 0; nt < 8; nt++)
#pragma unroll
            for (int q = 0; q < 4; q++) acc[mt][nt][q] = 0.f;

    gemm_bf3(sAh, sAl, sBh, sBl, rbase, gr, gc, acc);   // GEMM1: t1 @ w2

    // epilogue 1: m = silu(D + b2); scatter; write bf16 hi/lo m -> sA (own rows)
#pragma unroll
    for (int mt = 0; mt < 2; mt++) {
        int ra = rbase + mt * 16 + gr, rb = ra + 8;
        int da = sdst[ra], db = sdst[rb];
#pragma unroll
        for (int nt = 0; nt < 8; nt++) {
            int col = nt * 8 + gc * 2;
            float m00 = silu_f(acc[mt][nt][0] + sb2v[col]);
            float m01 = silu_f(acc[mt][nt][1] + sb2v[col + 1]);
            float m10 = silu_f(acc[mt][nt][2] + sb2v[col]);
            float m11 = silu_f(acc[mt][nt][3] + sb2v[col + 1]);
            if (da >= 0) red_add_v2(&g_m[da * 64 + col], m00, m01);
            if (db >= 0) red_add_v2(&g_m[db * 64 + col], m10, m11);
            float h00 = bfhi(m00), h01 = bfhi(m01);
            float h10 = bfhi(m10), h11 = bfhi(m11);
            int oa = ra * LW + nt * 4 + gc, ob = rb * LW + nt * 4 + gc;
            sAh[oa] = pbf2(h00, h01);
            sAl[oa] = pbf2(m00 - h00, m01 - h01);
            sAh[ob] = pbf2(h10, h11);
            sAl[ob] = pbf2(m10 - h10, m11 - h11);
        }
    }
    __syncthreads();   // all GEMM1 sB reads done

    // restage xw1^T hi/lo
    for (int p = tid; p < 2048; p += 256) {
        int k2 = p >> 6, n = p & 63;
        float w0 = xw1[(k2 * 2) * 64 + n];
        float w1_ = xw1[(k2 * 2 + 1) * 64 + n];
        float h0 = bfhi(w0), h1 = bfhi(w1_);
        sBh[n * LW + k2] = pbf2(h0, h1);
        sBl[n * LW + k2] = pbf2(w0 - h0, w1_ - h1);
    }
    __syncthreads();

#pragma unroll
    for (int mt = 0; mt < 2; mt++)
#pragma unroll
        for (int nt = 0; nt < 8; nt++)
#pragma unroll
            for (int q = 0; q < 4; q++) acc[mt][nt][q] = 0.f;

    gemm_bf3(sAh, sAl, sBh, sBl, rbase, gr, gc, acc);   // GEMM2: m @ xw1

    // epilogue 2: W = silu(D + xb1) . xw2 + xb2
    {
        float Wv[2][2] = {{0.f, 0.f}, {0.f, 0.f}};
#pragma unroll
        for (int mt = 0; mt < 2; mt++)
#pragma unroll
            for (int nt = 0; nt < 8; nt++) {
                int col = nt * 8 + gc * 2;
                Wv[mt][0] += silu_f(acc[mt][nt][0] + sxb1[col]) * sxw2[col]
                           + silu_f(acc[mt][nt][1] + sxb1[col + 1]) * sxw2[col + 1];
                Wv[mt][1] += silu_f(acc[mt][nt][2] + sxb1[col]) * sxw2[col]
                           + silu_f(acc[mt][nt][3] + sxb1[col + 1]) * sxw2[col + 1];
            }
#pragma unroll
        for (int off = 1; off <= 2; off <<= 1) {
            Wv[0][0] += __shfl_xor_sync(0xffffffffu, Wv[0][0], off);
            Wv[0][1] += __shfl_xor_sync(0xffffffffu, Wv[0][1], off);
            Wv[1][0] += __shfl_xor_sync(0xffffffffu, Wv[1][0], off);
            Wv[1][1] += __shfl_xor_sync(0xffffffffu, Wv[1][1], off);
        }
        if (gc == 0) {
            float xb2v = __ldg(xb2);
            sWe[rbase + gr]      = Wv[0][0] + xb2v;
            sWe[rbase + gr + 8]  = Wv[0][1] + xb2v;
            sWe[rbase + gr + 16] = Wv[1][0] + xb2v;
            sWe[rbase + gr + 24] = Wv[1][1] + xb2v;
        }
    }
    __syncthreads();

    for (int p = tid; p < ET * 3; p += 256) {
        int e = p / 3, cc = p - e * 3;
        int d = sdst[e];
        if (d >= 0) atomicAdd(&g_dx[d * 3 + cc], sWe[e] * sxd[e * 3 + cc]);
    }
}

#define EDGE_DYN_BYTES ((2 * ET * LW + 2 * 64 * LW) * 4)

// ---------------------------------------------------------------------------
// Fused node_update + node_pre(next layer). Also zeroes m/dx after reading.
__global__ __launch_bounds__(NT)
void update_pre_kernel(const float* __restrict__ hw1, const float* __restrict__ hb1,
                       const float* __restrict__ hw2, const float* __restrict__ hb2,
                       const float* __restrict__ ew1n, int N) {
    __shared__ float sA[TS * LDA];
    __shared__ float sW[4096];
    int tid = threadIdx.x;
    int n0 = blockIdx.x * TS;
    int tx = tid & 15, ty = tid >> 4;

    // pass A: h
    for (int p = tid; p < TS * 16; p += NT) {
        int i = p >> 4, j = (p & 15) * 4;
        int n = n0 + i;
        float4 v = make_float4(0.f, 0.f, 0.f, 0.f);
        if (n < N) v = *(const float4*)&g_h[n * 64 + j];
        *(float4*)&sA[i * LDA + j] = v;
    }
    for (int p = tid; p < 1024; p += NT)
        *(float4*)&sW[p * 4] = *(const float4*)&hw1[p * 4];
    __syncthreads();

    u64 acc[4][2];
    ZERO_ACC(acc);
    gemm_t(sA, sW, tx, ty, acc);
    __syncthreads();

    // pass B: m (read then zero for next layer)
    for (int p = tid; p < TS * 16; p += NT) {
        int i = p >> 4, j = (p & 15) * 4;
        int n = n0 + i;
        float4 v = make_float4(0.f, 0.f, 0.f, 0.f);
        if (n < N) {
            v = *(const float4*)&g_m[n * 64 + j];
            *(float4*)&g_m[n * 64 + j] = make_float4(0.f, 0.f, 0.f, 0.f);
        }
        *(float4*)&sA[i * LDA + j] = v;
    }
    for (int p = tid; p < 1024; p += NT)
        *(float4*)&sW[p * 4] = *(const float4*)&hw1[4096 + p * 4];
    __syncthreads();
    gemm_t(sA, sW, tx, ty, acc);
    __syncthreads();

    // t = silu(acc + hb1) -> sA ; load hw2
#pragma unroll
    for (int i = 0; i < 4; i++) {
        int e = ty * 4 + i;
        float c[4]; UNPACK_ROW(acc[i], c);
#pragma unroll
        for (int q = 0; q < 4; q++) c[q] = silu_f(c[q] + hb1[tx * 4 + q]);
        *(float4*)&sA[e * LDA + tx * 4] = make_float4(c[0], c[1], c[2], c[3]);
    }
    for (int p = tid; p < 1024; p += NT)
        *(float4*)&sW[p * 4] = *(const float4*)&hw2[p * 4];
    __syncthreads();

    ZERO_ACC(acc);
    gemm_t(sA, sW, tx, ty, acc);
    __syncthreads();   // all reads of sA(t) done before overwrite

    // hnew = h_old + acc + hb2 -> g_h AND sA ; x += dx (zero dx)
#pragma unroll
    for (int i = 0; i < 4; i++) {
        int n = n0 + ty * 4 + i;
        if (n < N) {
            float c[4]; UNPACK_ROW(acc[i], c);
            float4 o = *(const float4*)&g_h[n * 64 + tx * 4];
            o.x += c[0] + hb2[tx * 4 + 0];
            o.y += c[1] + hb2[tx * 4 + 1];
            o.z += c[2] + hb2[tx * 4 + 2];
            o.w += c[3] + hb2[tx * 4 + 3];
            *(float4*)&g_h[n * 64 + tx * 4] = o;
            *(float4*)&sA[(ty * 4 + i) * LDA + tx * 4] = o;
        } else {
            *(float4*)&sA[(ty * 4 + i) * LDA + tx * 4] = make_float4(0.f, 0.f, 0.f, 0.f);
        }
    }
    if (tid < TS * 3) {
        int idx = n0 * 3 + tid;
        if (idx < N * 3) {
            g_x[idx] = g_x[idx] + g_dx[idx];
            g_dx[idx] = 0.f;
        }
    }
    for (int p = tid; p < 1024; p += NT)
        *(float4*)&sW[p * 4] = *(const float4*)&ew1n[p * 4];
    __syncthreads();

    // node_pre for next layer
    ZERO_ACC(acc);
    gemm_t(sA, sW, tx, ty, acc);
#pragma unroll
    for (int i = 0; i < 4; i++) {
        int n = n0 + ty * 4 + i;
        if (n < N) {
            float c[4]; UNPACK_ROW(acc[i], c);
            *(float4*)&g_Ad[n * 64 + tx * 4] = make_float4(c[0], c[1], c[2], c[3]);
        }
    }
    __syncthreads();
    for (int p = tid; p < 1024; p += NT)
        *(float4*)&sW[p * 4] = *(const float4*)&ew1n[4096 + p * 4];
    __syncthreads();
    ZERO_ACC(acc);
    gemm_t(sA, sW, tx, ty, acc);
#pragma unroll
    for (int i = 0; i < 4; i++) {
        int n = n0 + ty * 4 + i;
        if (n < N) {
            float c[4]; UNPACK_ROW(acc[i], c);
            *(float4*)&g_As[n * 64 + tx * 4] = make_float4(c[0], c[1], c[2], c[3]);
        }
    }
}

// ---------------------------------------------------------------------------
// Final node update: writes h, x into the output buffer.
__global__ __launch_bounds__(NT)
void final_update_kernel(const float* __restrict__ hw1, const float* __restrict__ hb1,
                         const float* __restrict__ hw2, const float* __restrict__ hb2,
                         float* __restrict__ outh, float* __restrict__ outx, int N) {
    __shared__ float sA[TS * LDA];
    __shared__ float sW[4096];
    int tid = threadIdx.x;
    int n0 = blockIdx.x * TS;
    int tx = tid & 15, ty = tid >> 4;

    for (int p = tid; p < TS * 16; p += NT) {
        int i = p >> 4, j = (p & 15) * 4;
        int n = n0 + i;
        float4 v = make_float4(0.f, 0.f, 0.f, 0.f);
        if (n < N) v = *(const float4*)&g_h[n * 64 + j];
        *(float4*)&sA[i * LDA + j] = v;
    }
    for (int p = tid; p < 1024; p += NT)
        *(float4*)&sW[p * 4] = *(const float4*)&hw1[p * 4];
    __syncthreads();

    u64 acc[4][2];
    ZERO_ACC(acc);
    gemm_t(sA, sW, tx, ty, acc);
    __syncthreads();

    for (int p = tid; p < TS * 16; p += NT) {
        int i = p >> 4, j = (p & 15) * 4;
        int n = n0 + i;
        float4 v = make_float4(0.f, 0.f, 0.f, 0.f);
        if (n < N) v = *(const float4*)&g_m[n * 64 + j];
        *(float4*)&sA[i * LDA + j] = v;
    }
    for (int p = tid; p < 1024; p += NT)
        *(float4*)&sW[p * 4] = *(const float4*)&hw1[4096 + p * 4];
    __syncthreads();
    gemm_t(sA, sW, tx, ty, acc);
    __syncthreads();

#pragma unroll
    for (int i = 0; i < 4; i++) {
        int e = ty * 4 + i;
        float c[4]; UNPACK_ROW(acc[i], c);
#pragma unroll
        for (int q = 0; q < 4; q++) c[q] = silu_f(c[q] + hb1[tx * 4 + q]);
        *(float4*)&sA[e * LDA + tx * 4] = make_float4(c[0], c[1], c[2], c[3]);
    }
    for (int p = tid; p < 1024; p += NT)
        *(float4*)&sW[p * 4] = *(const float4*)&hw2[p * 4];
    __syncthreads();

    ZERO_ACC(acc);
    gemm_t(sA, sW, tx, ty, acc);

#pragma unroll
    for (int i = 0; i < 4; i++) {
        int n = n0 + ty * 4 + i;
        if (n < N) {
            float c[4]; UNPACK_ROW(acc[i], c);
            float4 o = *(const float4*)&g_h[n * 64 + tx * 4];
            o.x += c[0] + hb2[tx * 4 + 0];
            o.y += c[1] + hb2[tx * 4 + 1];
            o.z += c[2] + hb2[tx * 4 + 2];
            o.w += c[3] + hb2[tx * 4 + 3];
            *(float4*)&outh[n * 64 + tx * 4] = o;
        }
    }
    if (tid < TS * 3) {
        int idx = n0 * 3 + tid;
        if (idx < N * 3) outx[idx] = g_x[idx] + g_dx[idx];
    }
}

// ---------------------------------------------------------------------------
extern "C" void kernel_launch(void* const* d_in, const int* in_sizes, int n_in,
                              void* d_out, int out_size) {
    const int*   an   = (const int*)d_in[0];
    const float* pos  = (const float*)d_in[1];
    const int*   eidx = (const int*)d_in[2];
    // d_in[3] = edge_attr (unused by reference)
    const float* emb  = (const float*)d_in[4];
    const float* e_w1 = (const float*)d_in[5];
    const float* e_b1 = (const float*)d_in[6];
    const float* e_w2 = (const float*)d_in[7];
    const float* e_b2 = (const float*)d_in[8];
    const float* h_w1 = (const float*)d_in[9];
    const float* h_b1 = (const float*)d_in[10];
    const float* h_w2 = (const float*)d_in[11];
    const float* h_b2 = (const float*)d_in[12];
    const float* x_w1 = (const float*)d_in[13];
    const float* x_b1 = (const float*)d_in[14];
    const float* x_w2 = (const float*)d_in[15];
    const float* x_b2 = (const float*)d_in[16];

    int N = in_sizes[0];
    int E = in_sizes[2] / 2;
    float* out = (float*)d_out;

    cudaFuncSetAttribute(edge_kernel_bf3,
                         cudaFuncAttributeMaxDynamicSharedMemorySize,
                         EDGE_DYN_BYTES);

    int nodeBlocks = (N + TS - 1) / TS;
    int edgeBlocks = (E + ET - 1) / ET;

    init_pre_kernel<<<nodeBlocks, NT>>>(an, emb, pos, e_w1, N);

    edge_kernel_bf3<<<edgeBlocks, 256, EDGE_DYN_BYTES>>>(
        eidx, eidx + E,
        e_w1 + 128 * 64, e_b1,
        e_w2, e_b2,
        x_w1, x_b1,
        x_w2, x_b2, E);

    update_pre_kernel<<<nodeBlocks, NT>>>(
        h_w1, h_b1, h_w2, h_b2,
        e_w1 + 129 * 64, N);

    edge_kernel_bf3<<<edgeBlocks, 256, EDGE_DYN_BYTES>>>(
        eidx, eidx + E,
        e_w1 + 129 * 64 + 128 * 64, e_b1 + 64,
        e_w2 + 4096, e_b2 + 64,
        x_w1 + 4096, x_b1 + 64,
        x_w2 + 64, x_b2 + 1, E);

    final_update_kernel<<<nodeBlocks, NT>>>(
        h_w1 + 128 * 64, h_b1 + 64,
        h_w2 + 4096, h_b2 + 64,
        out, out + (size_t)N * 64, N);
}

// round 9
// speedup vs baseline: 1.7555x; 1.0610x over previous
#include <cuda_runtime.h>
#include <cuda_bf16.h>
#include <cstdint>

#define NT 256          // node kernels: threads per block
#define TS 64           // node tile rows
#define LDA 68          // sA row stride (floats) for SIMT gemm
#define ET 256          // edge tile (edges per block)
#define LW 36           // edge smem row stride in u32 (72 bf16)

typedef unsigned long long u64;

__device__ float g_h [50048 * 64];
__device__ float g_x [50048 * 3];
__device__ float g_Ad[50048 * 64];   // h @ e_w1[0:64]   (dst part)
__device__ float g_As[50048 * 64];   // h @ e_w1[64:128] (src part)
__device__ float g_m [50048 * 64];   // segment-sum of m_ij
__device__ float g_dx[50048 * 3];    // segment-sum of W_ij * x_diff

__device__ __forceinline__ float silu_f(float v) {
    return v / (1.0f + __expf(-v));
}
__device__ __forceinline__ u64 pdup(float x) {
    u64 r; asm("mov.b64 %0, {%1, %1};" : "=l"(r) : "f"(x)); return r;
}
__device__ __forceinline__ void up2(u64 v, float& a, float& b) {
    asm("mov.b64 {%0, %1}, %2;" : "=f"(a), "=f"(b) : "l"(v));
}
__device__ __forceinline__ void fma2(u64& c, u64 a, u64 b) {
    asm("fma.rn.f32x2 %0, %1, %2, %0;" : "+l"(c) : "l"(a), "l"(b));
}
__device__ __forceinline__ void red_add_v2(float* p, float a, float b) {
    asm volatile("red.global.add.v2.f32 [%0], {%1, %2};"
                 :: "l"(p), "f"(a), "f"(b) : "memory");
}
__device__ __forceinline__ uint32_t pbf2(float lo, float hi) {
    __nv_bfloat162 t;
    t.x = __float2bfloat16_rn(lo);
    t.y = __float2bfloat16_rn(hi);
    return *reinterpret_cast<uint32_t*>(&t);
}
__device__ __forceinline__ float bfhi(float x) {
    return __bfloat162float(__float2bfloat16_rn(x));
}
__device__ __forceinline__ uint32_t smem_u32p(const void* p) {
    uint32_t a;
    asm("{ .reg .u64 t; cvta.to.shared.u64 t, %1; cvt.u32.u64 %0, t; }"
        : "=r"(a) : "l"(p));
    return a;
}
// D(16x8,f32) += A(16x16,bf16,row) * B(16x8,bf16,col)
__device__ __forceinline__ void mma_bf16(float c[4], const uint32_t a[4],
                                         uint32_t b0, uint32_t b1) {
    asm volatile(
        "mma.sync.aligned.m16n8k16.row.col.f32.bf16.bf16.f32 "
        "{%0,%1,%2,%3}, {%4,%5,%6,%7}, {%8,%9}, {%0,%1,%2,%3};"
        : "+f"(c[0]), "+f"(c[1]), "+f"(c[2]), "+f"(c[3])
        : "r"(a[0]), "r"(a[1]), "r"(a[2]), "r"(a[3]), "r"(b0), "r"(b1));
}
__device__ __forceinline__ void ldsm_x4(uint32_t r[4], uint32_t addr) {
    asm volatile("ldmatrix.sync.aligned.m8n8.x4.shared.b16 {%0,%1,%2,%3}, [%4];"
                 : "=r"(r[0]), "=r"(r[1]), "=r"(r[2]), "=r"(r[3]) : "r"(addr));
}

// 3-term bf16 split GEMM via ldmatrix. Warp owns rows rbase..rbase+31.
__device__ __forceinline__ void gemm_bf3(uint32_t aH, uint32_t aL,
                                         uint32_t bH, uint32_t bL,
                                         int lane, int rbase,
                                         float acc[2][8][4]) {
    int l7 = lane & 7;
    int aRow = l7 + ((lane >> 3) & 1) * 8;      // row within 16-row tile
    int aColU = ((lane >> 4) & 1) * 4;          // k-half in u32
    int bRow = ((lane >> 4) << 3) + l7;         // n within 16-n pair
    int bColU = ((lane >> 3) & 1) * 4;
#pragma unroll
    for (int c = 0; c < 4; c++) {
        int kc = c * 8;                         // u32 k base
        uint32_t ah0[4], al0[4], ah1[4], al1[4];
        uint32_t off0 = (uint32_t)((rbase + aRow) * LW + kc + aColU) * 4u;
        uint32_t off1 = off0 + 16u * LW * 4u;
        ldsm_x4(ah0, aH + off0); ldsm_x4(al0, aL + off0);
        ldsm_x4(ah1, aH + off1); ldsm_x4(al1, aL + off1);
#pragma unroll
        for (int ntp = 0; ntp < 4; ntp++) {
            uint32_t boff = (uint32_t)((ntp * 16 + bRow) * LW + kc + bColU) * 4u;
            uint32_t bh[4], bl[4];
            ldsm_x4(bh, bH + boff);
            ldsm_x4(bl, bL + boff);
            int n0 = 2 * ntp, n1 = 2 * ntp + 1;
            mma_bf16(acc[0][n0], ah0, bh[0], bh[1]);
            mma_bf16(acc[0][n0], ah0, bl[0], bl[1]);
            mma_bf16(acc[0][n0], al0, bh[0], bh[1]);
            mma_bf16(acc[0][n1], ah0, bh[2], bh[3]);
            mma_bf16(acc[0][n1], ah0, bl[2], bl[3]);
            mma_bf16(acc[0][n1], al0, bh[2], bh[3]);
            mma_bf16(acc[1][n0], ah1, bh[0], bh[1]);
            mma_bf16(acc[1][n0], ah1, bl[0], bl[1]);
            mma_bf16(acc[1][n0], al1, bh[0], bh[1]);
            mma_bf16(acc[1][n1], ah1, bh[2], bh[3]);
            mma_bf16(acc[1][n1], ah1, bl[2], bl[3]);
            mma_bf16(acc[1][n1], al1, bh[2], bh[3]);
        }
    }
}

// ===================== SIMT gemm (node kernels, R4-proven) ==================
__device__ __forceinline__ void gemm_t(const float* __restrict__ sA,
                                       const float* __restrict__ sW,
                                       int tx, int ty, u64 acc[4][2]) {
    const float* aR = sA + ty * 4 * LDA;
    const float* bC = sW + tx * 4;
#pragma unroll
    for (int kb = 0; kb < 64; kb += 4) {
        float4 av[4];
#pragma unroll
        for (int i = 0; i < 4; i++)
            av[i] = *(const float4*)(aR + i * LDA + kb);
#pragma unroll
        for (int kk = 0; kk < 4; kk++) {
            ulonglong2 b = *(const ulonglong2*)(bC + (kb + kk) * 64);
#pragma unroll
            for (int i = 0; i < 4; i++) {
                float a = (kk == 0) ? av[i].x : (kk == 1) ? av[i].y
                        : (kk == 2) ? av[i].z : av[i].w;
                u64 aa = pdup(a);
                fma2(acc[i][0], aa, b.x);
                fma2(acc[i][1], aa, b.y);
            }
        }
    }
}

#define ZERO_ACC(acc)                             \
    _Pragma("unroll") for (int i_ = 0; i_ < 4; i_++) { (acc)[i_][0] = 0ull; (acc)[i_][1] = 0ull; }
#define UNPACK_ROW(acc_row, c)  \
    up2((acc_row)[0], (c)[0], (c)[1]); up2((acc_row)[1], (c)[2], (c)[3]);

// ---------------------------------------------------------------------------
// Fused init + node_pre (layer 0)
__global__ __launch_bounds__(NT)
void init_pre_kernel(const int* __restrict__ an, const float* __restrict__ emb,
                     const float* __restrict__ pos, const float* __restrict__ w1,
                     int N) {
    __shared__ float sA[TS * LDA];
    __shared__ float sW[4096];
    int tid = threadIdx.x;
    int n0 = blockIdx.x * TS;
    int tx = tid & 15, ty = tid >> 4;

    for (int p = tid; p < TS * 16; p += NT) {
        int i = p >> 4, j = (p & 15) * 4;
        int n = n0 + i;
        float4 v = make_float4(0.f, 0.f, 0.f, 0.f);
        if (n < N) {
            v = *(const float4*)&emb[an[n] * 64 + j];
            *(float4*)&g_h[n * 64 + j] = v;
            *(float4*)&g_m[n * 64 + j] = make_float4(0.f, 0.f, 0.f, 0.f);
        }
        *(float4*)&sA[i * LDA + j] = v;
    }
    if (tid < TS * 3) {
        int idx = n0 * 3 + tid;
        if (idx < N * 3) { g_x[idx] = pos[idx]; g_dx[idx] = 0.f; }
    }
    for (int p = tid; p < 1024; p += NT)
        *(float4*)&sW[p * 4] = *(const float4*)&w1[p * 4];
    __syncthreads();

    u64 acc[4][2];
    ZERO_ACC(acc);
    gemm_t(sA, sW, tx, ty, acc);
#pragma unroll
    for (int i = 0; i < 4; i++) {
        int n = n0 + ty * 4 + i;
        if (n < N) {
            float c[4]; UNPACK_ROW(acc[i], c);
            *(float4*)&g_Ad[n * 64 + tx * 4] = make_float4(c[0], c[1], c[2], c[3]);
        }
    }
    __syncthreads();
    for (int p = tid; p < 1024; p += NT)
        *(float4*)&sW[p * 4] = *(const float4*)&w1[4096 + p * 4];
    __syncthreads();
    ZERO_ACC(acc);
    gemm_t(sA, sW, tx, ty, acc);
#pragma unroll
    for (int i = 0; i < 4; i++) {
        int n = n0 + ty * 4 + i;
        if (n < N) {
            float c[4]; UNPACK_ROW(acc[i], c);
            *(float4*)&g_As[n * 64 + tx * 4] = make_float4(c[0], c[1], c[2], c[3]);
        }
    }
}

// ---------------------------------------------------------------------------
// 3xBF16 edge kernel, ldmatrix fragments, both weights resident,
// no mid-kernel block barriers. 256 edges/block, 8 warps x 32 rows.
__global__ __launch_bounds__(256, 2)
void edge_kernel_bf3(const int* __restrict__ src, const int* __restrict__ dst,
                     const float* __restrict__ w1r, const float* __restrict__ b1,
                     const float* __restrict__ w2,  const float* __restrict__ b2,
                     const float* __restrict__ xw1, const float* __restrict__ xb1,
                     const float* __restrict__ xw2, const float* __restrict__ xb2,
                     int E) {
    extern __shared__ uint32_t dynu[];
    uint32_t* sAh  = dynu;                   // [ET][LW]
    uint32_t* sAl  = sAh + ET * LW;
    uint32_t* sB0h = sAl + ET * LW;          // w2  [64][LW]
    uint32_t* sB0l = sB0h + 64 * LW;
    uint32_t* sB1h = sB0l + 64 * LW;         // xw1 [64][LW]
    uint32_t* sB1l = sB1h + 64 * LW;
    __shared__ int   sdst[ET], ssrc[ET];
    __shared__ float srwe[ET];               // sr (pre-sync) aliased with sWe (post)
    __shared__ float sw1r[64], sb1v[64], sb2v[64], sxb1[64], sxw2[64];

    int tid = threadIdx.x;
    int lane = tid & 31, warp = tid >> 5;
    int gr = lane >> 2, gc = lane & 3;
    int e0 = blockIdx.x * ET;
    int rbase = warp * 32;

    uint32_t aH = smem_u32p(sAh), aL = smem_u32p(sAl);
    uint32_t b0H = smem_u32p(sB0h), b0L = smem_u32p(sB0l);
    uint32_t b1H = smem_u32p(sB1h), b1L = smem_u32p(sB1l);

    // per-edge metadata: own edge in registers + SMEM for cross-thread staging
    int my_d;
    float xd0, xd1, xd2;
    {
        int eg = e0 + tid;
        int s = 0; my_d = -1;
        xd0 = xd1 = xd2 = 0.f;
        if (eg < E) {
            s = src[eg]; my_d = dst[eg];
            xd0 = g_x[s * 3 + 0] - g_x[my_d * 3 + 0];
            xd1 = g_x[s * 3 + 1] - g_x[my_d * 3 + 1];
            xd2 = g_x[s * 3 + 2] - g_x[my_d * 3 + 2];
        }
        ssrc[tid] = s; sdst[tid] = my_d;
        srwe[tid] = sqrtf(xd0 * xd0 + xd1 * xd1 + xd2 * xd2);
    }
    if (tid < 64) {
        sw1r[tid] = w1r[tid]; sb1v[tid] = b1[tid]; sb2v[tid] = b2[tid];
        sxb1[tid] = xb1[tid]; sxw2[tid] = xw2[tid];
    }
    // stage BOTH weights (n-major, hi/lo bf16)
    for (int p = tid; p < 2048; p += 256) {
        int k2 = p >> 6, n = p & 63;
        float a0 = w2[(k2 * 2) * 64 + n];
        float a1 = w2[(k2 * 2 + 1) * 64 + n];
        float h0 = bfhi(a0), h1 = bfhi(a1);
        sB0h[n * LW + k2] = pbf2(h0, h1);
        sB0l[n * LW + k2] = pbf2(a0 - h0, a1 - h1);
        float c0 = xw1[(k2 * 2) * 64 + n];
        float c1 = xw1[(k2 * 2 + 1) * 64 + n];
        float g0 = bfhi(c0), g1 = bfhi(c1);
        sB1h[n * LW + k2] = pbf2(g0, g1);
        sB1l[n * LW + k2] = pbf2(c0 - g0, c1 - g1);
    }
    __syncthreads();   // metadata + weights visible

    // stage t1 = silu(Ad[dst]+As[src]+r*w1r+b1), split hi/lo
    for (int p = tid; p < ET * 16; p += 256) {
        int e = p >> 4, j = (p & 15) * 4;
        int d = sdst[e];
        int dd = d < 0 ? 0 : d;
        int s  = ssrc[e];
        float4 ad = *(const float4*)&g_Ad[dd * 64 + j];
        float4 as = *(const float4*)&g_As[s * 64 + j];
        float r = srwe[e];
        float t0 = silu_f(ad.x + as.x + r * sw1r[j + 0] + sb1v[j + 0]);
        float t1 = silu_f(ad.y + as.y + r * sw1r[j + 1] + sb1v[j + 1]);
        float t2 = silu_f(ad.z + as.z + r * sw1r[j + 2] + sb1v[j + 2]);
        float t3 = silu_f(ad.w + as.w + r * sw1r[j + 3] + sb1v[j + 3]);
        float h0 = bfhi(t0), h1 = bfhi(t1), h2 = bfhi(t2), h3 = bfhi(t3);
        int o = e * LW + (j >> 1);
        sAh[o]     = pbf2(h0, h1);
        sAh[o + 1] = pbf2(h2, h3);
        sAl[o]     = pbf2(t0 - h0, t1 - h1);
        sAl[o + 1] = pbf2(t2 - h2, t3 - h3);
    }
    __syncthreads();   // t1 fully staged (last block-wide barrier)

    float acc[2][8][4];
#pragma unroll
    for (int mt = 0; mt < 2; mt++)
#pragma unroll
        for (int nt = 0; nt < 8; nt++)
#pragma unroll
            for (int q = 0; q < 4; q++) acc[mt][nt][q] = 0.f;

    gemm_bf3(aH, aL, b0H, b0L, lane, rbase, acc);   // GEMM1: t1 @ w2

    // epilogue 1: m = silu(D + b2); scatter; rewrite own A rows (hi/lo)
#pragma unroll
    for (int mt = 0; mt < 2; mt++) {
        int ra = rbase + mt * 16 + gr, rb = ra + 8;
        int da = sdst[ra], db = sdst[rb];
#pragma unroll
        for (int nt = 0; nt < 8; nt++) {
            int col = nt * 8 + gc * 2;
            float m00 = silu_f(acc[mt][nt][0] + sb2v[col]);
            float m01 = silu_f(acc[mt][nt][1] + sb2v[col + 1]);
            float m10 = silu_f(acc[mt][nt][2] + sb2v[col]);
            float m11 = silu_f(acc[mt][nt][3] + sb2v[col + 1]);
            if (da >= 0) red_add_v2(&g_m[da * 64 + col], m00, m01);
            if (db >= 0) red_add_v2(&g_m[db * 64 + col], m10, m11);
            float h00 = bfhi(m00), h01 = bfhi(m01);
            float h10 = bfhi(m10), h11 = bfhi(m11);
            int oa = ra * LW + nt * 4 + gc, ob = rb * LW + nt * 4 + gc;
            sAh[oa] = pbf2(h00, h01);
            sAl[oa] = pbf2(m00 - h00, m01 - h01);
            sAh[ob] = pbf2(h10, h11);
            sAl[ob] = pbf2(m10 - h10, m11 - h11);
        }
    }
    __syncwarp();   // cross-lane visibility of m within the warp

#pragma unroll
    for (int mt = 0; mt < 2; mt++)
#pragma unroll
        for (int nt = 0; nt < 8; nt++)
#pragma unroll
            for (int q = 0; q < 4; q++) acc[mt][nt][q] = 0.f;

    gemm_bf3(aH, aL, b1H, b1L, lane, rbase, acc);   // GEMM2: m @ xw1

    // epilogue 2: W = silu(D + xb1) . xw2 + xb2
    {
        float Wv[2][2] = {{0.f, 0.f}, {0.f, 0.f}};
#pragma unroll
        for (int mt = 0; mt < 2; mt++)
#pragma unroll
            for (int nt = 0; nt < 8; nt++) {
                int col = nt * 8 + gc * 2;
                Wv[mt][0] += silu_f(acc[mt][nt][0] + sxb1[col]) * sxw2[col]
                           + silu_f(acc[mt][nt][1] + sxb1[col + 1]) * sxw2[col + 1];
                Wv[mt][1] += silu_f(acc[mt][nt][2] + sxb1[col]) * sxw2[col]
                           + silu_f(acc[mt][nt][3] + sxb1[col + 1]) * sxw2[col + 1];
            }
#pragma unroll
        for (int off = 1; off <= 2; off <<= 1) {
            Wv[0][0] += __shfl_xor_sync(0xffffffffu, Wv[0][0], off);
            Wv[0][1] += __shfl_xor_sync(0xffffffffu, Wv[0][1], off);
            Wv[1][0] += __shfl_xor_sync(0xffffffffu, Wv[1][0], off);
            Wv[1][1] += __shfl_xor_sync(0xffffffffu, Wv[1][1], off);
        }
        if (gc == 0) {
            float xb2v = __ldg(xb2);
            srwe[rbase + gr]      = Wv[0][0] + xb2v;
            srwe[rbase + gr + 8]  = Wv[0][1] + xb2v;
            srwe[rbase + gr + 16] = Wv[1][0] + xb2v;
            srwe[rbase + gr + 24] = Wv[1][1] + xb2v;
        }
    }
    __syncwarp();

    // dx scatter: own edge from registers
    if (my_d >= 0) {
        float W = srwe[tid];
        atomicAdd(&g_dx[my_d * 3 + 0], W * xd0);
        atomicAdd(&g_dx[my_d * 3 + 1], W * xd1);
        atomicAdd(&g_dx[my_d * 3 + 2], W * xd2);
    }
}

#define EDGE_DYN_BYTES ((2 * ET * LW + 4 * 64 * LW) * 4)

// ---------------------------------------------------------------------------
// Fused node_update + node_pre(next layer). Zeroes m/dx after reading.
__global__ __launch_bounds__(NT)
void update_pre_kernel(const float* __restrict__ hw1, const float* __restrict__ hb1,
                       const float* __restrict__ hw2, const float* __restrict__ hb2,
                       const float* __restrict__ ew1n, int N) {
    __shared__ float sA[TS * LDA];
    __shared__ float sW[4096];
    int tid = threadIdx.x;
    int n0 = blockIdx.x * TS;
    int tx = tid & 15, ty = tid >> 4;

    for (int p = tid; p < TS * 16; p += NT) {
        int i = p >> 4, j = (p & 15) * 4;
        int n = n0 + i;
        float4 v = make_float4(0.f, 0.f, 0.f, 0.f);
        if (n < N) v = *(const float4*)&g_h[n * 64 + j];
        *(float4*)&sA[i * LDA + j] = v;
    }
    for (int p = tid; p < 1024; p += NT)
        *(float4*)&sW[p * 4] = *(const float4*)&hw1[p * 4];
    __syncthreads();

    u64 acc[4][2];
    ZERO_ACC(acc);
    gemm_t(sA, sW, tx, ty, acc);
    __syncthreads();

    for (int p = tid; p < TS * 16; p += NT) {
        int i = p >> 4, j = (p & 15) * 4;
        int n = n0 + i;
        float4 v = make_float4(0.f, 0.f, 0.f, 0.f);
        if (n < N) {
            v = *(const float4*)&g_m[n * 64 + j];
            *(float4*)&g_m[n * 64 + j] = make_float4(0.f, 0.f, 0.f, 0.f);
        }
        *(float4*)&sA[i * LDA + j] = v;
    }
    for (int p = tid; p < 1024; p += NT)
        *(float4*)&sW[p * 4] = *(const float4*)&hw1[4096 + p * 4];
    __syncthreads();
    gemm_t(sA, sW, tx, ty, acc);
    __syncthreads();

#pragma unroll
    for (int i = 0; i < 4; i++) {
        int e = ty * 4 + i;
        float c[4]; UNPACK_ROW(acc[i], c);
#pragma unroll
        for (int q = 0; q < 4; q++) c[q] = silu_f(c[q] + hb1[tx * 4 + q]);
        *(float4*)&sA[e * LDA + tx * 4] = make_float4(c[0], c[1], c[2], c[3]);
    }
    for (int p = tid; p < 1024; p += NT)
        *(float4*)&sW[p * 4] = *(const float4*)&hw2[p * 4];
    __syncthreads();

    ZERO_ACC(acc);
    gemm_t(sA, sW, tx, ty, acc);
    __syncthreads();

#pragma unroll
    for (int i = 0; i < 4; i++) {
        int n = n0 + ty * 4 + i;
        if (n < N) {
            float c[4]; UNPACK_ROW(acc[i], c);
            float4 o = *(const float4*)&g_h[n * 64 + tx * 4];
            o.x += c[0] + hb2[tx * 4 + 0];
            o.y += c[1] + hb2[tx * 4 + 1];
            o.z += c[2] + hb2[tx * 4 + 2];
            o.w += c[3] + hb2[tx * 4 + 3];
            *(float4*)&g_h[n * 64 + tx * 4] = o;
            *(float4*)&sA[(ty * 4 + i) * LDA + tx * 4] = o;
        } else {
            *(float4*)&sA[(ty * 4 + i) * LDA + tx * 4] = make_float4(0.f, 0.f, 0.f, 0.f);
        }
    }
    if (tid < TS * 3) {
        int idx = n0 * 3 + tid;
        if (idx < N * 3) {
            g_x[idx] = g_x[idx] + g_dx[idx];
            g_dx[idx] = 0.f;
        }
    }
    for (int p = tid; p < 1024; p += NT)
        *(float4*)&sW[p * 4] = *(const float4*)&ew1n[p * 4];
    __syncthreads();

    ZERO_ACC(acc);
    gemm_t(sA, sW, tx, ty, acc);
#pragma unroll
    for (int i = 0; i < 4; i++) {
        int n = n0 + ty * 4 + i;
        if (n < N) {
            float c[4]; UNPACK_ROW(acc[i], c);
            *(float4*)&g_Ad[n * 64 + tx * 4] = make_float4(c[0], c[1], c[2], c[3]);
        }
    }
    __syncthreads();
    for (int p = tid; p < 1024; p += NT)
        *(float4*)&sW[p * 4] = *(const float4*)&ew1n[4096 + p * 4];
    __syncthreads();
    ZERO_ACC(acc);
    gemm_t(sA, sW, tx, ty, acc);
#pragma unroll
    for (int i = 0; i < 4; i++) {
        int n = n0 + ty * 4 + i;
        if (n < N) {
            float c[4]; UNPACK_ROW(acc[i], c);
            *(float4*)&g_As[n * 64 + tx * 4] = make_float4(c[0], c[1], c[2], c[3]);
        }
    }
}

// ---------------------------------------------------------------------------
__global__ __launch_bounds__(NT)
void final_update_kernel(const float* __restrict__ hw1, const float* __restrict__ hb1,
                         const float* __restrict__ hw2, const float* __restrict__ hb2,
                         float* __restrict__ outh, float* __restrict__ outx, int N) {
    __shared__ float sA[TS * LDA];
    __shared__ float sW[4096];
    int tid = threadIdx.x;
    int n0 = blockIdx.x * TS;
    int tx = tid & 15, ty = tid >> 4;

    for (int p = tid; p < TS * 16; p += NT) {
        int i = p >> 4, j = (p & 15) * 4;
        int n = n0 + i;
        float4 v = make_float4(0.f, 0.f, 0.f, 0.f);
        if (n < N) v = *(const float4*)&g_h[n * 64 + j];
        *(float4*)&sA[i * LDA + j] = v;
    }
    for (int p = tid; p < 1024; p += NT)
        *(float4*)&sW[p * 4] = *(const float4*)&hw1[p * 4];
    __syncthreads();

    u64 acc[4][2];
    ZERO_ACC(acc);
    gemm_t(sA, sW, tx, ty, acc);
    __syncthreads();

    for (int p = tid; p < TS * 16; p += NT) {
        int i = p >> 4, j = (p & 15) * 4;
        int n = n0 + i;
        float4 v = make_float4(0.f, 0.f, 0.f, 0.f);
        if (n < N) v = *(const float4*)&g_m[n * 64 + j];
        *(float4*)&sA[i * LDA + j] = v;
    }
    for (int p = tid; p < 1024; p += NT)
        *(float4*)&sW[p * 4] = *(const float4*)&hw1[4096 + p * 4];
    __syncthreads();
    gemm_t(sA, sW, tx, ty, acc);
    __syncthreads();

#pragma unroll
    for (int i = 0; i < 4; i++) {
        int e = ty * 4 + i;
        float c[4]; UNPACK_ROW(acc[i], c);
#pragma unroll
        for (int q = 0; q < 4; q++) c[q] = silu_f(c[q] + hb1[tx * 4 + q]);
        *(float4*)&sA[e * LDA + tx * 4] = make_float4(c[0], c[1], c[2], c[3]);
    }
    for (int p = tid; p < 1024; p += NT)
        *(float4*)&sW[p * 4] = *(const float4*)&hw2[p * 4];
    __syncthreads();

    ZERO_ACC(acc);
    gemm_t(sA, sW, tx, ty, acc);

#pragma unroll
    for (int i = 0; i < 4; i++) {
        int n = n0 + ty * 4 + i;
        if (n < N) {
            float c[4]; UNPACK_ROW(acc[i], c);
            float4 o = *(const float4*)&g_h[n * 64 + tx * 4];
            o.x += c[0] + hb2[tx * 4 + 0];
            o.y += c[1] + hb2[tx * 4 + 1];
            o.z += c[2] + hb2[tx * 4 + 2];
            o.w += c[3] + hb2[tx * 4 + 3];
            *(float4*)&outh[n * 64 + tx * 4] = o;
        }
    }
    if (tid < TS * 3) {
        int idx = n0 * 3 + tid;
        if (idx < N * 3) outx[idx] = g_x[idx] + g_dx[idx];
    }
}

// ---------------------------------------------------------------------------
extern "C" void kernel_launch(void* const* d_in, const int* in_sizes, int n_in,
                              void* d_out, int out_size) {
    const int*   an   = (const int*)d_in[0];
    const float* pos  = (const float*)d_in[1];
    const int*   eidx = (const int*)d_in[2];
    // d_in[3] = edge_attr (unused by reference)
    const float* emb  = (const float*)d_in[4];
    const float* e_w1 = (const float*)d_in[5];
    const float* e_b1 = (const float*)d_in[6];
    const float* e_w2 = (const float*)d_in[7];
    const float* e_b2 = (const float*)d_in[8];
    const float* h_w1 = (const float*)d_in[9];
    const float* h_b1 = (const float*)d_in[10];
    const float* h_w2 = (const float*)d_in[11];
    const float* h_b2 = (const float*)d_in[12];
    const float* x_w1 = (const float*)d_in[13];
    const float* x_b1 = (const float*)d_in[14];
    const float* x_w2 = (const float*)d_in[15];
    const float* x_b2 = (const float*)d_in[16];

    int N = in_sizes[0];
    int E = in_sizes[2] / 2;
    float* out = (float*)d_out;

    cudaFuncSetAttribute(edge_kernel_bf3,
                         cudaFuncAttributeMaxDynamicSharedMemorySize,
                         EDGE_DYN_BYTES);

    int nodeBlocks = (N + TS - 1) / TS;
    int edgeBlocks = (E + ET - 1) / ET;

    init_pre_kernel<<<nodeBlocks, NT>>>(an, emb, pos, e_w1, N);

    edge_kernel_bf3<<<edgeBlocks, 256, EDGE_DYN_BYTES>>>(
        eidx, eidx + E,
        e_w1 + 128 * 64, e_b1,
        e_w2, e_b2,
        x_w1, x_b1,
        x_w2, x_b2, E);

    update_pre_kernel<<<nodeBlocks, NT>>>(
        h_w1, h_b1, h_w2, h_b2,
        e_w1 + 129 * 64, N);

    edge_kernel_bf3<<<edgeBlocks, 256, EDGE_DYN_BYTES>>>(
        eidx, eidx + E,
        e_w1 + 129 * 64 + 128 * 64, e_b1 + 64,
        e_w2 + 4096, e_b2 + 64,
        x_w1 + 4096, x_b1 + 64,
        x_w2 + 64, x_b2 + 1, E);

    final_update_kernel<<<nodeBlocks, NT>>>(
        h_w1 + 128 * 64, h_b1 + 64,
        h_w2 + 4096, h_b2 + 64,
        out, out + (size_t)N * 64, N);
}

// round 11
// speedup vs baseline: 2.0623x; 1.1748x over previous
#include <cuda_runtime.h>
#include <cuda_bf16.h>
#include <cstdint>

#define NT 256          // node kernels: threads per block
#define TS 64           // node tile rows
#define LDA 68          // sA row stride (floats) for SIMT gemm
#define ET 192          // edge tile (edges per block)
#define ENT 384         // edge kernel threads (12 warps x 16 rows)
#define LW 36           // edge smem row stride in u32 (72 bf16)

typedef unsigned long long u64;

__device__ float g_h [50048 * 64];
__device__ float g_x [50048 * 3];
__device__ float g_Ad[50048 * 64];   // h @ e_w1[0:64]   (dst part)
__device__ float g_As[50048 * 64];   // h @ e_w1[64:128] (src part)
__device__ float g_m [50048 * 64];   // segment-sum of m_ij
__device__ float g_dx[50048 * 3];    // segment-sum of W_ij * x_diff

__device__ __forceinline__ float silu_f(float v) {
    return v / (1.0f + __expf(-v));
}
__device__ __forceinline__ u64 pdup(float x) {
    u64 r; asm("mov.b64 %0, {%1, %1};" : "=l"(r) : "f"(x)); return r;
}
__device__ __forceinline__ void up2(u64 v, float& a, float& b) {
    asm("mov.b64 {%0, %1}, %2;" : "=f"(a), "=f"(b) : "l"(v));
}
__device__ __forceinline__ void fma2(u64& c, u64 a, u64 b) {
    asm("fma.rn.f32x2 %0, %1, %2, %0;" : "+l"(c) : "l"(a), "l"(b));
}
__device__ __forceinline__ void red_add_v4(float* p, float a, float b, float c, float d) {
    asm volatile("red.global.add.v4.f32 [%0], {%1, %2, %3, %4};"
                 :: "l"(p), "f"(a), "f"(b), "f"(c), "f"(d) : "memory");
}
__device__ __forceinline__ uint32_t pbf2(float lo, float hi) {
    __nv_bfloat162 t;
    t.x = __float2bfloat16_rn(lo);
    t.y = __float2bfloat16_rn(hi);
    return *reinterpret_cast<uint32_t*>(&t);
}
__device__ __forceinline__ float bfhi(float x) {
    return __bfloat162float(__float2bfloat16_rn(x));
}
__device__ __forceinline__ float2 ubf2(uint32_t u) {
    __nv_bfloat162 t = *reinterpret_cast<__nv_bfloat162*>(&u);
    return make_float2(__bfloat162float(t.x), __bfloat162float(t.y));
}
__device__ __forceinline__ uint32_t smem_u32p(const void* p) {
    uint32_t a;
    asm("{ .reg .u64 t; cvta.to.shared.u64 t, %1; cvt.u32.u64 %0, t; }"
        : "=r"(a) : "l"(p));
    return a;
}
// D(16x8,f32) += A(16x16,bf16,row) * B(16x8,bf16,col)
__device__ __forceinline__ void mma_bf16(float c[4], const uint32_t a[4],
                                         uint32_t b0, uint32_t b1) {
    asm volatile(
        "mma.sync.aligned.m16n8k16.row.col.f32.bf16.bf16.f32 "
        "{%0,%1,%2,%3}, {%4,%5,%6,%7}, {%8,%9}, {%0,%1,%2,%3};"
        : "+f"(c[0]), "+f"(c[1]), "+f"(c[2]), "+f"(c[3])
        : "r"(a[0]), "r"(a[1]), "r"(a[2]), "r"(a[3]), "r"(b0), "r"(b1));
}
__device__ __forceinline__ void ldsm_x4(uint32_t r[4], uint32_t addr) {
    asm volatile("ldmatrix.sync.aligned.m8n8.x4.shared.b16 {%0,%1,%2,%3}, [%4];"
                 : "=r"(r[0]), "=r"(r[1]), "=r"(r[2]), "=r"(r[3]) : "r"(addr));
}

// 3-term bf16 split GEMM via ldmatrix. Warp owns 16 rows rbase..rbase+15.
__device__ __forceinline__ void gemm_bf3(uint32_t aH, uint32_t aL,
                                         uint32_t bH, uint32_t bL,
                                         int lane, int rbase,
                                         float acc[8][4]) {
    int l7 = lane & 7;
    int aRow = l7 + ((lane >> 3) & 1) * 8;      // row within 16-row tile
    int aColU = ((lane >> 4) & 1) * 4;          // k-half in u32
    int bRow = ((lane >> 4) << 3) + l7;         // n within 16-n pair
    int bColU = ((lane >> 3) & 1) * 4;
#pragma unroll
    for (int c = 0; c < 4; c++) {
        int kc = c * 8;                         // u32 k base
        uint32_t ah[4], al[4];
        uint32_t off = (uint32_t)((rbase + aRow) * LW + kc + aColU) * 4u;
        ldsm_x4(ah, aH + off);
        ldsm_x4(al, aL + off);
#pragma unroll
        for (int ntp = 0; ntp < 4; ntp++) {
            uint32_t boff = (uint32_t)((ntp * 16 + bRow) * LW + kc + bColU) * 4u;
            uint32_t bh[4], bl[4];
            ldsm_x4(bh, bH + boff);
            ldsm_x4(bl, bL + boff);
            int n0 = 2 * ntp, n1 = 2 * ntp + 1;
            mma_bf16(acc[n0], ah, bh[0], bh[1]);
            mma_bf16(acc[n0], ah, bl[0], bl[1]);
            mma_bf16(acc[n0], al, bh[0], bh[1]);
            mma_bf16(acc[n1], ah, bh[2], bh[3]);
            mma_bf16(acc[n1], ah, bl[2], bl[3]);
            mma_bf16(acc[n1], al, bh[2], bh[3]);
        }
    }
}

// ===================== SIMT gemm (node kernels, R4-proven) ==================
__device__ __forceinline__ void gemm_t(const float* __restrict__ sA,
                                       const float* __restrict__ sW,
                                       int tx, int ty, u64 acc[4][2]) {
    const float* aR = sA + ty * 4 * LDA;
    const float* bC = sW + tx * 4;
#pragma unroll
    for (int kb = 0; kb < 64; kb += 4) {
        float4 av[4];
#pragma unroll
        for (int i = 0; i < 4; i++)
            av[i] = *(const float4*)(aR + i * LDA + kb);
#pragma unroll
        for (int kk = 0; kk < 4; kk++) {
            ulonglong2 b = *(const ulonglong2*)(bC + (kb + kk) * 64);
#pragma unroll
            for (int i = 0; i < 4; i++) {
                float a = (kk == 0) ? av[i].x : (kk == 1) ? av[i].y
                        : (kk == 2) ? av[i].z : av[i].w;
                u64 aa = pdup(a);
                fma2(acc[i][0], aa, b.x);
                fma2(acc[i][1], aa, b.y);
            }
        }
    }
}

#define ZERO_ACC(acc)                             \
    _Pragma("unroll") for (int i_ = 0; i_ < 4; i_++) { (acc)[i_][0] = 0ull; (acc)[i_][1] = 0ull; }
#define UNPACK_ROW(acc_row, c)  \
    up2((acc_row)[0], (c)[0], (c)[1]); up2((acc_row)[1], (c)[2], (c)[3]);

// ---------------------------------------------------------------------------
// Fused init + node_pre (layer 0)
__global__ __launch_bounds__(NT)
void init_pre_kernel(const int* __restrict__ an, const float* __restrict__ emb,
                     const float* __restrict__ pos, const float* __restrict__ w1,
                     int N) {
    __shared__ float sA[TS * LDA];
    __shared__ float sW[4096];
    int tid = threadIdx.x;
    int n0 = blockIdx.x * TS;
    int tx = tid & 15, ty = tid >> 4;

    for (int p = tid; p < TS * 16; p += NT) {
        int i = p >> 4, j = (p & 15) * 4;
        int n = n0 + i;
        float4 v = make_float4(0.f, 0.f, 0.f, 0.f);
        if (n < N) {
            v = *(const float4*)&emb[an[n] * 64 + j];
            *(float4*)&g_h[n * 64 + j] = v;
            *(float4*)&g_m[n * 64 + j] = make_float4(0.f, 0.f, 0.f, 0.f);
        }
        *(float4*)&sA[i * LDA + j] = v;
    }
    if (tid < TS * 3) {
        int idx = n0 * 3 + tid;
        if (idx < N * 3) { g_x[idx] = pos[idx]; g_dx[idx] = 0.f; }
    }
    for (int p = tid; p < 1024; p += NT)
        *(float4*)&sW[p * 4] = *(const float4*)&w1[p * 4];
    __syncthreads();

    u64 acc[4][2];
    ZERO_ACC(acc);
    gemm_t(sA, sW, tx, ty, acc);
#pragma unroll
    for (int i = 0; i < 4; i++) {
        int n = n0 + ty * 4 + i;
        if (n < N) {
            float c[4]; UNPACK_ROW(acc[i], c);
            *(float4*)&g_Ad[n * 64 + tx * 4] = make_float4(c[0], c[1], c[2], c[3]);
        }
    }
    __syncthreads();
    for (int p = tid; p < 1024; p += NT)
        *(float4*)&sW[p * 4] = *(const float4*)&w1[4096 + p * 4];
    __syncthreads();
    ZERO_ACC(acc);
    gemm_t(sA, sW, tx, ty, acc);
#pragma unroll
    for (int i = 0; i < 4; i++) {
        int n = n0 + ty * 4 + i;
        if (n < N) {
            float c[4]; UNPACK_ROW(acc[i], c);
            *(float4*)&g_As[n * 64 + tx * 4] = make_float4(c[0], c[1], c[2], c[3]);
        }
    }
}

// ---------------------------------------------------------------------------
// 3xBF16 edge kernel: ET=192 edges/block, 384 threads (12 warps x 16 rows).
__global__ __launch_bounds__(ENT, 2)
void edge_kernel_bf3(const int* __restrict__ src, const int* __restrict__ dst,
                     const float* __restrict__ w1r, const float* __restrict__ b1,
                     const float* __restrict__ w2,  const float* __restrict__ b2,
                     const float* __restrict__ xw1, const float* __restrict__ xb1,
                     const float* __restrict__ xw2, const float* __restrict__ xb2,
                     int E) {
    extern __shared__ uint32_t dynu[];
    uint32_t* sAh  = dynu;                   // [ET][LW]
    uint32_t* sAl  = sAh + ET * LW;
    uint32_t* sB0h = sAl + ET * LW;          // w2  [64][LW]
    uint32_t* sB0l = sB0h + 64 * LW;
    uint32_t* sB1h = sB0l + 64 * LW;         // xw1 [64][LW]
    uint32_t* sB1l = sB1h + 64 * LW;
    __shared__ int   sdst[ET], ssrc[ET];
    __shared__ float srwe[ET];               // sr (pre-sync) aliased with sWe (post)
    __shared__ float sw1r[64], sb1v[64], sb2v[64], sxb1[64], sxw2[64];

    int tid = threadIdx.x;
    int lane = tid & 31, warp = tid >> 5;
    int gr = lane >> 2, gc = lane & 3;
    int e0 = blockIdx.x * ET;
    int rbase = warp * 16;

    uint32_t aH = smem_u32p(sAh), aL = smem_u32p(sAl);
    uint32_t b0H = smem_u32p(sB0h), b0L = smem_u32p(sB0l);
    uint32_t b1H = smem_u32p(sB1h), b1L = smem_u32p(sB1l);

    // per-edge metadata (threads 0..ET-1 own one edge each)
    int my_d = -1;
    float xd0 = 0.f, xd1 = 0.f, xd2 = 0.f;
    if (tid < ET) {
        int eg = e0 + tid;
        int s = 0;
        if (eg < E) {
            s = src[eg]; my_d = dst[eg];
            xd0 = g_x[s * 3 + 0] - g_x[my_d * 3 + 0];
            xd1 = g_x[s * 3 + 1] - g_x[my_d * 3 + 1];
            xd2 = g_x[s * 3 + 2] - g_x[my_d * 3 + 2];
        }
        ssrc[tid] = s; sdst[tid] = my_d;
        srwe[tid] = sqrtf(xd0 * xd0 + xd1 * xd1 + xd2 * xd2);
    }
    if (tid >= 256 && tid < 320) {
        int j = tid - 256;
        sw1r[j] = w1r[j]; sb1v[j] = b1[j]; sb2v[j] = b2[j];
        sxb1[j] = xb1[j]; sxw2[j] = xw2[j];
    }
    // stage BOTH weights (n-major, hi/lo bf16)
    for (int p = tid; p < 2048; p += ENT) {
        int k2 = p >> 6, n = p & 63;
        float a0 = w2[(k2 * 2) * 64 + n];
        float a1 = w2[(k2 * 2 + 1) * 64 + n];
        float h0 = bfhi(a0), h1 = bfhi(a1);
        sB0h[n * LW + k2] = pbf2(h0, h1);
        sB0l[n * LW + k2] = pbf2(a0 - h0, a1 - h1);
        float c0 = xw1[(k2 * 2) * 64 + n];
        float c1 = xw1[(k2 * 2 + 1) * 64 + n];
        float g0 = bfhi(c0), g1 = bfhi(c1);
        sB1h[n * LW + k2] = pbf2(g0, g1);
        sB1l[n * LW + k2] = pbf2(c0 - g0, c1 - g1);
    }
    __syncthreads();   // metadata + weights visible

    // stage t1 = silu(Ad[dst]+As[src]+r*w1r+b1), split hi/lo
    for (int p = tid; p < ET * 16; p += ENT) {
        int e = p >> 4, j = (p & 15) * 4;
        int d = sdst[e];
        int dd = d < 0 ? 0 : d;
        int s  = ssrc[e];
        float4 ad = *(const float4*)&g_Ad[dd * 64 + j];
        float4 as = *(const float4*)&g_As[s * 64 + j];
        float r = srwe[e];
        float t0 = silu_f(ad.x + as.x + r * sw1r[j + 0] + sb1v[j + 0]);
        float t1 = silu_f(ad.y + as.y + r * sw1r[j + 1] + sb1v[j + 1]);
        float t2 = silu_f(ad.z + as.z + r * sw1r[j + 2] + sb1v[j + 2]);
        float t3 = silu_f(ad.w + as.w + r * sw1r[j + 3] + sb1v[j + 3]);
        float h0 = bfhi(t0), h1 = bfhi(t1), h2 = bfhi(t2), h3 = bfhi(t3);
        int o = e * LW + (j >> 1);
        sAh[o]     = pbf2(h0, h1);
        sAh[o + 1] = pbf2(h2, h3);
        sAl[o]     = pbf2(t0 - h0, t1 - h1);
        sAl[o + 1] = pbf2(t2 - h2, t3 - h3);
    }
    __syncthreads();   // t1 fully staged

    float acc[8][4];
#pragma unroll
    for (int nt = 0; nt < 8; nt++)
#pragma unroll
        for (int q = 0; q < 4; q++) acc[nt][q] = 0.f;

    gemm_bf3(aH, aL, b0H, b0L, lane, rbase, acc);   // GEMM1: t1 @ w2

    // epilogue 1: m = silu(D + b2) -> rewrite own A rows (hi/lo)
    {
        int ra = rbase + gr, rb = ra + 8;
#pragma unroll
        for (int nt = 0; nt < 8; nt++) {
            int col = nt * 8 + gc * 2;
            float m00 = silu_f(acc[nt][0] + sb2v[col]);
            float m01 = silu_f(acc[nt][1] + sb2v[col + 1]);
            float m10 = silu_f(acc[nt][2] + sb2v[col]);
            float m11 = silu_f(acc[nt][3] + sb2v[col + 1]);
            float h00 = bfhi(m00), h01 = bfhi(m01);
            float h10 = bfhi(m10), h11 = bfhi(m11);
            int oa = ra * LW + nt * 4 + gc, ob = rb * LW + nt * 4 + gc;
            sAh[oa] = pbf2(h00, h01);
            sAl[oa] = pbf2(m00 - h00, m01 - h01);
            sAh[ob] = pbf2(h10, h11);
            sAl[ob] = pbf2(m10 - h10, m11 - h11);
        }
    }
    __syncwarp();

    // coalesced m-scatter (m = hi + lo, exact): 16 rows x 16 v4-groups per warp
    for (int i = lane; i < 16 * 16; i += 32) {
        int row = rbase + (i >> 4);
        int j2 = (i & 15) * 2;             // u32 offset within row
        int d = sdst[row];
        if (d >= 0) {
            uint32_t h0 = sAh[row * LW + j2], h1 = sAh[row * LW + j2 + 1];
            uint32_t l0 = sAl[row * LW + j2], l1 = sAl[row * LW + j2 + 1];
            float2 fh0 = ubf2(h0), fh1 = ubf2(h1);
            float2 fl0 = ubf2(l0), fl1 = ubf2(l1);
            red_add_v4(&g_m[d * 64 + j2 * 2],
                       fh0.x + fl0.x, fh0.y + fl0.y,
                       fh1.x + fl1.x, fh1.y + fl1.y);
        }
    }
    __syncwarp();

#pragma unroll
    for (int nt = 0; nt < 8; nt++)
#pragma unroll
        for (int q = 0; q < 4; q++) acc[nt][q] = 0.f;

    gemm_bf3(aH, aL, b1H, b1L, lane, rbase, acc);   // GEMM2: m @ xw1

    // epilogue 2: W = silu(D + xb1) . xw2 + xb2
    {
        float Wv0 = 0.f, Wv1 = 0.f;
#pragma unroll
        for (int nt = 0; nt < 8; nt++) {
            int col = nt * 8 + gc * 2;
            Wv0 += silu_f(acc[nt][0] + sxb1[col]) * sxw2[col]
                 + silu_f(acc[nt][1] + sxb1[col + 1]) * sxw2[col + 1];
            Wv1 += silu_f(acc[nt][2] + sxb1[col]) * sxw2[col]
                 + silu_f(acc[nt][3] + sxb1[col + 1]) * sxw2[col + 1];
        }
#pragma unroll
        for (int off = 1; off <= 2; off <<= 1) {
            Wv0 += __shfl_xor_sync(0xffffffffu, Wv0, off);
            Wv1 += __shfl_xor_sync(0xffffffffu, Wv1, off);
        }
        if (gc == 0) {
            float xb2v = __ldg(xb2);
            srwe[rbase + gr]     = Wv0 + xb2v;
            srwe[rbase + gr + 8] = Wv1 + xb2v;
        }
    }
    // Row tid is owned by warp tid/16 but thread tid is in warp tid/32:
    // sWe values cross warps -> need a block barrier, not __syncwarp (R10 bug).
    __syncthreads();

    // dx scatter: own edge from registers
    if (my_d >= 0) {
        float W = srwe[tid];
        atomicAdd(&g_dx[my_d * 3 + 0], W * xd0);
        atomicAdd(&g_dx[my_d * 3 + 1], W * xd1);
        atomicAdd(&g_dx[my_d * 3 + 2], W * xd2);
    }
}

#define EDGE_DYN_BYTES ((2 * ET * LW + 4 * 64 * LW) * 4)

// ---------------------------------------------------------------------------
// Fused node_update + node_pre(next layer). Zeroes m/dx after reading.
__global__ __launch_bounds__(NT)
void update_pre_kernel(const float* __restrict__ hw1, const float* __restrict__ hb1,
                       const float* __restrict__ hw2, const float* __restrict__ hb2,
                       const float* __restrict__ ew1n, int N) {
    __shared__ float sA[TS * LDA];
    __shared__ float sW[4096];
    int tid = threadIdx.x;
    int n0 = blockIdx.x * TS;
    int tx = tid & 15, ty = tid >> 4;

    for (int p = tid; p < TS * 16; p += NT) {
        int i = p >> 4, j = (p & 15) * 4;
        int n = n0 + i;
        float4 v = make_float4(0.f, 0.f, 0.f, 0.f);
        if (n < N) v = *(const float4*)&g_h[n * 64 + j];
        *(float4*)&sA[i * LDA + j] = v;
    }
    for (int p = tid; p < 1024; p += NT)
        *(float4*)&sW[p * 4] = *(const float4*)&hw1[p * 4];
    __syncthreads();

    u64 acc[4][2];
    ZERO_ACC(acc);
    gemm_t(sA, sW, tx, ty, acc);
    __syncthreads();

    for (int p = tid; p < TS * 16; p += NT) {
        int i = p >> 4, j = (p & 15) * 4;
        int n = n0 + i;
        float4 v = make_float4(0.f, 0.f, 0.f, 0.f);
        if (n < N) {
            v = *(const float4*)&g_m[n * 64 + j];
            *(float4*)&g_m[n * 64 + j] = make_float4(0.f, 0.f, 0.f, 0.f);
        }
        *(float4*)&sA[i * LDA + j] = v;
    }
    for (int p = tid; p < 1024; p += NT)
        *(float4*)&sW[p * 4] = *(const float4*)&hw1[4096 + p * 4];
    __syncthreads();
    gemm_t(sA, sW, tx, ty, acc);
    __syncthreads();

#pragma unroll
    for (int i = 0; i < 4; i++) {
        int e = ty * 4 + i;
        float c[4]; UNPACK_ROW(acc[i], c);
#pragma unroll
        for (int q = 0; q < 4; q++) c[q] = silu_f(c[q] + hb1[tx * 4 + q]);
        *(float4*)&sA[e * LDA + tx * 4] = make_float4(c[0], c[1], c[2], c[3]);
    }
    for (int p = tid; p < 1024; p += NT)
        *(float4*)&sW[p * 4] = *(const float4*)&hw2[p * 4];
    __syncthreads();

    ZERO_ACC(acc);
    gemm_t(sA, sW, tx, ty, acc);
    __syncthreads();

#pragma unroll
    for (int i = 0; i < 4; i++) {
        int n = n0 + ty * 4 + i;
        if (n < N) {
            float c[4]; UNPACK_ROW(acc[i], c);
            float4 o = *(const float4*)&g_h[n * 64 + tx * 4];
            o.x += c[0] + hb2[tx * 4 + 0];
            o.y += c[1] + hb2[tx * 4 + 1];
            o.z += c[2] + hb2[tx * 4 + 2];
            o.w += c[3] + hb2[tx * 4 + 3];
            *(float4*)&g_h[n * 64 + tx * 4] = o;
            *(float4*)&sA[(ty * 4 + i) * LDA + tx * 4] = o;
        } else {
            *(float4*)&sA[(ty * 4 + i) * LDA + tx * 4] = make_float4(0.f, 0.f, 0.f, 0.f);
        }
    }
    if (tid < TS * 3) {
        int idx = n0 * 3 + tid;
        if (idx < N * 3) {
            g_x[idx] = g_x[idx] + g_dx[idx];
            g_dx[idx] = 0.f;
        }
    }
    for (int p = tid; p < 1024; p += NT)
        *(float4*)&sW[p * 4] = *(const float4*)&ew1n[p * 4];
    __syncthreads();

    ZERO_ACC(acc);
    gemm_t(sA, sW, tx, ty, acc);
#pragma unroll
    for (int i = 0; i < 4; i++) {
        int n = n0 + ty * 4 + i;
        if (n < N) {
            float c[4]; UNPACK_ROW(acc[i], c);
            *(float4*)&g_Ad[n * 64 + tx * 4] = make_float4(c[0], c[1], c[2], c[3]);
        }
    }
    __syncthreads();
    for (int p = tid; p < 1024; p += NT)
        *(float4*)&sW[p * 4] = *(const float4*)&ew1n[4096 + p * 4];
    __syncthreads();
    ZERO_ACC(acc);
    gemm_t(sA, sW, tx, ty, acc);
#pragma unroll
    for (int i = 0; i < 4; i++) {
        int n = n0 + ty * 4 + i;
        if (n < N) {
            float c[4]; UNPACK_ROW(acc[i], c);
            *(float4*)&g_As[n * 64 + tx * 4] = make_float4(c[0], c[1], c[2], c[3]);
        }
    }
}

// ---------------------------------------------------------------------------
__global__ __launch_bounds__(NT)
void final_update_kernel(const float* __restrict__ hw1, const float* __restrict__ hb1,
                         const float* __restrict__ hw2, const float* __restrict__ hb2,
                         float* __restrict__ outh, float* __restrict__ outx, int N) {
    __shared__ float sA[TS * LDA];
    __shared__ float sW[4096];
    int tid = threadIdx.x;
    int n0 = blockIdx.x * TS;
    int tx = tid & 15, ty = tid >> 4;

    for (int p = tid; p < TS * 16; p += NT) {
        int i = p >> 4, j = (p & 15) * 4;
        int n = n0 + i;
        float4 v = make_float4(0.f, 0.f, 0.f, 0.f);
        if (n < N) v = *(const float4*)&g_h[n * 64 + j];
        *(float4*)&sA[i * LDA + j] = v;
    }
    for (int p = tid; p < 1024; p += NT)
        *(float4*)&sW[p * 4] = *(const float4*)&hw1[p * 4];
    __syncthreads();

    u64 acc[4][2];
    ZERO_ACC(acc);
    gemm_t(sA, sW, tx, ty, acc);
    __syncthreads();

    for (int p = tid; p < TS * 16; p += NT) {
        int i = p >> 4, j = (p & 15) * 4;
        int n = n0 + i;
        float4 v = make_float4(0.f, 0.f, 0.f, 0.f);
        if (n < N) v = *(const float4*)&g_m[n * 64 + j];
        *(float4*)&sA[i * LDA + j] = v;
    }
    for (int p = tid; p < 1024; p += NT)
        *(float4*)&sW[p * 4] = *(const float4*)&hw1[4096 + p * 4];
    __syncthreads();
    gemm_t(sA, sW, tx, ty, acc);
    __syncthreads();

#pragma unroll
    for (int i = 0; i < 4; i++) {
        int e = ty * 4 + i;
        float c[4]; UNPACK_ROW(acc[i], c);
#pragma unroll
        for (int q = 0; q < 4; q++) c[q] = silu_f(c[q] + hb1[tx * 4 + q]);
        *(float4*)&sA[e * LDA + tx * 4] = make_float4(c[0], c[1], c[2], c[3]);
    }
    for (int p = tid; p < 1024; p += NT)
        *(float4*)&sW[p * 4] = *(const float4*)&hw2[p * 4];
    __syncthreads();

    ZERO_ACC(acc);
    gemm_t(sA, sW, tx, ty, acc);

#pragma unroll
    for (int i = 0; i < 4; i++) {
        int n = n0 + ty * 4 + i;
        if (n < N) {
            float c[4]; UNPACK_ROW(acc[i], c);
            float4 o = *(const float4*)&g_h[n * 64 + tx * 4];
            o.x += c[0] + hb2[tx * 4 + 0];
            o.y += c[1] + hb2[tx * 4 + 1];
            o.z += c[2] + hb2[tx * 4 + 2];
            o.w += c[3] + hb2[tx * 4 + 3];
            *(float4*)&outh[n * 64 + tx * 4] = o;
        }
    }
    if (tid < TS * 3) {
        int idx = n0 * 3 + tid;
        if (idx < N * 3) outx[idx] = g_x[idx] + g_dx[idx];
    }
}

// ---------------------------------------------------------------------------
extern "C" void kernel_launch(void* const* d_in, const int* in_sizes, int n_in,
                              void* d_out, int out_size) {
    const int*   an   = (const int*)d_in[0];
    const float* pos  = (const float*)d_in[1];
    const int*   eidx = (const int*)d_in[2];
    // d_in[3] = edge_attr (unused by reference)
    const float* emb  = (const float*)d_in[4];
    const float* e_w1 = (const float*)d_in[5];
    const float* e_b1 = (const float*)d_in[6];
    const float* e_w2 = (const float*)d_in[7];
    const float* e_b2 = (const float*)d_in[8];
    const float* h_w1 = (const float*)d_in[9];
    const float* h_b1 = (const float*)d_in[10];
    const float* h_w2 = (const float*)d_in[11];
    const float* h_b2 = (const float*)d_in[12];
    const float* x_w1 = (const float*)d_in[13];
    const float* x_b1 = (const float*)d_in[14];
    const float* x_w2 = (const float*)d_in[15];
    const float* x_b2 = (const float*)d_in[16];

    int N = in_sizes[0];
    int E = in_sizes[2] / 2;
    float* out = (float*)d_out;

    cudaFuncSetAttribute(edge_kernel_bf3,
                         cudaFuncAttributeMaxDynamicSharedMemorySize,
                         EDGE_DYN_BYTES);

    int nodeBlocks = (N + TS - 1) / TS;
    int edgeBlocks = (E + ET - 1) / ET;

    init_pre_kernel<<<nodeBlocks, NT>>>(an, emb, pos, e_w1, N);

    edge_kernel_bf3<<<edgeBlocks, ENT, EDGE_DYN_BYTES>>>(
        eidx, eidx + E,
        e_w1 + 128 * 64, e_b1,
        e_w2, e_b2,
        x_w1, x_b1,
        x_w2, x_b2, E);

    update_pre_kernel<<<nodeBlocks, NT>>>(
        h_w1, h_b1, h_w2, h_b2,
        e_w1 + 129 * 64, N);

    edge_kernel_bf3<<<edgeBlocks, ENT, EDGE_DYN_BYTES>>>(
        eidx, eidx + E,
        e_w1 + 129 * 64 + 128 * 64, e_b1 + 64,
        e_w2 + 4096, e_b2 + 64,
        x_w1 + 4096, x_b1 + 64,
        x_w2 + 64, x_b2 + 1, E);

    final_update_kernel<<<nodeBlocks, NT>>>(
        h_w1 + 128 * 64, h_b1 + 64,
        h_w2 + 4096, h_b2 + 64,
        out, out + (size_t)N * 64, N);
}

// round 12
// speedup vs baseline: 2.1076x; 1.0220x over previous
#include <cuda_runtime.h>
#include <cuda_bf16.h>
#include <cstdint>

#define NT 256          // node kernels: threads per block
#define TS 64           // node tile rows
#define LDA 68          // sA row stride (floats) for SIMT gemm
#define ET 192          // edge tile (edges per block)
#define ENT 384         // edge kernel threads (12 warps x 16 rows)
#define LW 36           // edge smem row stride in u32 (72 bf16)

typedef unsigned long long u64;

__device__ float g_h [50048 * 64];
__device__ float g_x [50048 * 3];
__device__ float g_Ad[50048 * 64];   // h @ e_w1[0:64]   (dst part)
__device__ float g_As[50048 * 64];   // h @ e_w1[64:128] (src part)
__device__ float g_m [50048 * 64];   // segment-sum of m_ij
__device__ float g_dx[50048 * 3];    // segment-sum of W_ij * x_diff

__device__ __forceinline__ float silu_f(float v) {
    return v / (1.0f + __expf(-v));
}
__device__ __forceinline__ u64 pdup(float x) {
    u64 r; asm("mov.b64 %0, {%1, %1};" : "=l"(r) : "f"(x)); return r;
}
__device__ __forceinline__ void up2(u64 v, float& a, float& b) {
    asm("mov.b64 {%0, %1}, %2;" : "=f"(a), "=f"(b) : "l"(v));
}
__device__ __forceinline__ void fma2(u64& c, u64 a, u64 b) {
    asm("fma.rn.f32x2 %0, %1, %2, %0;" : "+l"(c) : "l"(a), "l"(b));
}
__device__ __forceinline__ void red_add_v4(float* p, float a, float b, float c, float d) {
    asm volatile("red.global.add.v4.f32 [%0], {%1, %2, %3, %4};"
                 :: "l"(p), "f"(a), "f"(b), "f"(c), "f"(d) : "memory");
}
__device__ __forceinline__ uint32_t pbf2(float lo, float hi) {
    __nv_bfloat162 t;
    t.x = __float2bfloat16_rn(lo);
    t.y = __float2bfloat16_rn(hi);
    return *reinterpret_cast<uint32_t*>(&t);
}
__device__ __forceinline__ float bfhi(float x) {
    return __bfloat162float(__float2bfloat16_rn(x));
}
__device__ __forceinline__ float2 ubf2(uint32_t u) {
    __nv_bfloat162 t = *reinterpret_cast<__nv_bfloat162*>(&u);
    return make_float2(__bfloat162float(t.x), __bfloat162float(t.y));
}
__device__ __forceinline__ uint32_t smem_u32p(const void* p) {
    uint32_t a;
    asm("{ .reg .u64 t; cvta.to.shared.u64 t, %1; cvt.u32.u64 %0, t; }"
        : "=r"(a) : "l"(p));
    return a;
}
// D(16x8,f32) += A(16x16,bf16,row) * B(16x8,bf16,col)
__device__ __forceinline__ void mma_bf16(float c[4], const uint32_t a[4],
                                         uint32_t b0, uint32_t b1) {
    asm volatile(
        "mma.sync.aligned.m16n8k16.row.col.f32.bf16.bf16.f32 "
        "{%0,%1,%2,%3}, {%4,%5,%6,%7}, {%8,%9}, {%0,%1,%2,%3};"
        : "+f"(c[0]), "+f"(c[1]), "+f"(c[2]), "+f"(c[3])
        : "r"(a[0]), "r"(a[1]), "r"(a[2]), "r"(a[3]), "r"(b0), "r"(b1));
}
__device__ __forceinline__ void ldsm_x4(uint32_t r[4], uint32_t addr) {
    asm volatile("ldmatrix.sync.aligned.m8n8.x4.shared.b16 {%0,%1,%2,%3}, [%4];"
                 : "=r"(r[0]), "=r"(r[1]), "=r"(r[2]), "=r"(r[3]) : "r"(addr));
}

// 3-term bf16 split GEMM via ldmatrix. Warp owns 16 rows rbase..rbase+15.
__device__ __forceinline__ void gemm_bf3(uint32_t aH, uint32_t aL,
                                         uint32_t bH, uint32_t bL,
                                         int lane, int rbase,
                                         float acc[8][4]) {
    int l7 = lane & 7;
    int aRow = l7 + ((lane >> 3) & 1) * 8;      // row within 16-row tile
    int aColU = ((lane >> 4) & 1) * 4;          // k-half in u32
    int bRow = ((lane >> 4) << 3) + l7;         // n within 16-n pair
    int bColU = ((lane >> 3) & 1) * 4;
#pragma unroll
    for (int c = 0; c < 4; c++) {
        int kc = c * 8;                         // u32 k base
        uint32_t ah[4], al[4];
        uint32_t off = (uint32_t)((rbase + aRow) * LW + kc + aColU) * 4u;
        ldsm_x4(ah, aH + off);
        ldsm_x4(al, aL + off);
#pragma unroll
        for (int ntp = 0; ntp < 4; ntp++) {
            uint32_t boff = (uint32_t)((ntp * 16 + bRow) * LW + kc + bColU) * 4u;
            uint32_t bh[4], bl[4];
            ldsm_x4(bh, bH + boff);
            ldsm_x4(bl, bL + boff);
            int n0 = 2 * ntp, n1 = 2 * ntp + 1;
            mma_bf16(acc[n0], ah, bh[0], bh[1]);
            mma_bf16(acc[n0], ah, bl[0], bl[1]);
            mma_bf16(acc[n0], al, bh[0], bh[1]);
            mma_bf16(acc[n1], ah, bh[2], bh[3]);
            mma_bf16(acc[n1], ah, bl[2], bl[3]);
            mma_bf16(acc[n1], al, bh[2], bh[3]);
        }
    }
}

// ===================== SIMT gemm (node kernels, R4-proven) ==================
__device__ __forceinline__ void gemm_t(const float* __restrict__ sA,
                                       const float* __restrict__ sW,
                                       int tx, int ty, u64 acc[4][2]) {
    const float* aR = sA + ty * 4 * LDA;
    const float* bC = sW + tx * 4;
#pragma unroll
    for (int kb = 0; kb < 64; kb += 4) {
        float4 av[4];
#pragma unroll
        for (int i = 0; i < 4; i++)
            av[i] = *(const float4*)(aR + i * LDA + kb);
#pragma unroll
        for (int kk = 0; kk < 4; kk++) {
            ulonglong2 b = *(const ulonglong2*)(bC + (kb + kk) * 64);
#pragma unroll
            for (int i = 0; i < 4; i++) {
                float a = (kk == 0) ? av[i].x : (kk == 1) ? av[i].y
                        : (kk == 2) ? av[i].z : av[i].w;
                u64 aa = pdup(a);
                fma2(acc[i][0], aa, b.x);
                fma2(acc[i][1], aa, b.y);
            }
        }
    }
}

#define ZERO_ACC(acc)                             \
    _Pragma("unroll") for (int i_ = 0; i_ < 4; i_++) { (acc)[i_][0] = 0ull; (acc)[i_][1] = 0ull; }
#define UNPACK_ROW(acc_row, c)  \
    up2((acc_row)[0], (c)[0], (c)[1]); up2((acc_row)[1], (c)[2], (c)[3]);

// ---------------------------------------------------------------------------
// Fused init + node_pre (layer 0)
__global__ __launch_bounds__(NT)
void init_pre_kernel(const int* __restrict__ an, const float* __restrict__ emb,
                     const float* __restrict__ pos, const float* __restrict__ w1,
                     int N) {
    __shared__ float sA[TS * LDA];
    __shared__ float sW[4096];
    int tid = threadIdx.x;
    int n0 = blockIdx.x * TS;
    int tx = tid & 15, ty = tid >> 4;

    for (int p = tid; p < TS * 16; p += NT) {
        int i = p >> 4, j = (p & 15) * 4;
        int n = n0 + i;
        float4 v = make_float4(0.f, 0.f, 0.f, 0.f);
        if (n < N) {
            v = *(const float4*)&emb[an[n] * 64 + j];
            *(float4*)&g_h[n * 64 + j] = v;
            *(float4*)&g_m[n * 64 + j] = make_float4(0.f, 0.f, 0.f, 0.f);
        }
        *(float4*)&sA[i * LDA + j] = v;
    }
    if (tid < TS * 3) {
        int idx = n0 * 3 + tid;
        if (idx < N * 3) { g_x[idx] = pos[idx]; g_dx[idx] = 0.f; }
    }
    for (int p = tid; p < 1024; p += NT)
        *(float4*)&sW[p * 4] = *(const float4*)&w1[p * 4];
    __syncthreads();

    u64 acc[4][2];
    ZERO_ACC(acc);
    gemm_t(sA, sW, tx, ty, acc);
#pragma unroll
    for (int i = 0; i < 4; i++) {
        int n = n0 + ty * 4 + i;
        if (n < N) {
            float c[4]; UNPACK_ROW(acc[i], c);
            *(float4*)&g_Ad[n * 64 + tx * 4] = make_float4(c[0], c[1], c[2], c[3]);
        }
    }
    __syncthreads();
    for (int p = tid; p < 1024; p += NT)
        *(float4*)&sW[p * 4] = *(const float4*)&w1[4096 + p * 4];
    __syncthreads();
    ZERO_ACC(acc);
    gemm_t(sA, sW, tx, ty, acc);
#pragma unroll
    for (int i = 0; i < 4; i++) {
        int n = n0 + ty * 4 + i;
        if (n < N) {
            float c[4]; UNPACK_ROW(acc[i], c);
            *(float4*)&g_As[n * 64 + tx * 4] = make_float4(c[0], c[1], c[2], c[3]);
        }
    }
}

// ---------------------------------------------------------------------------
// 3xBF16 edge kernel: ET=192 edges/block, 384 threads (12 warps x 16 rows).
// Warp-synchronous: ONE block barrier (weights), everything else warp-local.
__global__ __launch_bounds__(ENT, 2)
void edge_kernel_bf3(const int* __restrict__ src, const int* __restrict__ dst,
                     const float* __restrict__ w1r, const float* __restrict__ b1,
                     const float* __restrict__ w2,  const float* __restrict__ b2,
                     const float* __restrict__ xw1, const float* __restrict__ xb1,
                     const float* __restrict__ xw2, const float* __restrict__ xb2,
                     int E) {
    extern __shared__ uint32_t dynu[];
    uint32_t* sAh  = dynu;                   // [ET][LW]
    uint32_t* sAl  = sAh + ET * LW;
    uint32_t* sB0h = sAl + ET * LW;          // w2  [64][LW]
    uint32_t* sB0l = sB0h + 64 * LW;
    uint32_t* sB1h = sB0l + 64 * LW;         // xw1 [64][LW]
    uint32_t* sB1l = sB1h + 64 * LW;
    __shared__ int   sdst[ET], ssrc[ET];
    __shared__ float sxd[ET * 3];
    __shared__ float srwe[ET];               // r (pre) aliased with W (post), warp-local
    __shared__ float sw1r[64], sb1v[64], sb2v[64], sxb1[64], sxw2[64];

    int tid = threadIdx.x;
    int lane = tid & 31, warp = tid >> 5;
    int gr = lane >> 2, gc = lane & 3;
    int e0 = blockIdx.x * ET;
    int rbase = warp * 16;

    uint32_t aH = smem_u32p(sAh), aL = smem_u32p(sAl);
    uint32_t b0H = smem_u32p(sB0h), b0L = smem_u32p(sB0l);
    uint32_t b1H = smem_u32p(sB1h), b1L = smem_u32p(sB1l);

    // warp-local metadata: lanes 0..15 own rows rbase+lane
    if (lane < 16) {
        int row = rbase + lane;
        int eg = e0 + row;
        int s = 0, d = -1;
        float d0 = 0.f, d1 = 0.f, d2 = 0.f;
        if (eg < E) {
            s = src[eg]; d = dst[eg];
            d0 = g_x[s * 3 + 0] - g_x[d * 3 + 0];
            d1 = g_x[s * 3 + 1] - g_x[d * 3 + 1];
            d2 = g_x[s * 3 + 2] - g_x[d * 3 + 2];
        }
        ssrc[row] = s; sdst[row] = d;
        sxd[row * 3 + 0] = d0; sxd[row * 3 + 1] = d1; sxd[row * 3 + 2] = d2;
        srwe[row] = sqrtf(d0 * d0 + d1 * d1 + d2 * d2);
    }
    if (tid >= 256 && tid < 320) {
        int j = tid - 256;
        sw1r[j] = w1r[j]; sb1v[j] = b1[j]; sb2v[j] = b2[j];
        sxb1[j] = xb1[j]; sxw2[j] = xw2[j];
    }
    // stage BOTH weights (n-major, hi/lo bf16), block-strided
    for (int p = tid; p < 2048; p += ENT) {
        int k2 = p >> 6, n = p & 63;
        float a0 = w2[(k2 * 2) * 64 + n];
        float a1 = w2[(k2 * 2 + 1) * 64 + n];
        float h0 = bfhi(a0), h1 = bfhi(a1);
        sB0h[n * LW + k2] = pbf2(h0, h1);
        sB0l[n * LW + k2] = pbf2(a0 - h0, a1 - h1);
        float c0 = xw1[(k2 * 2) * 64 + n];
        float c1 = xw1[(k2 * 2 + 1) * 64 + n];
        float g0 = bfhi(c0), g1 = bfhi(c1);
        sB1h[n * LW + k2] = pbf2(g0, g1);
        sB1l[n * LW + k2] = pbf2(c0 - g0, c1 - g1);
    }
    __syncthreads();   // the ONLY block barrier: weights + biases visible

    // warp-local t1 staging: own 16 rows x 16 float4-groups, 8 iters/lane
#pragma unroll
    for (int it = 0; it < 8; it++) {
        int i = it * 32 + lane;
        int row = rbase + (i >> 4);
        int j = (i & 15) * 4;
        int d = sdst[row];
        int dd = d < 0 ? 0 : d;
        int s  = ssrc[row];
        float4 ad = *(const float4*)&g_Ad[dd * 64 + j];
        float4 as = *(const float4*)&g_As[s * 64 + j];
        float r = srwe[row];
        float t0 = silu_f(ad.x + as.x + r * sw1r[j + 0] + sb1v[j + 0]);
        float t1 = silu_f(ad.y + as.y + r * sw1r[j + 1] + sb1v[j + 1]);
        float t2 = silu_f(ad.z + as.z + r * sw1r[j + 2] + sb1v[j + 2]);
        float t3 = silu_f(ad.w + as.w + r * sw1r[j + 3] + sb1v[j + 3]);
        float h0 = bfhi(t0), h1 = bfhi(t1), h2 = bfhi(t2), h3 = bfhi(t3);
        int o = row * LW + (j >> 1);
        sAh[o]     = pbf2(h0, h1);
        sAh[o + 1] = pbf2(h2, h3);
        sAl[o]     = pbf2(t0 - h0, t1 - h1);
        sAl[o + 1] = pbf2(t2 - h2, t3 - h3);
    }
    __syncwarp();      // own rows staged

    float acc[8][4];
#pragma unroll
    for (int nt = 0; nt < 8; nt++)
#pragma unroll
        for (int q = 0; q < 4; q++) acc[nt][q] = 0.f;

    gemm_bf3(aH, aL, b0H, b0L, lane, rbase, acc);   // GEMM1: t1 @ w2

    // epilogue 1: m = silu(D + b2) -> rewrite own A rows (hi/lo)
    {
        int ra = rbase + gr, rb = ra + 8;
#pragma unroll
        for (int nt = 0; nt < 8; nt++) {
            int col = nt * 8 + gc * 2;
            float m00 = silu_f(acc[nt][0] + sb2v[col]);
            float m01 = silu_f(acc[nt][1] + sb2v[col + 1]);
            float m10 = silu_f(acc[nt][2] + sb2v[col]);
            float m11 = silu_f(acc[nt][3] + sb2v[col + 1]);
            float h00 = bfhi(m00), h01 = bfhi(m01);
            float h10 = bfhi(m10), h11 = bfhi(m11);
            int oa = ra * LW + nt * 4 + gc, ob = rb * LW + nt * 4 + gc;
            sAh[oa] = pbf2(h00, h01);
            sAl[oa] = pbf2(m00 - h00, m01 - h01);
            sAh[ob] = pbf2(h10, h11);
            sAl[ob] = pbf2(m10 - h10, m11 - h11);
        }
    }
    __syncwarp();

    // coalesced m-scatter (m = hi + lo, exact): own 16 rows x 16 v4-groups
    for (int i = lane; i < 16 * 16; i += 32) {
        int row = rbase + (i >> 4);
        int j2 = (i & 15) * 2;             // u32 offset within row
        int d = sdst[row];
        if (d >= 0) {
            uint32_t h0 = sAh[row * LW + j2], h1 = sAh[row * LW + j2 + 1];
            uint32_t l0 = sAl[row * LW + j2], l1 = sAl[row * LW + j2 + 1];
            float2 fh0 = ubf2(h0), fh1 = ubf2(h1);
            float2 fl0 = ubf2(l0), fl1 = ubf2(l1);
            red_add_v4(&g_m[d * 64 + j2 * 2],
                       fh0.x + fl0.x, fh0.y + fl0.y,
                       fh1.x + fl1.x, fh1.y + fl1.y);
        }
    }
    __syncwarp();

#pragma unroll
    for (int nt = 0; nt < 8; nt++)
#pragma unroll
        for (int q = 0; q < 4; q++) acc[nt][q] = 0.f;

    gemm_bf3(aH, aL, b1H, b1L, lane, rbase, acc);   // GEMM2: m @ xw1

    // epilogue 2: W = silu(D + xb1) . xw2 + xb2  (warp-local rows)
    {
        float Wv0 = 0.f, Wv1 = 0.f;
#pragma unroll
        for (int nt = 0; nt < 8; nt++) {
            int col = nt * 8 + gc * 2;
            Wv0 += silu_f(acc[nt][0] + sxb1[col]) * sxw2[col]
                 + silu_f(acc[nt][1] + sxb1[col + 1]) * sxw2[col + 1];
            Wv1 += silu_f(acc[nt][2] + sxb1[col]) * sxw2[col]
                 + silu_f(acc[nt][3] + sxb1[col + 1]) * sxw2[col + 1];
        }
#pragma unroll
        for (int off = 1; off <= 2; off <<= 1) {
            Wv0 += __shfl_xor_sync(0xffffffffu, Wv0, off);
            Wv1 += __shfl_xor_sync(0xffffffffu, Wv1, off);
        }
        if (gc == 0) {
            float xb2v = __ldg(xb2);
            srwe[rbase + gr]     = Wv0 + xb2v;
            srwe[rbase + gr + 8] = Wv1 + xb2v;
        }
    }
    __syncwarp();      // W for own rows visible within warp

    // dx scatter: lanes 0..15 handle own rows (all data warp-local)
    if (lane < 16) {
        int row = rbase + lane;
        int d = sdst[row];
        if (d >= 0) {
            float W = srwe[row];
            atomicAdd(&g_dx[d * 3 + 0], W * sxd[row * 3 + 0]);
            atomicAdd(&g_dx[d * 3 + 1], W * sxd[row * 3 + 1]);
            atomicAdd(&g_dx[d * 3 + 2], W * sxd[row * 3 + 2]);
        }
    }
}

#define EDGE_DYN_BYTES ((2 * ET * LW + 4 * 64 * LW) * 4)

// ---------------------------------------------------------------------------
// Fused node_update + node_pre(next layer). Zeroes m/dx after reading.
__global__ __launch_bounds__(NT)
void update_pre_kernel(const float* __restrict__ hw1, const float* __restrict__ hb1,
                       const float* __restrict__ hw2, const float* __restrict__ hb2,
                       const float* __restrict__ ew1n, int N) {
    __shared__ float sA[TS * LDA];
    __shared__ float sW[4096];
    int tid = threadIdx.x;
    int n0 = blockIdx.x * TS;
    int tx = tid & 15, ty = tid >> 4;

    for (int p = tid; p < TS * 16; p += NT) {
        int i = p >> 4, j = (p & 15) * 4;
        int n = n0 + i;
        float4 v = make_float4(0.f, 0.f, 0.f, 0.f);
        if (n < N) v = *(const float4*)&g_h[n * 64 + j];
        *(float4*)&sA[i * LDA + j] = v;
    }
    for (int p = tid; p < 1024; p += NT)
        *(float4*)&sW[p * 4] = *(const float4*)&hw1[p * 4];
    __syncthreads();

    u64 acc[4][2];
    ZERO_ACC(acc);
    gemm_t(sA, sW, tx, ty, acc);
    __syncthreads();

    for (int p = tid; p < TS * 16; p += NT) {
        int i = p >> 4, j = (p & 15) * 4;
        int n = n0 + i;
        float4 v = make_float4(0.f, 0.f, 0.f, 0.f);
        if (n < N) {
            v = *(const float4*)&g_m[n * 64 + j];
            *(float4*)&g_m[n * 64 + j] = make_float4(0.f, 0.f, 0.f, 0.f);
        }
        *(float4*)&sA[i * LDA + j] = v;
    }
    for (int p = tid; p < 1024; p += NT)
        *(float4*)&sW[p * 4] = *(const float4*)&hw1[4096 + p * 4];
    __syncthreads();
    gemm_t(sA, sW, tx, ty, acc);
    __syncthreads();

#pragma unroll
    for (int i = 0; i < 4; i++) {
        int e = ty * 4 + i;
        float c[4]; UNPACK_ROW(acc[i], c);
#pragma unroll
        for (int q = 0; q < 4; q++) c[q] = silu_f(c[q] + hb1[tx * 4 + q]);
        *(float4*)&sA[e * LDA + tx * 4] = make_float4(c[0], c[1], c[2], c[3]);
    }
    for (int p = tid; p < 1024; p += NT)
        *(float4*)&sW[p * 4] = *(const float4*)&hw2[p * 4];
    __syncthreads();

    ZERO_ACC(acc);
    gemm_t(sA, sW, tx, ty, acc);
    __syncthreads();

#pragma unroll
    for (int i = 0; i < 4; i++) {
        int n = n0 + ty * 4 + i;
        if (n < N) {
            float c[4]; UNPACK_ROW(acc[i], c);
            float4 o = *(const float4*)&g_h[n * 64 + tx * 4];
            o.x += c[0] + hb2[tx * 4 + 0];
            o.y += c[1] + hb2[tx * 4 + 1];
            o.z += c[2] + hb2[tx * 4 + 2];
            o.w += c[3] + hb2[tx * 4 + 3];
            *(float4*)&g_h[n * 64 + tx * 4] = o;
            *(float4*)&sA[(ty * 4 + i) * LDA + tx * 4] = o;
        } else {
            *(float4*)&sA[(ty * 4 + i) * LDA + tx * 4] = make_float4(0.f, 0.f, 0.f, 0.f);
        }
    }
    if (tid < TS * 3) {
        int idx = n0 * 3 + tid;
        if (idx < N * 3) {
            g_x[idx] = g_x[idx] + g_dx[idx];
            g_dx[idx] = 0.f;
        }
    }
    for (int p = tid; p < 1024; p += NT)
        *(float4*)&sW[p * 4] = *(const float4*)&ew1n[p * 4];
    __syncthreads();

    ZERO_ACC(acc);
    gemm_t(sA, sW, tx, ty, acc);
#pragma unroll
    for (int i = 0; i < 4; i++) {
        int n = n0 + ty * 4 + i;
        if (n < N) {
            float c[4]; UNPACK_ROW(acc[i], c);
            *(float4*)&g_Ad[n * 64 + tx * 4] = make_float4(c[0], c[1], c[2], c[3]);
        }
    }
    __syncthreads();
    for (int p = tid; p < 1024; p += NT)
        *(float4*)&sW[p * 4] = *(const float4*)&ew1n[4096 + p * 4];
    __syncthreads();
    ZERO_ACC(acc);
    gemm_t(sA, sW, tx, ty, acc);
#pragma unroll
    for (int i = 0; i < 4; i++) {
        int n = n0 + ty * 4 + i;
        if (n < N) {
            float c[4]; UNPACK_ROW(acc[i], c);
            *(float4*)&g_As[n * 64 + tx * 4] = make_float4(c[0], c[1], c[2], c[3]);
        }
    }
}

// ---------------------------------------------------------------------------
__global__ __launch_bounds__(NT)
void final_update_kernel(const float* __restrict__ hw1, const float* __restrict__ hb1,
                         const float* __restrict__ hw2, const float* __restrict__ hb2,
                         float* __restrict__ outh, float* __restrict__ outx, int N) {
    __shared__ float sA[TS * LDA];
    __shared__ float sW[4096];
    int tid = threadIdx.x;
    int n0 = blockIdx.x * TS;
    int tx = tid & 15, ty = tid >> 4;

    for (int p = tid; p < TS * 16; p += NT) {
        int i = p >> 4, j = (p & 15) * 4;
        int n = n0 + i;
        float4 v = make_float4(0.f, 0.f, 0.f, 0.f);
        if (n < N) v = *(const float4*)&g_h[n * 64 + j];
        *(float4*)&sA[i * LDA + j] = v;
    }
    for (int p = tid; p < 1024; p += NT)
        *(float4*)&sW[p * 4] = *(const float4*)&hw1[p * 4];
    __syncthreads();

    u64 acc[4][2];
    ZERO_ACC(acc);
    gemm_t(sA, sW, tx, ty, acc);
    __syncthreads();

    for (int p = tid; p < TS * 16; p += NT) {
        int i = p >> 4, j = (p & 15) * 4;
        int n = n0 + i;
        float4 v = make_float4(0.f, 0.f, 0.f, 0.f);
        if (n < N) v = *(const float4*)&g_m[n * 64 + j];
        *(float4*)&sA[i * LDA + j] = v;
    }
    for (int p = tid; p < 1024; p += NT)
        *(float4*)&sW[p * 4] = *(const float4*)&hw1[4096 + p * 4];
    __syncthreads();
    gemm_t(sA, sW, tx, ty, acc);
    __syncthreads();

#pragma unroll
    for (int i = 0; i < 4; i++) {
        int e = ty * 4 + i;
        float c[4]; UNPACK_ROW(acc[i], c);
#pragma unroll
        for (int q = 0; q < 4; q++) c[q] = silu_f(c[q] + hb1[tx * 4 + q]);
        *(float4*)&sA[e * LDA + tx * 4] = make_float4(c[0], c[1], c[2], c[3]);
    }
    for (int p = tid; p < 1024; p += NT)
        *(float4*)&sW[p * 4] = *(const float4*)&hw2[p * 4];
    __syncthreads();

    ZERO_ACC(acc);
    gemm_t(sA, sW, tx, ty, acc);

#pragma unroll
    for (int i = 0; i < 4; i++) {
        int n = n0 + ty * 4 + i;
        if (n < N) {
            float c[4]; UNPACK_ROW(acc[i], c);
            float4 o = *(const float4*)&g_h[n * 64 + tx * 4];
            o.x += c[0] + hb2[tx * 4 + 0];
            o.y += c[1] + hb2[tx * 4 + 1];
            o.z += c[2] + hb2[tx * 4 + 2];
            o.w += c[3] + hb2[tx * 4 + 3];
            *(float4*)&outh[n * 64 + tx * 4] = o;
        }
    }
    if (tid < TS * 3) {
        int idx = n0 * 3 + tid;
        if (idx < N * 3) outx[idx] = g_x[idx] + g_dx[idx];
    }
}

// ---------------------------------------------------------------------------
extern "C" void kernel_launch(void* const* d_in, const int* in_sizes, int n_in,
                              void* d_out, int out_size) {
    const int*   an   = (const int*)d_in[0];
    const float* pos  = (const float*)d_in[1];
    const int*   eidx = (const int*)d_in[2];
    // d_in[3] = edge_attr (unused by reference)
    const float* emb  = (const float*)d_in[4];
    const float* e_w1 = (const float*)d_in[5];
    const float* e_b1 = (const float*)d_in[6];
    const float* e_w2 = (const float*)d_in[7];
    const float* e_b2 = (const float*)d_in[8];
    const float* h_w1 = (const float*)d_in[9];
    const float* h_b1 = (const float*)d_in[10];
    const float* h_w2 = (const float*)d_in[11];
    const float* h_b2 = (const float*)d_in[12];
    const float* x_w1 = (const float*)d_in[13];
    const float* x_b1 = (const float*)d_in[14];
    const float* x_w2 = (const float*)d_in[15];
    const float* x_b2 = (const float*)d_in[16];

    int N = in_sizes[0];
    int E = in_sizes[2] / 2;
    float* out = (float*)d_out;

    cudaFuncSetAttribute(edge_kernel_bf3,
                         cudaFuncAttributeMaxDynamicSharedMemorySize,
                         EDGE_DYN_BYTES);

    int nodeBlocks = (N + TS - 1) / TS;
    int edgeBlocks = (E + ET - 1) / ET;

    init_pre_kernel<<<nodeBlocks, NT>>>(an, emb, pos, e_w1, N);

    edge_kernel_bf3<<<edgeBlocks, ENT, EDGE_DYN_BYTES>>>(
        eidx, eidx + E,
        e_w1 + 128 * 64, e_b1,
        e_w2, e_b2,
        x_w1, x_b1,
        x_w2, x_b2, E);

    update_pre_kernel<<<nodeBlocks, NT>>>(
        h_w1, h_b1, h_w2, h_b2,
        e_w1 + 129 * 64, N);

    edge_kernel_bf3<<<edgeBlocks, ENT, EDGE_DYN_BYTES>>>(
        eidx, eidx + E,
        e_w1 + 129 * 64 + 128 * 64, e_b1 + 64,
        e_w2 + 4096, e_b2 + 64,
        x_w1 + 4096, x_b1 + 64,
        x_w2 + 64, x_b2 + 1, E);

    final_update_kernel<<<nodeBlocks, NT>>>(
        h_w1 + 128 * 64, h_b1 + 64,
        h_w2 + 4096, h_b2 + 64,
        out, out + (size_t)N * 64, N);
}

// round 13
// speedup vs baseline: 2.1889x; 1.0386x over previous
#include <cuda_runtime.h>
#include <cuda_bf16.h>
#include <cstdint>

#define NT 256          // node kernels: threads per block
#define TS 64           // node tile rows
#define LDA 68          // sA row stride (floats) for SIMT gemm
#define ET 224          // edge tile (edges per block)
#define ENT 448         // edge kernel threads (14 warps x 16 rows)
#define LW 36           // edge smem row stride in u32 (72 bf16)

typedef unsigned long long u64;

__device__ float g_h [50048 * 64];
__device__ float g_x [50048 * 3];
__device__ float g_Ad[50048 * 64];   // h @ e_w1[0:64]   (dst part)
__device__ float g_As[50048 * 64];   // h @ e_w1[64:128] (src part)
__device__ float g_m [50048 * 64];   // segment-sum of m_ij
__device__ float g_dx[50048 * 3];    // segment-sum of W_ij * x_diff

__device__ __forceinline__ float silu_f(float v) {
    return v / (1.0f + __expf(-v));
}
__device__ __forceinline__ u64 pdup(float x) {
    u64 r; asm("mov.b64 %0, {%1, %1};" : "=l"(r) : "f"(x)); return r;
}
__device__ __forceinline__ void up2(u64 v, float& a, float& b) {
    asm("mov.b64 {%0, %1}, %2;" : "=f"(a), "=f"(b) : "l"(v));
}
__device__ __forceinline__ void fma2(u64& c, u64 a, u64 b) {
    asm("fma.rn.f32x2 %0, %1, %2, %0;" : "+l"(c) : "l"(a), "l"(b));
}
__device__ __forceinline__ void red_add_v4(float* p, float a, float b, float c, float d) {
    asm volatile("red.global.add.v4.f32 [%0], {%1, %2, %3, %4};"
                 :: "l"(p), "f"(a), "f"(b), "f"(c), "f"(d) : "memory");
}
__device__ __forceinline__ uint32_t pbf2(float lo, float hi) {
    __nv_bfloat162 t;
    t.x = __float2bfloat16_rn(lo);
    t.y = __float2bfloat16_rn(hi);
    return *reinterpret_cast<uint32_t*>(&t);
}
__device__ __forceinline__ float bfhi(float x) {
    return __bfloat162float(__float2bfloat16_rn(x));
}
__device__ __forceinline__ float2 ubf2(uint32_t u) {
    __nv_bfloat162 t = *reinterpret_cast<__nv_bfloat162*>(&u);
    return make_float2(__bfloat162float(t.x), __bfloat162float(t.y));
}
__device__ __forceinline__ uint32_t smem_u32p(const void* p) {
    uint32_t a;
    asm("{ .reg .u64 t; cvta.to.shared.u64 t, %1; cvt.u32.u64 %0, t; }"
        : "=r"(a) : "l"(p));
    return a;
}
// D(16x8,f32) += A(16x16,bf16,row) * B(16x8,bf16,col)
__device__ __forceinline__ void mma_bf16(float c[4], const uint32_t a[4],
                                         uint32_t b0, uint32_t b1) {
    asm volatile(
        "mma.sync.aligned.m16n8k16.row.col.f32.bf16.bf16.f32 "
        "{%0,%1,%2,%3}, {%4,%5,%6,%7}, {%8,%9}, {%0,%1,%2,%3};"
        : "+f"(c[0]), "+f"(c[1]), "+f"(c[2]), "+f"(c[3])
        : "r"(a[0]), "r"(a[1]), "r"(a[2]), "r"(a[3]), "r"(b0), "r"(b1));
}
__device__ __forceinline__ void ldsm_x4(uint32_t r[4], uint32_t addr) {
    asm volatile("ldmatrix.sync.aligned.m8n8.x4.shared.b16 {%0,%1,%2,%3}, [%4];"
                 : "=r"(r[0]), "=r"(r[1]), "=r"(r[2]), "=r"(r[3]) : "r"(addr));
}

// 3-term bf16 split GEMM via ldmatrix. Warp owns 16 rows rbase..rbase+15.
__device__ __forceinline__ void gemm_bf3(uint32_t aH, uint32_t aL,
                                         uint32_t bH, uint32_t bL,
                                         int lane, int rbase,
                                         float acc[8][4]) {
    int l7 = lane & 7;
    int aRow = l7 + ((lane >> 3) & 1) * 8;      // row within 16-row tile
    int aColU = ((lane >> 4) & 1) * 4;          // k-half in u32
    int bRow = ((lane >> 4) << 3) + l7;         // n within 16-n pair
    int bColU = ((lane >> 3) & 1) * 4;
#pragma unroll
    for (int c = 0; c < 4; c++) {
        int kc = c * 8;                         // u32 k base
        uint32_t ah[4], al[4];
        uint32_t off = (uint32_t)((rbase + aRow) * LW + kc + aColU) * 4u;
        ldsm_x4(ah, aH + off);
        ldsm_x4(al, aL + off);
#pragma unroll
        for (int ntp = 0; ntp < 4; ntp++) {
            uint32_t boff = (uint32_t)((ntp * 16 + bRow) * LW + kc + bColU) * 4u;
            uint32_t bh[4], bl[4];
            ldsm_x4(bh, bH + boff);
            ldsm_x4(bl, bL + boff);
            int n0 = 2 * ntp, n1 = 2 * ntp + 1;
            mma_bf16(acc[n0], ah, bh[0], bh[1]);
            mma_bf16(acc[n0], ah, bl[0], bl[1]);
            mma_bf16(acc[n0], al, bh[0], bh[1]);
            mma_bf16(acc[n1], ah, bh[2], bh[3]);
            mma_bf16(acc[n1], ah, bl[2], bl[3]);
            mma_bf16(acc[n1], al, bh[2], bh[3]);
        }
    }
}

// ===================== SIMT gemm (node kernels, R4-proven) ==================
__device__ __forceinline__ void gemm_t(const float* __restrict__ sA,
                                       const float* __restrict__ sW,
                                       int tx, int ty, u64 acc[4][2]) {
    const float* aR = sA + ty * 4 * LDA;
    const float* bC = sW + tx * 4;
#pragma unroll
    for (int kb = 0; kb < 64; kb += 4) {
        float4 av[4];
#pragma unroll
        for (int i = 0; i < 4; i++)
            av[i] = *(const float4*)(aR + i * LDA + kb);
#pragma unroll
        for (int kk = 0; kk < 4; kk++) {
            ulonglong2 b = *(const ulonglong2*)(bC + (kb + kk) * 64);
#pragma unroll
            for (int i = 0; i < 4; i++) {
                float a = (kk == 0) ? av[i].x : (kk == 1) ? av[i].y
                        : (kk == 2) ? av[i].z : av[i].w;
                u64 aa = pdup(a);
                fma2(acc[i][0], aa, b.x);
                fma2(acc[i][1], aa, b.y);
            }
        }
    }
}

#define ZERO_ACC(acc)                             \
    _Pragma("unroll") for (int i_ = 0; i_ < 4; i_++) { (acc)[i_][0] = 0ull; (acc)[i_][1] = 0ull; }
#define UNPACK_ROW(acc_row, c)  \
    up2((acc_row)[0], (c)[0], (c)[1]); up2((acc_row)[1], (c)[2], (c)[3]);

// ---------------------------------------------------------------------------
// Fused init + node_pre (layer 0)
__global__ __launch_bounds__(NT)
void init_pre_kernel(const int* __restrict__ an, const float* __restrict__ emb,
                     const float* __restrict__ pos, const float* __restrict__ w1,
                     int N) {
    __shared__ float sA[TS * LDA];
    __shared__ float sW[4096];
    int tid = threadIdx.x;
    int n0 = blockIdx.x * TS;
    int tx = tid & 15, ty = tid >> 4;

    for (int p = tid; p < TS * 16; p += NT) {
        int i = p >> 4, j = (p & 15) * 4;
        int n = n0 + i;
        float4 v = make_float4(0.f, 0.f, 0.f, 0.f);
        if (n < N) {
            v = *(const float4*)&emb[an[n] * 64 + j];
            *(float4*)&g_h[n * 64 + j] = v;
            *(float4*)&g_m[n * 64 + j] = make_float4(0.f, 0.f, 0.f, 0.f);
        }
        *(float4*)&sA[i * LDA + j] = v;
    }
    if (tid < TS * 3) {
        int idx = n0 * 3 + tid;
        if (idx < N * 3) { g_x[idx] = pos[idx]; g_dx[idx] = 0.f; }
    }
    for (int p = tid; p < 1024; p += NT)
        *(float4*)&sW[p * 4] = *(const float4*)&w1[p * 4];
    __syncthreads();

    u64 acc[4][2];
    ZERO_ACC(acc);
    gemm_t(sA, sW, tx, ty, acc);
#pragma unroll
    for (int i = 0; i < 4; i++) {
        int n = n0 + ty * 4 + i;
        if (n < N) {
            float c[4]; UNPACK_ROW(acc[i], c);
            *(float4*)&g_Ad[n * 64 + tx * 4] = make_float4(c[0], c[1], c[2], c[3]);
        }
    }
    __syncthreads();
    for (int p = tid; p < 1024; p += NT)
        *(float4*)&sW[p * 4] = *(const float4*)&w1[4096 + p * 4];
    __syncthreads();
    ZERO_ACC(acc);
    gemm_t(sA, sW, tx, ty, acc);
#pragma unroll
    for (int i = 0; i < 4; i++) {
        int n = n0 + ty * 4 + i;
        if (n < N) {
            float c[4]; UNPACK_ROW(acc[i], c);
            *(float4*)&g_As[n * 64 + tx * 4] = make_float4(c[0], c[1], c[2], c[3]);
        }
    }
}

// ---------------------------------------------------------------------------
// 3xBF16 edge kernel: ET=224 edges/block, 448 threads (14 warps x 16 rows).
// Warp-synchronous: ONE block barrier (weights), everything else warp-local.
__global__ __launch_bounds__(ENT, 2)
void edge_kernel_bf3(const int* __restrict__ src, const int* __restrict__ dst,
                     const float* __restrict__ w1r, const float* __restrict__ b1,
                     const float* __restrict__ w2,  const float* __restrict__ b2,
                     const float* __restrict__ xw1, const float* __restrict__ xb1,
                     const float* __restrict__ xw2, const float* __restrict__ xb2,
                     int E) {
    extern __shared__ uint32_t dynu[];
    uint32_t* sAh  = dynu;                   // [ET][LW]
    uint32_t* sAl  = sAh + ET * LW;
    uint32_t* sB0h = sAl + ET * LW;          // w2  [64][LW]
    uint32_t* sB0l = sB0h + 64 * LW;
    uint32_t* sB1h = sB0l + 64 * LW;         // xw1 [64][LW]
    uint32_t* sB1l = sB1h + 64 * LW;
    __shared__ int   sdst[ET], ssrc[ET];
    __shared__ float sxd[ET * 3];
    __shared__ float srwe[ET];               // r (pre) aliased with W (post), warp-local
    __shared__ float sw1r[64], sb1v[64], sb2v[64], sxb1[64], sxw2[64];

    int tid = threadIdx.x;
    int lane = tid & 31, warp = tid >> 5;
    int gr = lane >> 2, gc = lane & 3;
    int e0 = blockIdx.x * ET;
    int rbase = warp * 16;

    uint32_t aH = smem_u32p(sAh), aL = smem_u32p(sAl);
    uint32_t b0H = smem_u32p(sB0h), b0L = smem_u32p(sB0l);
    uint32_t b1H = smem_u32p(sB1h), b1L = smem_u32p(sB1l);

    // warp-local metadata: lanes 0..15 own rows rbase+lane
    if (lane < 16) {
        int row = rbase + lane;
        int eg = e0 + row;
        int s = 0, d = -1;
        float d0 = 0.f, d1 = 0.f, d2 = 0.f;
        if (eg < E) {
            s = src[eg]; d = dst[eg];
            d0 = g_x[s * 3 + 0] - g_x[d * 3 + 0];
            d1 = g_x[s * 3 + 1] - g_x[d * 3 + 1];
            d2 = g_x[s * 3 + 2] - g_x[d * 3 + 2];
        }
        ssrc[row] = s; sdst[row] = d;
        sxd[row * 3 + 0] = d0; sxd[row * 3 + 1] = d1; sxd[row * 3 + 2] = d2;
        srwe[row] = sqrtf(d0 * d0 + d1 * d1 + d2 * d2);
    }
    if (tid >= 256 && tid < 320) {
        int j = tid - 256;
        sw1r[j] = w1r[j]; sb1v[j] = b1[j]; sb2v[j] = b2[j];
        sxb1[j] = xb1[j]; sxw2[j] = xw2[j];
    }
    // stage BOTH weights (n-major, hi/lo bf16), block-strided
    for (int p = tid; p < 2048; p += ENT) {
        int k2 = p >> 6, n = p & 63;
        float a0 = w2[(k2 * 2) * 64 + n];
        float a1 = w2[(k2 * 2 + 1) * 64 + n];
        float h0 = bfhi(a0), h1 = bfhi(a1);
        sB0h[n * LW + k2] = pbf2(h0, h1);
        sB0l[n * LW + k2] = pbf2(a0 - h0, a1 - h1);
        float c0 = xw1[(k2 * 2) * 64 + n];
        float c1 = xw1[(k2 * 2 + 1) * 64 + n];
        float g0 = bfhi(c0), g1 = bfhi(c1);
        sB1h[n * LW + k2] = pbf2(g0, g1);
        sB1l[n * LW + k2] = pbf2(c0 - g0, c1 - g1);
    }
    __syncthreads();   // the ONLY block barrier: weights + biases visible

    // warp-local t1 staging: own 16 rows x 16 float4-groups, 8 iters/lane
#pragma unroll
    for (int it = 0; it < 8; it++) {
        int i = it * 32 + lane;
        int row = rbase + (i >> 4);
        int j = (i & 15) * 4;
        int d = sdst[row];
        int dd = d < 0 ? 0 : d;
        int s  = ssrc[row];
        float4 ad = *(const float4*)&g_Ad[dd * 64 + j];
        float4 as = *(const float4*)&g_As[s * 64 + j];
        float r = srwe[row];
        float t0 = silu_f(ad.x + as.x + r * sw1r[j + 0] + sb1v[j + 0]);
        float t1 = silu_f(ad.y + as.y + r * sw1r[j + 1] + sb1v[j + 1]);
        float t2 = silu_f(ad.z + as.z + r * sw1r[j + 2] + sb1v[j + 2]);
        float t3 = silu_f(ad.w + as.w + r * sw1r[j + 3] + sb1v[j + 3]);
        float h0 = bfhi(t0), h1 = bfhi(t1), h2 = bfhi(t2), h3 = bfhi(t3);
        int o = row * LW + (j >> 1);
        sAh[o]     = pbf2(h0, h1);
        sAh[o + 1] = pbf2(h2, h3);
        sAl[o]     = pbf2(t0 - h0, t1 - h1);
        sAl[o + 1] = pbf2(t2 - h2, t3 - h3);
    }
    __syncwarp();      // own rows staged

    float acc[8][4];
#pragma unroll
    for (int nt = 0; nt < 8; nt++)
#pragma unroll
        for (int q = 0; q < 4; q++) acc[nt][q] = 0.f;

    gemm_bf3(aH, aL, b0H, b0L, lane, rbase, acc);   // GEMM1: t1 @ w2

    // epilogue 1: m = silu(D + b2) -> rewrite own A rows (hi/lo)
    {
        int ra = rbase + gr, rb = ra + 8;
#pragma unroll
        for (int nt = 0; nt < 8; nt++) {
            int col = nt * 8 + gc * 2;
            float m00 = silu_f(acc[nt][0] + sb2v[col]);
            float m01 = silu_f(acc[nt][1] + sb2v[col + 1]);
            float m10 = silu_f(acc[nt][2] + sb2v[col]);
            float m11 = silu_f(acc[nt][3] + sb2v[col + 1]);
            float h00 = bfhi(m00), h01 = bfhi(m01);
            float h10 = bfhi(m10), h11 = bfhi(m11);
            int oa = ra * LW + nt * 4 + gc, ob = rb * LW + nt * 4 + gc;
            sAh[oa] = pbf2(h00, h01);
            sAl[oa] = pbf2(m00 - h00, m01 - h01);
            sAh[ob] = pbf2(h10, h11);
            sAl[ob] = pbf2(m10 - h10, m11 - h11);
        }
    }
    __syncwarp();

    // coalesced m-scatter (m = hi + lo, exact): own 16 rows x 16 v4-groups
    for (int i = lane; i < 16 * 16; i += 32) {
        int row = rbase + (i >> 4);
        int j2 = (i & 15) * 2;             // u32 offset within row
        int d = sdst[row];
        if (d >= 0) {
            uint32_t h0 = sAh[row * LW + j2], h1 = sAh[row * LW + j2 + 1];
            uint32_t l0 = sAl[row * LW + j2], l1 = sAl[row * LW + j2 + 1];
            float2 fh0 = ubf2(h0), fh1 = ubf2(h1);
            float2 fl0 = ubf2(l0), fl1 = ubf2(l1);
            red_add_v4(&g_m[d * 64 + j2 * 2],
                       fh0.x + fl0.x, fh0.y + fl0.y,
                       fh1.x + fl1.x, fh1.y + fl1.y);
        }
    }
    __syncwarp();

#pragma unroll
    for (int nt = 0; nt < 8; nt++)
#pragma unroll
        for (int q = 0; q < 4; q++) acc[nt][q] = 0.f;

    gemm_bf3(aH, aL, b1H, b1L, lane, rbase, acc);   // GEMM2: m @ xw1

    // epilogue 2: W = silu(D + xb1) . xw2 + xb2  (warp-local rows)
    {
        float Wv0 = 0.f, Wv1 = 0.f;
#pragma unroll
        for (int nt = 0; nt < 8; nt++) {
            int col = nt * 8 + gc * 2;
            Wv0 += silu_f(acc[nt][0] + sxb1[col]) * sxw2[col]
                 + silu_f(acc[nt][1] + sxb1[col + 1]) * sxw2[col + 1];
            Wv1 += silu_f(acc[nt][2] + sxb1[col]) * sxw2[col]
                 + silu_f(acc[nt][3] + sxb1[col + 1]) * sxw2[col + 1];
        }
#pragma unroll
        for (int off = 1; off <= 2; off <<= 1) {
            Wv0 += __shfl_xor_sync(0xffffffffu, Wv0, off);
            Wv1 += __shfl_xor_sync(0xffffffffu, Wv1, off);
        }
        if (gc == 0) {
            float xb2v = __ldg(xb2);
            srwe[rbase + gr]     = Wv0 + xb2v;
            srwe[rbase + gr + 8] = Wv1 + xb2v;
        }
    }
    __syncwarp();      // W for own rows visible within warp

    // dx scatter: lanes 0..15 handle own rows (all data warp-local)
    if (lane < 16) {
        int row = rbase + lane;
        int d = sdst[row];
        if (d >= 0) {
            float W = srwe[row];
            atomicAdd(&g_dx[d * 3 + 0], W * sxd[row * 3 + 0]);
            atomicAdd(&g_dx[d * 3 + 1], W * sxd[row * 3 + 1]);
            atomicAdd(&g_dx[d * 3 + 2], W * sxd[row * 3 + 2]);
        }
    }
}

#define EDGE_DYN_BYTES ((2 * ET * LW + 4 * 64 * LW) * 4)

// ---------------------------------------------------------------------------
// Fused node_update + node_pre(next layer). Zeroes m/dx after reading.
__global__ __launch_bounds__(NT)
void update_pre_kernel(const float* __restrict__ hw1, const float* __restrict__ hb1,
                       const float* __restrict__ hw2, const float* __restrict__ hb2,
                       const float* __restrict__ ew1n, int N) {
    __shared__ float sA[TS * LDA];
    __shared__ float sW[4096];
    int tid = threadIdx.x;
    int n0 = blockIdx.x * TS;
    int tx = tid & 15, ty = tid >> 4;

    for (int p = tid; p < TS * 16; p += NT) {
        int i = p >> 4, j = (p & 15) * 4;
        int n = n0 + i;
        float4 v = make_float4(0.f, 0.f, 0.f, 0.f);
        if (n < N) v = *(const float4*)&g_h[n * 64 + j];
        *(float4*)&sA[i * LDA + j] = v;
    }
    for (int p = tid; p < 1024; p += NT)
        *(float4*)&sW[p * 4] = *(const float4*)&hw1[p * 4];
    __syncthreads();

    u64 acc[4][2];
    ZERO_ACC(acc);
    gemm_t(sA, sW, tx, ty, acc);
    __syncthreads();

    for (int p = tid; p < TS * 16; p += NT) {
        int i = p >> 4, j = (p & 15) * 4;
        int n = n0 + i;
        float4 v = make_float4(0.f, 0.f, 0.f, 0.f);
        if (n < N) {
            v = *(const float4*)&g_m[n * 64 + j];
            *(float4*)&g_m[n * 64 + j] = make_float4(0.f, 0.f, 0.f, 0.f);
        }
        *(float4*)&sA[i * LDA + j] = v;
    }
    for (int p = tid; p < 1024; p += NT)
        *(float4*)&sW[p * 4] = *(const float4*)&hw1[4096 + p * 4];
    __syncthreads();
    gemm_t(sA, sW, tx, ty, acc);
    __syncthreads();

#pragma unroll
    for (int i = 0; i < 4; i++) {
        int e = ty * 4 + i;
        float c[4]; UNPACK_ROW(acc[i], c);
#pragma unroll
        for (int q = 0; q < 4; q++) c[q] = silu_f(c[q] + hb1[tx * 4 + q]);
        *(float4*)&sA[e * LDA + tx * 4] = make_float4(c[0], c[1], c[2], c[3]);
    }
    for (int p = tid; p < 1024; p += NT)
        *(float4*)&sW[p * 4] = *(const float4*)&hw2[p * 4];
    __syncthreads();

    ZERO_ACC(acc);
    gemm_t(sA, sW, tx, ty, acc);
    __syncthreads();

#pragma unroll
    for (int i = 0; i < 4; i++) {
        int n = n0 + ty * 4 + i;
        if (n < N) {
            float c[4]; UNPACK_ROW(acc[i], c);
            float4 o = *(const float4*)&g_h[n * 64 + tx * 4];
            o.x += c[0] + hb2[tx * 4 + 0];
            o.y += c[1] + hb2[tx * 4 + 1];
            o.z += c[2] + hb2[tx * 4 + 2];
            o.w += c[3] + hb2[tx * 4 + 3];
            *(float4*)&g_h[n * 64 + tx * 4] = o;
            *(float4*)&sA[(ty * 4 + i) * LDA + tx * 4] = o;
        } else {
            *(float4*)&sA[(ty * 4 + i) * LDA + tx * 4] = make_float4(0.f, 0.f, 0.f, 0.f);
        }
    }
    if (tid < TS * 3) {
        int idx = n0 * 3 + tid;
        if (idx < N * 3) {
            g_x[idx] = g_x[idx] + g_dx[idx];
            g_dx[idx] = 0.f;
        }
    }
    for (int p = tid; p < 1024; p += NT)
        *(float4*)&sW[p * 4] = *(const float4*)&ew1n[p * 4];
    __syncthreads();

    ZERO_ACC(acc);
    gemm_t(sA, sW, tx, ty, acc);
#pragma unroll
    for (int i = 0; i < 4; i++) {
        int n = n0 + ty * 4 + i;
        if (n < N) {
            float c[4]; UNPACK_ROW(acc[i], c);
            *(float4*)&g_Ad[n * 64 + tx * 4] = make_float4(c[0], c[1], c[2], c[3]);
        }
    }
    __syncthreads();
    for (int p = tid; p < 1024; p += NT)
        *(float4*)&sW[p * 4] = *(const float4*)&ew1n[4096 + p * 4];
    __syncthreads();
    ZERO_ACC(acc);
    gemm_t(sA, sW, tx, ty, acc);
#pragma unroll
    for (int i = 0; i < 4; i++) {
        int n = n0 + ty * 4 + i;
        if (n < N) {
            float c[4]; UNPACK_ROW(acc[i], c);
            *(float4*)&g_As[n * 64 + tx * 4] = make_float4(c[0], c[1], c[2], c[3]);
        }
    }
}

// ---------------------------------------------------------------------------
__global__ __launch_bounds__(NT)
void final_update_kernel(const float* __restrict__ hw1, const float* __restrict__ hb1,
                         const float* __restrict__ hw2, const float* __restrict__ hb2,
                         float* __restrict__ outh, float* __restrict__ outx, int N) {
    __shared__ float sA[TS * LDA];
    __shared__ float sW[4096];
    int tid = threadIdx.x;
    int n0 = blockIdx.x * TS;
    int tx = tid & 15, ty = tid >> 4;

    for (int p = tid; p < TS * 16; p += NT) {
        int i = p >> 4, j = (p & 15) * 4;
        int n = n0 + i;
        float4 v = make_float4(0.f, 0.f, 0.f, 0.f);
        if (n < N) v = *(const float4*)&g_h[n * 64 + j];
        *(float4*)&sA[i * LDA + j] = v;
    }
    for (int p = tid; p < 1024; p += NT)
        *(float4*)&sW[p * 4] = *(const float4*)&hw1[p * 4];
    __syncthreads();

    u64 acc[4][2];
    ZERO_ACC(acc);
    gemm_t(sA, sW, tx, ty, acc);
    __syncthreads();

    for (int p = tid; p < TS * 16; p += NT) {
        int i = p >> 4, j = (p & 15) * 4;
        int n = n0 + i;
        float4 v = make_float4(0.f, 0.f, 0.f, 0.f);
        if (n < N) v = *(const float4*)&g_m[n * 64 + j];
        *(float4*)&sA[i * LDA + j] = v;
    }
    for (int p = tid; p < 1024; p += NT)
        *(float4*)&sW[p * 4] = *(const float4*)&hw1[4096 + p * 4];
    __syncthreads();
    gemm_t(sA, sW, tx, ty, acc);
    __syncthreads();

#pragma unroll
    for (int i = 0; i < 4; i++) {
        int e = ty * 4 + i;
        float c[4]; UNPACK_ROW(acc[i], c);
#pragma unroll
        for (int q = 0; q < 4; q++) c[q] = silu_f(c[q] + hb1[tx * 4 + q]);
        *(float4*)&sA[e * LDA + tx * 4] = make_float4(c[0], c[1], c[2], c[3]);
    }
    for (int p = tid; p < 1024; p += NT)
        *(float4*)&sW[p * 4] = *(const float4*)&hw2[p * 4];
    __syncthreads();

    ZERO_ACC(acc);
    gemm_t(sA, sW, tx, ty, acc);

#pragma unroll
    for (int i = 0; i < 4; i++) {
        int n = n0 + ty * 4 + i;
        if (n < N) {
            float c[4]; UNPACK_ROW(acc[i], c);
            float4 o = *(const float4*)&g_h[n * 64 + tx * 4];
            o.x += c[0] + hb2[tx * 4 + 0];
            o.y += c[1] + hb2[tx * 4 + 1];
            o.z += c[2] + hb2[tx * 4 + 2];
            o.w += c[3] + hb2[tx * 4 + 3];
            *(float4*)&outh[n * 64 + tx * 4] = o;
        }
    }
    if (tid < TS * 3) {
        int idx = n0 * 3 + tid;
        if (idx < N * 3) outx[idx] = g_x[idx] + g_dx[idx];
    }
}

// ---------------------------------------------------------------------------
extern "C" void kernel_launch(void* const* d_in, const int* in_sizes, int n_in,
                              void* d_out, int out_size) {
    const int*   an   = (const int*)d_in[0];
    const float* pos  = (const float*)d_in[1];
    const int*   eidx = (const int*)d_in[2];
    // d_in[3] = edge_attr (unused by reference)
    const float* emb  = (const float*)d_in[4];
    const float* e_w1 = (const float*)d_in[5];
    const float* e_b1 = (const float*)d_in[6];
    const float* e_w2 = (const float*)d_in[7];
    const float* e_b2 = (const float*)d_in[8];
    const float* h_w1 = (const float*)d_in[9];
    const float* h_b1 = (const float*)d_in[10];
    const float* h_w2 = (const float*)d_in[11];
    const float* h_b2 = (const float*)d_in[12];
    const float* x_w1 = (const float*)d_in[13];
    const float* x_b1 = (const float*)d_in[14];
    const float* x_w2 = (const float*)d_in[15];
    const float* x_b2 = (const float*)d_in[16];

    int N = in_sizes[0];
    int E = in_sizes[2] / 2;
    float* out = (float*)d_out;

    cudaFuncSetAttribute(edge_kernel_bf3,
                         cudaFuncAttributeMaxDynamicSharedMemorySize,
                         EDGE_DYN_BYTES);

    int nodeBlocks = (N + TS - 1) / TS;
    int edgeBlocks = (E + ET - 1) / ET;

    init_pre_kernel<<<nodeBlocks, NT>>>(an, emb, pos, e_w1, N);

    edge_kernel_bf3<<<edgeBlocks, ENT, EDGE_DYN_BYTES>>>(
        eidx, eidx + E,
        e_w1 + 128 * 64, e_b1,
        e_w2, e_b2,
        x_w1, x_b1,
        x_w2, x_b2, E);

    update_pre_kernel<<<nodeBlocks, NT>>>(
        h_w1, h_b1, h_w2, h_b2,
        e_w1 + 129 * 64, N);

    edge_kernel_bf3<<<edgeBlocks, ENT, EDGE_DYN_BYTES>>>(
        eidx, eidx + E,
        e_w1 + 129 * 64 + 128 * 64, e_b1 + 64,
        e_w2 + 4096, e_b2 + 64,
        x_w1 + 4096, x_b1 + 64,
        x_w2 + 64, x_b2 + 1, E);

    final_update_kernel<<<nodeBlocks, NT>>>(
        h_w1 + 128 * 64, h_b1 + 64,
        h_w2 + 4096, h_b2 + 64,
        out, out + (size_t)N * 64, N);
}

// round 14
// speedup vs baseline: 2.5068x; 1.1453x over previous
#include <cuda_runtime.h>
#include <cuda_bf16.h>
#include <cstdint>

#define NT 256          // node kernels: threads per block
#define TS 64           // node tile rows
#define LDA 68          // sA row stride (floats) for SIMT gemm
#define ET 224          // edge tile (edges per block)
#define ENT 448         // edge kernel threads (14 warps x 16 rows)
#define LW 36           // edge smem row stride in u32 (72 bf16)

typedef unsigned long long u64;

__device__ float g_h [50048 * 64];
__device__ float g_x [50048 * 3];
__device__ float g_Ad[50048 * 64];   // h @ e_w1[0:64]   (dst part)
__device__ float g_As[50048 * 64];   // h @ e_w1[64:128] (src part)
__device__ float g_m [50048 * 64];   // segment-sum of m_ij
__device__ float g_dx[50048 * 3];    // segment-sum of W_ij * x_diff

// Fast silu: MUFU.EX2 + FADD + MUFU.RCP + FMUL (vs ~20-issue exact fp32 div).
__device__ __forceinline__ float silu_f(float v) {
    return __fdividef(v, 1.0f + __expf(-v));
}
__device__ __forceinline__ u64 pdup(float x) {
    u64 r; asm("mov.b64 %0, {%1, %1};" : "=l"(r) : "f"(x)); return r;
}
__device__ __forceinline__ void up2(u64 v, float& a, float& b) {
    asm("mov.b64 {%0, %1}, %2;" : "=f"(a), "=f"(b) : "l"(v));
}
__device__ __forceinline__ void fma2(u64& c, u64 a, u64 b) {
    asm("fma.rn.f32x2 %0, %1, %2, %0;" : "+l"(c) : "l"(a), "l"(b));
}
__device__ __forceinline__ void red_add_v4(float* p, float a, float b, float c, float d) {
    asm volatile("red.global.add.v4.f32 [%0], {%1, %2, %3, %4};"
                 :: "l"(p), "f"(a), "f"(b), "f"(c), "f"(d) : "memory");
}
__device__ __forceinline__ uint32_t pbf2(float lo, float hi) {
    __nv_bfloat162 t;
    t.x = __float2bfloat16_rn(lo);
    t.y = __float2bfloat16_rn(hi);
    return *reinterpret_cast<uint32_t*>(&t);
}
__device__ __forceinline__ float bfhi(float x) {
    return __bfloat162float(__float2bfloat16_rn(x));
}
__device__ __forceinline__ float2 ubf2(uint32_t u) {
    __nv_bfloat162 t = *reinterpret_cast<__nv_bfloat162*>(&u);
    return make_float2(__bfloat162float(t.x), __bfloat162float(t.y));
}
__device__ __forceinline__ uint32_t smem_u32p(const void* p) {
    uint32_t a;
    asm("{ .reg .u64 t; cvta.to.shared.u64 t, %1; cvt.u32.u64 %0, t; }"
        : "=r"(a) : "l"(p));
    return a;
}
// D(16x8,f32) += A(16x16,bf16,row) * B(16x8,bf16,col)
__device__ __forceinline__ void mma_bf16(float c[4], const uint32_t a[4],
                                         uint32_t b0, uint32_t b1) {
    asm volatile(
        "mma.sync.aligned.m16n8k16.row.col.f32.bf16.bf16.f32 "
        "{%0,%1,%2,%3}, {%4,%5,%6,%7}, {%8,%9}, {%0,%1,%2,%3};"
        : "+f"(c[0]), "+f"(c[1]), "+f"(c[2]), "+f"(c[3])
        : "r"(a[0]), "r"(a[1]), "r"(a[2]), "r"(a[3]), "r"(b0), "r"(b1));
}
__device__ __forceinline__ void ldsm_x4(uint32_t r[4], uint32_t addr) {
    asm volatile("ldmatrix.sync.aligned.m8n8.x4.shared.b16 {%0,%1,%2,%3}, [%4];"
                 : "=r"(r[0]), "=r"(r[1]), "=r"(r[2]), "=r"(r[3]) : "r"(addr));
}

// 3-term bf16 split GEMM via ldmatrix. Warp owns 16 rows rbase..rbase+15.
// n0/n1 MMA streams interleaved: dependent-acc chains get distance-2 spacing.
__device__ __forceinline__ void gemm_bf3(uint32_t aH, uint32_t aL,
                                         uint32_t bH, uint32_t bL,
                                         int lane, int rbase,
                                         float acc[8][4]) {
    int l7 = lane & 7;
    int aRow = l7 + ((lane >> 3) & 1) * 8;      // row within 16-row tile
    int aColU = ((lane >> 4) & 1) * 4;          // k-half in u32
    int bRow = ((lane >> 4) << 3) + l7;         // n within 16-n pair
    int bColU = ((lane >> 3) & 1) * 4;
#pragma unroll
    for (int c = 0; c < 4; c++) {
        int kc = c * 8;                         // u32 k base
        uint32_t ah[4], al[4];
        uint32_t off = (uint32_t)((rbase + aRow) * LW + kc + aColU) * 4u;
        ldsm_x4(ah, aH + off);
        ldsm_x4(al, aL + off);
#pragma unroll
        for (int ntp = 0; ntp < 4; ntp++) {
            uint32_t boff = (uint32_t)((ntp * 16 + bRow) * LW + kc + bColU) * 4u;
            uint32_t bh[4], bl[4];
            ldsm_x4(bh, bH + boff);
            ldsm_x4(bl, bL + boff);
            int n0 = 2 * ntp, n1 = 2 * ntp + 1;
            mma_bf16(acc[n0], ah, bh[0], bh[1]);
            mma_bf16(acc[n1], ah, bh[2], bh[3]);
            mma_bf16(acc[n0], ah, bl[0], bl[1]);
            mma_bf16(acc[n1], ah, bl[2], bl[3]);
            mma_bf16(acc[n0], al, bh[0], bh[1]);
            mma_bf16(acc[n1], al, bh[2], bh[3]);
        }
    }
}

// ===================== SIMT gemm (node kernels, R4-proven) ==================
__device__ __forceinline__ void gemm_t(const float* __restrict__ sA,
                                       const float* __restrict__ sW,
                                       int tx, int ty, u64 acc[4][2]) {
    const float* aR = sA + ty * 4 * LDA;
    const float* bC = sW + tx * 4;
#pragma unroll
    for (int kb = 0; kb < 64; kb += 4) {
        float4 av[4];
#pragma unroll
        for (int i = 0; i < 4; i++)
            av[i] = *(const float4*)(aR + i * LDA + kb);
#pragma unroll
        for (int kk = 0; kk < 4; kk++) {
            ulonglong2 b = *(const ulonglong2*)(bC + (kb + kk) * 64);
#pragma unroll
            for (int i = 0; i < 4; i++) {
                float a = (kk == 0) ? av[i].x : (kk == 1) ? av[i].y
                        : (kk == 2) ? av[i].z : av[i].w;
                u64 aa = pdup(a);
                fma2(acc[i][0], aa, b.x);
                fma2(acc[i][1], aa, b.y);
            }
        }
    }
}

#define ZERO_ACC(acc)                             \
    _Pragma("unroll") for (int i_ = 0; i_ < 4; i_++) { (acc)[i_][0] = 0ull; (acc)[i_][1] = 0ull; }
#define UNPACK_ROW(acc_row, c)  \
    up2((acc_row)[0], (c)[0], (c)[1]); up2((acc_row)[1], (c)[2], (c)[3]);

// ---------------------------------------------------------------------------
// Fused init + node_pre (layer 0)
__global__ __launch_bounds__(NT)
void init_pre_kernel(const int* __restrict__ an, const float* __restrict__ emb,
                     const float* __restrict__ pos, const float* __restrict__ w1,
                     int N) {
    __shared__ float sA[TS * LDA];
    __shared__ float sW[4096];
    int tid = threadIdx.x;
    int n0 = blockIdx.x * TS;
    int tx = tid & 15, ty = tid >> 4;

    for (int p = tid; p < TS * 16; p += NT) {
        int i = p >> 4, j = (p & 15) * 4;
        int n = n0 + i;
        float4 v = make_float4(0.f, 0.f, 0.f, 0.f);
        if (n < N) {
            v = *(const float4*)&emb[an[n] * 64 + j];
            *(float4*)&g_h[n * 64 + j] = v;
            *(float4*)&g_m[n * 64 + j] = make_float4(0.f, 0.f, 0.f, 0.f);
        }
        *(float4*)&sA[i * LDA + j] = v;
    }
    if (tid < TS * 3) {
        int idx = n0 * 3 + tid;
        if (idx < N * 3) { g_x[idx] = pos[idx]; g_dx[idx] = 0.f; }
    }
    for (int p = tid; p < 1024; p += NT)
        *(float4*)&sW[p * 4] = *(const float4*)&w1[p * 4];
    __syncthreads();

    u64 acc[4][2];
    ZERO_ACC(acc);
    gemm_t(sA, sW, tx, ty, acc);
#pragma unroll
    for (int i = 0; i < 4; i++) {
        int n = n0 + ty * 4 + i;
        if (n < N) {
            float c[4]; UNPACK_ROW(acc[i], c);
            *(float4*)&g_Ad[n * 64 + tx * 4] = make_float4(c[0], c[1], c[2], c[3]);
        }
    }
    __syncthreads();
    for (int p = tid; p < 1024; p += NT)
        *(float4*)&sW[p * 4] = *(const float4*)&w1[4096 + p * 4];
    __syncthreads();
    ZERO_ACC(acc);
    gemm_t(sA, sW, tx, ty, acc);
#pragma unroll
    for (int i = 0; i < 4; i++) {
        int n = n0 + ty * 4 + i;
        if (n < N) {
            float c[4]; UNPACK_ROW(acc[i], c);
            *(float4*)&g_As[n * 64 + tx * 4] = make_float4(c[0], c[1], c[2], c[3]);
        }
    }
}

// ---------------------------------------------------------------------------
// 3xBF16 edge kernel: ET=224 edges/block, 448 threads (14 warps x 16 rows).
// Warp-synchronous: ONE block barrier (weights). x_diff kept in registers.
__global__ __launch_bounds__(ENT, 2)
void edge_kernel_bf3(const int* __restrict__ src, const int* __restrict__ dst,
                     const float* __restrict__ w1r, const float* __restrict__ b1,
                     const float* __restrict__ w2,  const float* __restrict__ b2,
                     const float* __restrict__ xw1, const float* __restrict__ xb1,
                     const float* __restrict__ xw2, const float* __restrict__ xb2,
                     int E) {
    extern __shared__ uint32_t dynu[];
    uint32_t* sAh  = dynu;                   // [ET][LW]
    uint32_t* sAl  = sAh + ET * LW;
    uint32_t* sB0h = sAl + ET * LW;          // w2  [64][LW]
    uint32_t* sB0l = sB0h + 64 * LW;
    uint32_t* sB1h = sB0l + 64 * LW;         // xw1 [64][LW]
    uint32_t* sB1l = sB1h + 64 * LW;
    __shared__ int   sdst[ET], ssrc[ET];
    __shared__ float srwe[ET];               // r (pre) aliased with W (post), warp-local
    __shared__ float sw1r[64], sb1v[64], sb2v[64], sxb1[64], sxw2[64];

    int tid = threadIdx.x;
    int lane = tid & 31, warp = tid >> 5;
    int gr = lane >> 2, gc = lane & 3;
    int e0 = blockIdx.x * ET;
    int rbase = warp * 16;

    uint32_t aH = smem_u32p(sAh), aL = smem_u32p(sAl);
    uint32_t b0H = smem_u32p(sB0h), b0L = smem_u32p(sB0l);
    uint32_t b1H = smem_u32p(sB1h), b1L = smem_u32p(sB1l);

    // warp-local metadata: lanes 0..15 own rows rbase+lane; x_diff in registers
    int my_d = -1;
    float xd0 = 0.f, xd1 = 0.f, xd2 = 0.f;
    if (lane < 16) {
        int row = rbase + lane;
        int eg = e0 + row;
        int s = 0;
        if (eg < E) {
            s = src[eg]; my_d = dst[eg];
            xd0 = g_x[s * 3 + 0] - g_x[my_d * 3 + 0];
            xd1 = g_x[s * 3 + 1] - g_x[my_d * 3 + 1];
            xd2 = g_x[s * 3 + 2] - g_x[my_d * 3 + 2];
        }
        ssrc[row] = s; sdst[row] = my_d;
        srwe[row] = sqrtf(xd0 * xd0 + xd1 * xd1 + xd2 * xd2);
    }
    if (tid >= 256 && tid < 320) {
        int j = tid - 256;
        sw1r[j] = w1r[j]; sb1v[j] = b1[j]; sb2v[j] = b2[j];
        sxb1[j] = xb1[j]; sxw2[j] = xw2[j];
    }
    // stage BOTH weights (n-major, hi/lo bf16), block-strided
    for (int p = tid; p < 2048; p += ENT) {
        int k2 = p >> 6, n = p & 63;
        float a0 = w2[(k2 * 2) * 64 + n];
        float a1 = w2[(k2 * 2 + 1) * 64 + n];
        float h0 = bfhi(a0), h1 = bfhi(a1);
        sB0h[n * LW + k2] = pbf2(h0, h1);
        sB0l[n * LW + k2] = pbf2(a0 - h0, a1 - h1);
        float c0 = xw1[(k2 * 2) * 64 + n];
        float c1 = xw1[(k2 * 2 + 1) * 64 + n];
        float g0 = bfhi(c0), g1 = bfhi(c1);
        sB1h[n * LW + k2] = pbf2(g0, g1);
        sB1l[n * LW + k2] = pbf2(c0 - g0, c1 - g1);
    }
    __syncthreads();   // the ONLY block barrier: weights + biases + metadata

    // warp-local t1 staging: own 16 rows x 16 float4-groups, 8 iters/lane
#pragma unroll
    for (int it = 0; it < 8; it++) {
        int i = it * 32 + lane;
        int row = rbase + (i >> 4);
        int j = (i & 15) * 4;
        int d = sdst[row];
        int dd = d < 0 ? 0 : d;
        int s  = ssrc[row];
        float4 ad = *(const float4*)&g_Ad[dd * 64 + j];
        float4 as = *(const float4*)&g_As[s * 64 + j];
        float r = srwe[row];
        float t0 = silu_f(ad.x + as.x + r * sw1r[j + 0] + sb1v[j + 0]);
        float t1 = silu_f(ad.y + as.y + r * sw1r[j + 1] + sb1v[j + 1]);
        float t2 = silu_f(ad.z + as.z + r * sw1r[j + 2] + sb1v[j + 2]);
        float t3 = silu_f(ad.w + as.w + r * sw1r[j + 3] + sb1v[j + 3]);
        float h0 = bfhi(t0), h1 = bfhi(t1), h2 = bfhi(t2), h3 = bfhi(t3);
        int o = row * LW + (j >> 1);
        sAh[o]     = pbf2(h0, h1);
        sAh[o + 1] = pbf2(h2, h3);
        sAl[o]     = pbf2(t0 - h0, t1 - h1);
        sAl[o + 1] = pbf2(t2 - h2, t3 - h3);
    }
    __syncwarp();      // own rows staged

    float acc[8][4];
#pragma unroll
    for (int nt = 0; nt < 8; nt++)
#pragma unroll
        for (int q = 0; q < 4; q++) acc[nt][q] = 0.f;

    gemm_bf3(aH, aL, b0H, b0L, lane, rbase, acc);   // GEMM1: t1 @ w2

    // epilogue 1: m = silu(D + b2) -> rewrite own A rows (hi/lo)
    {
        int ra = rbase + gr, rb = ra + 8;
#pragma unroll
        for (int nt = 0; nt < 8; nt++) {
            int col = nt * 8 + gc * 2;
            float m00 = silu_f(acc[nt][0] + sb2v[col]);
            float m01 = silu_f(acc[nt][1] + sb2v[col + 1]);
            float m10 = silu_f(acc[nt][2] + sb2v[col]);
            float m11 = silu_f(acc[nt][3] + sb2v[col + 1]);
            float h00 = bfhi(m00), h01 = bfhi(m01);
            float h10 = bfhi(m10), h11 = bfhi(m11);
            int oa = ra * LW + nt * 4 + gc, ob = rb * LW + nt * 4 + gc;
            sAh[oa] = pbf2(h00, h01);
            sAl[oa] = pbf2(m00 - h00, m01 - h01);
            sAh[ob] = pbf2(h10, h11);
            sAl[ob] = pbf2(m10 - h10, m11 - h11);
        }
    }
    __syncwarp();

    // coalesced m-scatter (m = hi + lo, exact): own 16 rows x 16 v4-groups
    for (int i = lane; i < 16 * 16; i += 32) {
        int row = rbase + (i >> 4);
        int j2 = (i & 15) * 2;             // u32 offset within row
        int d = sdst[row];
        if (d >= 0) {
            uint32_t h0 = sAh[row * LW + j2], h1 = sAh[row * LW + j2 + 1];
            uint32_t l0 = sAl[row * LW + j2], l1 = sAl[row * LW + j2 + 1];
            float2 fh0 = ubf2(h0), fh1 = ubf2(h1);
            float2 fl0 = ubf2(l0), fl1 = ubf2(l1);
            red_add_v4(&g_m[d * 64 + j2 * 2],
                       fh0.x + fl0.x, fh0.y + fl0.y,
                       fh1.x + fl1.x, fh1.y + fl1.y);
        }
    }
    __syncwarp();

#pragma unroll
    for (int nt = 0; nt < 8; nt++)
#pragma unroll
        for (int q = 0; q < 4; q++) acc[nt][q] = 0.f;

    gemm_bf3(aH, aL, b1H, b1L, lane, rbase, acc);   // GEMM2: m @ xw1

    // epilogue 2: W = silu(D + xb1) . xw2 + xb2  (warp-local rows)
    {
        float Wv0 = 0.f, Wv1 = 0.f;
#pragma unroll
        for (int nt = 0; nt < 8; nt++) {
            int col = nt * 8 + gc * 2;
            Wv0 += silu_f(acc[nt][0] + sxb1[col]) * sxw2[col]
                 + silu_f(acc[nt][1] + sxb1[col + 1]) * sxw2[col + 1];
            Wv1 += silu_f(acc[nt][2] + sxb1[col]) * sxw2[col]
                 + silu_f(acc[nt][3] + sxb1[col + 1]) * sxw2[col + 1];
        }
#pragma unroll
        for (int off = 1; off <= 2; off <<= 1) {
            Wv0 += __shfl_xor_sync(0xffffffffu, Wv0, off);
            Wv1 += __shfl_xor_sync(0xffffffffu, Wv1, off);
        }
        if (gc == 0) {
            float xb2v = __ldg(xb2);
            srwe[rbase + gr]     = Wv0 + xb2v;
            srwe[rbase + gr + 8] = Wv1 + xb2v;
        }
    }
    __syncwarp();      // W for own rows visible within warp

    // dx scatter: lanes 0..15 handle own rows (x_diff from registers)
    if (lane < 16 && my_d >= 0) {
        float W = srwe[rbase + lane];
        atomicAdd(&g_dx[my_d * 3 + 0], W * xd0);
        atomicAdd(&g_dx[my_d * 3 + 1], W * xd1);
        atomicAdd(&g_dx[my_d * 3 + 2], W * xd2);
    }
}

#define EDGE_DYN_BYTES ((2 * ET * LW + 4 * 64 * LW) * 4)

// ---------------------------------------------------------------------------
// Fused node_update + node_pre(next layer). Zeroes m/dx after reading.
__global__ __launch_bounds__(NT)
void update_pre_kernel(const float* __restrict__ hw1, const float* __restrict__ hb1,
                       const float* __restrict__ hw2, const float* __restrict__ hb2,
                       const float* __restrict__ ew1n, int N) {
    __shared__ float sA[TS * LDA];
    __shared__ float sW[4096];
    int tid = threadIdx.x;
    int n0 = blockIdx.x * TS;
    int tx = tid & 15, ty = tid >> 4;

    for (int p = tid; p < TS * 16; p += NT) {
        int i = p >> 4, j = (p & 15) * 4;
        int n = n0 + i;
        float4 v = make_float4(0.f, 0.f, 0.f, 0.f);
        if (n < N) v = *(const float4*)&g_h[n * 64 + j];
        *(float4*)&sA[i * LDA + j] = v;
    }
    for (int p = tid; p < 1024; p += NT)
        *(float4*)&sW[p * 4] = *(const float4*)&hw1[p * 4];
    __syncthreads();

    u64 acc[4][2];
    ZERO_ACC(acc);
    gemm_t(sA, sW, tx, ty, acc);
    __syncthreads();

    for (int p = tid; p < TS * 16; p += NT) {
        int i = p >> 4, j = (p & 15) * 4;
        int n = n0 + i;
        float4 v = make_float4(0.f, 0.f, 0.f, 0.f);
        if (n < N) {
            v = *(const float4*)&g_m[n * 64 + j];
            *(float4*)&g_m[n * 64 + j] = make_float4(0.f, 0.f, 0.f, 0.f);
        }
        *(float4*)&sA[i * LDA + j] = v;
    }
    for (int p = tid; p < 1024; p += NT)
        *(float4*)&sW[p * 4] = *(const float4*)&hw1[4096 + p * 4];
    __syncthreads();
    gemm_t(sA, sW, tx, ty, acc);
    __syncthreads();

#pragma unroll
    for (int i = 0; i < 4; i++) {
        int e = ty * 4 + i;
        float c[4]; UNPACK_ROW(acc[i], c);
#pragma unroll
        for (int q = 0; q < 4; q++) c[q] = silu_f(c[q] + hb1[tx * 4 + q]);
        *(float4*)&sA[e * LDA + tx * 4] = make_float4(c[0], c[1], c[2], c[3]);
    }
    for (int p = tid; p < 1024; p += NT)
        *(float4*)&sW[p * 4] = *(const float4*)&hw2[p * 4];
    __syncthreads();

    ZERO_ACC(acc);
    gemm_t(sA, sW, tx, ty, acc);
    __syncthreads();

#pragma unroll
    for (int i = 0; i < 4; i++) {
        int n = n0 + ty * 4 + i;
        if (n < N) {
            float c[4]; UNPACK_ROW(acc[i], c);
            float4 o = *(const float4*)&g_h[n * 64 + tx * 4];
            o.x += c[0] + hb2[tx * 4 + 0];
            o.y += c[1] + hb2[tx * 4 + 1];
            o.z += c[2] + hb2[tx * 4 + 2];
            o.w += c[3] + hb2[tx * 4 + 3];
            *(float4*)&g_h[n * 64 + tx * 4] = o;
            *(float4*)&sA[(ty * 4 + i) * LDA + tx * 4] = o;
        } else {
            *(float4*)&sA[(ty * 4 + i) * LDA + tx * 4] = make_float4(0.f, 0.f, 0.f, 0.f);
        }
    }
    if (tid < TS * 3) {
        int idx = n0 * 3 + tid;
        if (idx < N * 3) {
            g_x[idx] = g_x[idx] + g_dx[idx];
            g_dx[idx] = 0.f;
        }
    }
    for (int p = tid; p < 1024; p += NT)
        *(float4*)&sW[p * 4] = *(const float4*)&ew1n[p * 4];
    __syncthreads();

    ZERO_ACC(acc);
    gemm_t(sA, sW, tx, ty, acc);
#pragma unroll
    for (int i = 0; i < 4; i++) {
        int n = n0 + ty * 4 + i;
        if (n < N) {
            float c[4]; UNPACK_ROW(acc[i], c);
            *(float4*)&g_Ad[n * 64 + tx * 4] = make_float4(c[0], c[1], c[2], c[3]);
        }
    }
    __syncthreads();
    for (int p = tid; p < 1024; p += NT)
        *(float4*)&sW[p * 4] = *(const float4*)&ew1n[4096 + p * 4];
    __syncthreads();
    ZERO_ACC(acc);
    gemm_t(sA, sW, tx, ty, acc);
#pragma unroll
    for (int i = 0; i < 4; i++) {
        int n = n0 + ty * 4 + i;
        if (n < N) {
            float c[4]; UNPACK_ROW(acc[i], c);
            *(float4*)&g_As[n * 64 + tx * 4] = make_float4(c[0], c[1], c[2], c[3]);
        }
    }
}

// ---------------------------------------------------------------------------
__global__ __launch_bounds__(NT)
void final_update_kernel(const float* __restrict__ hw1, const float* __restrict__ hb1,
                         const float* __restrict__ hw2, const float* __restrict__ hb2,
                         float* __restrict__ outh, float* __restrict__ outx, int N) {
    __shared__ float sA[TS * LDA];
    __shared__ float sW[4096];
    int tid = threadIdx.x;
    int n0 = blockIdx.x * TS;
    int tx = tid & 15, ty = tid >> 4;

    for (int p = tid; p < TS * 16; p += NT) {
        int i = p >> 4, j = (p & 15) * 4;
        int n = n0 + i;
        float4 v = make_float4(0.f, 0.f, 0.f, 0.f);
        if (n < N) v = *(const float4*)&g_h[n * 64 + j];
        *(float4*)&sA[i * LDA + j] = v;
    }
    for (int p = tid; p < 1024; p += NT)
        *(float4*)&sW[p * 4] = *(const float4*)&hw1[p * 4];
    __syncthreads();

    u64 acc[4][2];
    ZERO_ACC(acc);
    gemm_t(sA, sW, tx, ty, acc);
    __syncthreads();

    for (int p = tid; p < TS * 16; p += NT) {
        int i = p >> 4, j = (p & 15) * 4;
        int n = n0 + i;
        float4 v = make_float4(0.f, 0.f, 0.f, 0.f);
        if (n < N) v = *(const float4*)&g_m[n * 64 + j];
        *(float4*)&sA[i * LDA + j] = v;
    }
    for (int p = tid; p < 1024; p += NT)
        *(float4*)&sW[p * 4] = *(const float4*)&hw1[4096 + p * 4];
    __syncthreads();
    gemm_t(sA, sW, tx, ty, acc);
    __syncthreads();

#pragma unroll
    for (int i = 0; i < 4; i++) {
        int e = ty * 4 + i;
        float c[4]; UNPACK_ROW(acc[i], c);
#pragma unroll
        for (int q = 0; q < 4; q++) c[q] = silu_f(c[q] + hb1[tx * 4 + q]);
        *(float4*)&sA[e * LDA + tx * 4] = make_float4(c[0], c[1], c[2], c[3]);
    }
    for (int p = tid; p < 1024; p += NT)
        *(float4*)&sW[p * 4] = *(const float4*)&hw2[p * 4];
    __syncthreads();

    ZERO_ACC(acc);
    gemm_t(sA, sW, tx, ty, acc);

#pragma unroll
    for (int i = 0; i < 4; i++) {
        int n = n0 + ty * 4 + i;
        if (n < N) {
            float c[4]; UNPACK_ROW(acc[i], c);
            float4 o = *(const float4*)&g_h[n * 64 + tx * 4];
            o.x += c[0] + hb2[tx * 4 + 0];
            o.y += c[1] + hb2[tx * 4 + 1];
            o.z += c[2] + hb2[tx * 4 + 2];
            o.w += c[3] + hb2[tx * 4 + 3];
            *(float4*)&outh[n * 64 + tx * 4] = o;
        }
    }
    if (tid < TS * 3) {
        int idx = n0 * 3 + tid;
        if (idx < N * 3) outx[idx] = g_x[idx] + g_dx[idx];
    }
}

// ---------------------------------------------------------------------------
extern "C" void kernel_launch(void* const* d_in, const int* in_sizes, int n_in,
                              void* d_out, int out_size) {
    const int*   an   = (const int*)d_in[0];
    const float* pos  = (const float*)d_in[1];
    const int*   eidx = (const int*)d_in[2];
    // d_in[3] = edge_attr (unused by reference)
    const float* emb  = (const float*)d_in[4];
    const float* e_w1 = (const float*)d_in[5];
    const float* e_b1 = (const float*)d_in[6];
    const float* e_w2 = (const float*)d_in[7];
    const float* e_b2 = (const float*)d_in[8];
    const float* h_w1 = (const float*)d_in[9];
    const float* h_b1 = (const float*)d_in[10];
    const float* h_w2 = (const float*)d_in[11];
    const float* h_b2 = (const float*)d_in[12];
    const float* x_w1 = (const float*)d_in[13];
    const float* x_b1 = (const float*)d_in[14];
    const float* x_w2 = (const float*)d_in[15];
    const float* x_b2 = (const float*)d_in[16];

    int N = in_sizes[0];
    int E = in_sizes[2] / 2;
    float* out = (float*)d_out;

    cudaFuncSetAttribute(edge_kernel_bf3,
                         cudaFuncAttributeMaxDynamicSharedMemorySize,
                         EDGE_DYN_BYTES);

    int nodeBlocks = (N + TS - 1) / TS;
    int edgeBlocks = (E + ET - 1) / ET;

    init_pre_kernel<<<nodeBlocks, NT>>>(an, emb, pos, e_w1, N);

    edge_kernel_bf3<<<edgeBlocks, ENT, EDGE_DYN_BYTES>>>(
        eidx, eidx + E,
        e_w1 + 128 * 64, e_b1,
        e_w2, e_b2,
        x_w1, x_b1,
        x_w2, x_b2, E);

    update_pre_kernel<<<nodeBlocks, NT>>>(
        h_w1, h_b1, h_w2, h_b2,
        e_w1 + 129 * 64, N);

    edge_kernel_bf3<<<edgeBlocks, ENT, EDGE_DYN_BYTES>>>(
        eidx, eidx + E,
        e_w1 + 129 * 64 + 128 * 64, e_b1 + 64,
        e_w2 + 4096, e_b2 + 64,
        x_w1 + 4096, x_b1 + 64,
        x_w2 + 64, x_b2 + 1, E);

    final_update_kernel<<<nodeBlocks, NT>>>(
        h_w1 + 128 * 64, h_b1 + 64,
        h_w2 + 4096, h_b2 + 64,
        out, out + (size_t)N * 64, N);
}

// round 15
// speedup vs baseline: 2.5173x; 1.0042x over previous
#include <cuda_runtime.h>
#include <cuda_bf16.h>
#include <cstdint>

#define NT 256          // node kernels: threads per block
#define TS 64           // node tile rows
#define LDA 68          // sA row stride (floats) for SIMT gemm
#define ET 224          // edge tile (edges per block)
#define ENT 448         // edge kernel threads (14 warps x 16 rows)
#define LW 36           // edge smem row stride in u32 (72 bf16)

typedef unsigned long long u64;

__device__ float g_h [50048 * 64];
__device__ float g_x [50048 * 3];
__device__ float g_Ad[50048 * 64];   // h @ e_w1[0:64]   (dst part)
__device__ float g_As[50048 * 64];   // h @ e_w1[64:128] (src part)
__device__ float g_m [50048 * 64];   // segment-sum of m_ij
__device__ float g_dx[50048 * 3];    // segment-sum of W_ij * x_diff

// Fast silu: MUFU.EX2 + FADD + MUFU.RCP + FMUL.
__device__ __forceinline__ float silu_f(float v) {
    return __fdividef(v, 1.0f + __expf(-v));
}
__device__ __forceinline__ u64 pdup(float x) {
    u64 r; asm("mov.b64 %0, {%1, %1};" : "=l"(r) : "f"(x)); return r;
}
__device__ __forceinline__ void up2(u64 v, float& a, float& b) {
    asm("mov.b64 {%0, %1}, %2;" : "=f"(a), "=f"(b) : "l"(v));
}
__device__ __forceinline__ void fma2(u64& c, u64 a, u64 b) {
    asm("fma.rn.f32x2 %0, %1, %2, %0;" : "+l"(c) : "l"(a), "l"(b));
}
__device__ __forceinline__ void red_add_v4(float* p, float a, float b, float c, float d) {
    asm volatile("red.global.add.v4.f32 [%0], {%1, %2, %3, %4};"
                 :: "l"(p), "f"(a), "f"(b), "f"(c), "f"(d) : "memory");
}
// single-instruction pack: {lo, hi} -> bf16x2
__device__ __forceinline__ uint32_t pbf2(float lo, float hi) {
    uint32_t r;
    asm("cvt.rn.bf16x2.f32 %0, %1, %2;" : "=r"(r) : "f"(hi), "f"(lo));
    return r;
}
__device__ __forceinline__ float bfhi(float x) {
    return __bfloat162float(__float2bfloat16_rn(x));
}
__device__ __forceinline__ uint32_t smem_u32p(const void* p) {
    uint32_t a;
    asm("{ .reg .u64 t; cvta.to.shared.u64 t, %1; cvt.u32.u64 %0, t; }"
        : "=r"(a) : "l"(p));
    return a;
}
// D(16x8,f32) += A(16x16,bf16,row) * B(16x8,bf16,col)
__device__ __forceinline__ void mma_bf16(float c[4], const uint32_t a[4],
                                         uint32_t b0, uint32_t b1) {
    asm volatile(
        "mma.sync.aligned.m16n8k16.row.col.f32.bf16.bf16.f32 "
        "{%0,%1,%2,%3}, {%4,%5,%6,%7}, {%8,%9}, {%0,%1,%2,%3};"
        : "+f"(c[0]), "+f"(c[1]), "+f"(c[2]), "+f"(c[3])
        : "r"(a[0]), "r"(a[1]), "r"(a[2]), "r"(a[3]), "r"(b0), "r"(b1));
}
__device__ __forceinline__ void ldsm_x4(uint32_t r[4], uint32_t addr) {
    asm volatile("ldmatrix.sync.aligned.m8n8.x4.shared.b16 {%0,%1,%2,%3}, [%4];"
                 : "=r"(r[0]), "=r"(r[1]), "=r"(r[2]), "=r"(r[3]) : "r"(addr));
}

// 3-term bf16 split GEMM via ldmatrix. Warp owns 16 rows rbase..rbase+15.
__device__ __forceinline__ void gemm_bf3(uint32_t aH, uint32_t aL,
                                         uint32_t bH, uint32_t bL,
                                         int lane, int rbase,
                                         float acc[8][4]) {
    int l7 = lane & 7;
    int aRow = l7 + ((lane >> 3) & 1) * 8;      // row within 16-row tile
    int aColU = ((lane >> 4) & 1) * 4;          // k-half in u32
    int bRow = ((lane >> 4) << 3) + l7;         // n within 16-n pair
    int bColU = ((lane >> 3) & 1) * 4;
#pragma unroll
    for (int c = 0; c < 4; c++) {
        int kc = c * 8;                         // u32 k base
        uint32_t ah[4], al[4];
        uint32_t off = (uint32_t)((rbase + aRow) * LW + kc + aColU) * 4u;
        ldsm_x4(ah, aH + off);
        ldsm_x4(al, aL + off);
#pragma unroll
        for (int ntp = 0; ntp < 4; ntp++) {
            uint32_t boff = (uint32_t)((ntp * 16 + bRow) * LW + kc + bColU) * 4u;
            uint32_t bh[4], bl[4];
            ldsm_x4(bh, bH + boff);
            ldsm_x4(bl, bL + boff);
            int n0 = 2 * ntp, n1 = 2 * ntp + 1;
            mma_bf16(acc[n0], ah, bh[0], bh[1]);
            mma_bf16(acc[n1], ah, bh[2], bh[3]);
            mma_bf16(acc[n0], ah, bl[0], bl[1]);
            mma_bf16(acc[n1], ah, bl[2], bl[3]);
            mma_bf16(acc[n0], al, bh[0], bh[1]);
            mma_bf16(acc[n1], al, bh[2], bh[3]);
        }
    }
}

// ===================== SIMT gemm (node kernels, R4-proven) ==================
__device__ __forceinline__ void gemm_t(const float* __restrict__ sA,
                                       const float* __restrict__ sW,
                                       int tx, int ty, u64 acc[4][2]) {
    const float* aR = sA + ty * 4 * LDA;
    const float* bC = sW + tx * 4;
#pragma unroll
    for (int kb = 0; kb < 64; kb += 4) {
        float4 av[4];
#pragma unroll
        for (int i = 0; i < 4; i++)
            av[i] = *(const float4*)(aR + i * LDA + kb);
#pragma unroll
        for (int kk = 0; kk < 4; kk++) {
            ulonglong2 b = *(const ulonglong2*)(bC + (kb + kk) * 64);
#pragma unroll
            for (int i = 0; i < 4; i++) {
                float a = (kk == 0) ? av[i].x : (kk == 1) ? av[i].y
                        : (kk == 2) ? av[i].z : av[i].w;
                u64 aa = pdup(a);
                fma2(acc[i][0], aa, b.x);
                fma2(acc[i][1], aa, b.y);
            }
        }
    }
}

#define ZERO_ACC(acc)                             \
    _Pragma("unroll") for (int i_ = 0; i_ < 4; i_++) { (acc)[i_][0] = 0ull; (acc)[i_][1] = 0ull; }
#define UNPACK_ROW(acc_row, c)  \
    up2((acc_row)[0], (c)[0], (c)[1]); up2((acc_row)[1], (c)[2], (c)[3]);

// ---------------------------------------------------------------------------
// Fused init + node_pre (layer 0)
__global__ __launch_bounds__(NT)
void init_pre_kernel(const int* __restrict__ an, const float* __restrict__ emb,
                     const float* __restrict__ pos, const float* __restrict__ w1,
                     int N) {
    __shared__ float sA[TS * LDA];
    __shared__ float sW[4096];
    int tid = threadIdx.x;
    int n0 = blockIdx.x * TS;
    int tx = tid & 15, ty = tid >> 4;

    for (int p = tid; p < TS * 16; p += NT) {
        int i = p >> 4, j = (p & 15) * 4;
        int n = n0 + i;
        float4 v = make_float4(0.f, 0.f, 0.f, 0.f);
        if (n < N) {
            v = *(const float4*)&emb[an[n] * 64 + j];
            *(float4*)&g_h[n * 64 + j] = v;
            *(float4*)&g_m[n * 64 + j] = make_float4(0.f, 0.f, 0.f, 0.f);
        }
        *(float4*)&sA[i * LDA + j] = v;
    }
    if (tid < TS * 3) {
        int idx = n0 * 3 + tid;
        if (idx < N * 3) { g_x[idx] = pos[idx]; g_dx[idx] = 0.f; }
    }
    for (int p = tid; p < 1024; p += NT)
        *(float4*)&sW[p * 4] = *(const float4*)&w1[p * 4];
    __syncthreads();

    u64 acc[4][2];
    ZERO_ACC(acc);
    gemm_t(sA, sW, tx, ty, acc);
#pragma unroll
    for (int i = 0; i < 4; i++) {
        int n = n0 + ty * 4 + i;
        if (n < N) {
            float c[4]; UNPACK_ROW(acc[i], c);
            *(float4*)&g_Ad[n * 64 + tx * 4] = make_float4(c[0], c[1], c[2], c[3]);
        }
    }
    __syncthreads();
    for (int p = tid; p < 1024; p += NT)
        *(float4*)&sW[p * 4] = *(const float4*)&w1[4096 + p * 4];
    __syncthreads();
    ZERO_ACC(acc);
    gemm_t(sA, sW, tx, ty, acc);
#pragma unroll
    for (int i = 0; i < 4; i++) {
        int n = n0 + ty * 4 + i;
        if (n < N) {
            float c[4]; UNPACK_ROW(acc[i], c);
            *(float4*)&g_As[n * 64 + tx * 4] = make_float4(c[0], c[1], c[2], c[3]);
        }
    }
}

// ---------------------------------------------------------------------------
// 3xBF16 edge kernel: ET=224 edges/block, 448 threads (14 warps x 16 rows).
// Warp-synchronous. m-scatter fused into epilogue-1 via lane shuffles.
__global__ __launch_bounds__(ENT, 2)
void edge_kernel_bf3(const int* __restrict__ src, const int* __restrict__ dst,
                     const float* __restrict__ w1r, const float* __restrict__ b1,
                     const float* __restrict__ w2,  const float* __restrict__ b2,
                     const float* __restrict__ xw1, const float* __restrict__ xb1,
                     const float* __restrict__ xw2, const float* __restrict__ xb2,
                     int E) {
    extern __shared__ uint32_t dynu[];
    uint32_t* sAh  = dynu;                   // [ET][LW]
    uint32_t* sAl  = sAh + ET * LW;
    uint32_t* sB0h = sAl + ET * LW;          // w2  [64][LW]
    uint32_t* sB0l = sB0h + 64 * LW;
    uint32_t* sB1h = sB0l + 64 * LW;         // xw1 [64][LW]
    uint32_t* sB1l = sB1h + 64 * LW;
    __shared__ int   sdst[ET], ssrc[ET];
    __shared__ float srwe[ET];               // r (pre) aliased with W (post), warp-local
    __shared__ float sw1r[64], sb1v[64], sb2v[64], sxb1[64], sxw2[64];

    int tid = threadIdx.x;
    int lane = tid & 31, warp = tid >> 5;
    int gr = lane >> 2, gc = lane & 3;
    int e0 = blockIdx.x * ET;
    int rbase = warp * 16;

    uint32_t aH = smem_u32p(sAh), aL = smem_u32p(sAl);
    uint32_t b0H = smem_u32p(sB0h), b0L = smem_u32p(sB0l);
    uint32_t b1H = smem_u32p(sB1h), b1L = smem_u32p(sB1l);

    // warp-local metadata: lanes 0..15 own rows rbase+lane; x_diff in registers
    int my_d = -1;
    float xd0 = 0.f, xd1 = 0.f, xd2 = 0.f;
    if (lane < 16) {
        int row = rbase + lane;
        int eg = e0 + row;
        int s = 0;
        if (eg < E) {
            s = src[eg]; my_d = dst[eg];
            xd0 = g_x[s * 3 + 0] - g_x[my_d * 3 + 0];
            xd1 = g_x[s * 3 + 1] - g_x[my_d * 3 + 1];
            xd2 = g_x[s * 3 + 2] - g_x[my_d * 3 + 2];
        }
        ssrc[row] = s; sdst[row] = my_d;
        srwe[row] = sqrtf(xd0 * xd0 + xd1 * xd1 + xd2 * xd2);
    }
    if (tid >= 256 && tid < 320) {
        int j = tid - 256;
        sw1r[j] = w1r[j]; sb1v[j] = b1[j]; sb2v[j] = b2[j];
        sxb1[j] = xb1[j]; sxw2[j] = xw2[j];
    }
    // stage BOTH weights (n-major, hi/lo bf16), block-strided
    for (int p = tid; p < 2048; p += ENT) {
        int k2 = p >> 6, n = p & 63;
        float a0 = w2[(k2 * 2) * 64 + n];
        float a1 = w2[(k2 * 2 + 1) * 64 + n];
        float h0 = bfhi(a0), h1 = bfhi(a1);
        sB0h[n * LW + k2] = pbf2(h0, h1);
        sB0l[n * LW + k2] = pbf2(a0 - h0, a1 - h1);
        float c0 = xw1[(k2 * 2) * 64 + n];
        float c1 = xw1[(k2 * 2 + 1) * 64 + n];
        float g0 = bfhi(c0), g1 = bfhi(c1);
        sB1h[n * LW + k2] = pbf2(g0, g1);
        sB1l[n * LW + k2] = pbf2(c0 - g0, c1 - g1);
    }
    __syncthreads();   // the ONLY block barrier

    // warp-local t1 staging: own 16 rows x 16 float4-groups, 8 iters/lane
#pragma unroll
    for (int it = 0; it < 8; it++) {
        int i = it * 32 + lane;
        int row = rbase + (i >> 4);
        int j = (i & 15) * 4;
        int d = sdst[row];
        int dd = d < 0 ? 0 : d;
        int s  = ssrc[row];
        float4 ad = *(const float4*)&g_Ad[dd * 64 + j];
        float4 as = *(const float4*)&g_As[s * 64 + j];
        float r = srwe[row];
        float t0 = silu_f(ad.x + as.x + r * sw1r[j + 0] + sb1v[j + 0]);
        float t1 = silu_f(ad.y + as.y + r * sw1r[j + 1] + sb1v[j + 1]);
        float t2 = silu_f(ad.z + as.z + r * sw1r[j + 2] + sb1v[j + 2]);
        float t3 = silu_f(ad.w + as.w + r * sw1r[j + 3] + sb1v[j + 3]);
        float h0 = bfhi(t0), h1 = bfhi(t1), h2 = bfhi(t2), h3 = bfhi(t3);
        int o = row * LW + (j >> 1);
        sAh[o]     = pbf2(h0, h1);
        sAh[o + 1] = pbf2(h2, h3);
        sAl[o]     = pbf2(t0 - h0, t1 - h1);
        sAl[o + 1] = pbf2(t2 - h2, t3 - h3);
    }
    __syncwarp();      // own rows staged

    float acc[8][4];
#pragma unroll
    for (int nt = 0; nt < 8; nt++)
#pragma unroll
        for (int q = 0; q < 4; q++) acc[nt][q] = 0.f;

    gemm_bf3(aH, aL, b0H, b0L, lane, rbase, acc);   // GEMM1: t1 @ w2

    // epilogue 1: m = silu(D + b2); scatter exact fp32 m via lane shuffles
    // (lanes gc / gc^1 own adjacent col pairs -> v4 assembled with shfl_xor 1);
    // rewrite own A rows as bf16 hi/lo for GEMM2.
    {
        int ra = rbase + gr, rb = ra + 8;
        int da = sdst[ra], db = sdst[rb];
#pragma unroll
        for (int nt = 0; nt < 8; nt++) {
            int col = nt * 8 + gc * 2;
            float m00 = silu_f(acc[nt][0] + sb2v[col]);
            float m01 = silu_f(acc[nt][1] + sb2v[col + 1]);
            float m10 = silu_f(acc[nt][2] + sb2v[col]);
            float m11 = silu_f(acc[nt][3] + sb2v[col + 1]);
            // partner pair (cols +2,+3 for even gc)
            float p00 = __shfl_xor_sync(0xffffffffu, m00, 1);
            float p01 = __shfl_xor_sync(0xffffffffu, m01, 1);
            float p10 = __shfl_xor_sync(0xffffffffu, m10, 1);
            float p11 = __shfl_xor_sync(0xffffffffu, m11, 1);
            if ((gc & 1) == 0) {
                if (da >= 0) red_add_v4(&g_m[da * 64 + col], m00, m01, p00, p01);
                if (db >= 0) red_add_v4(&g_m[db * 64 + col], m10, m11, p10, p11);
            }
            float h00 = bfhi(m00), h01 = bfhi(m01);
            float h10 = bfhi(m10), h11 = bfhi(m11);
            int oa = ra * LW + nt * 4 + gc, ob = rb * LW + nt * 4 + gc;
            sAh[oa] = pbf2(h00, h01);
            sAl[oa] = pbf2(m00 - h00, m01 - h01);
            sAh[ob] = pbf2(h10, h11);
            sAl[ob] = pbf2(m10 - h10, m11 - h11);
        }
    }
    __syncwarp();

#pragma unroll
    for (int nt = 0; nt < 8; nt++)
#pragma unroll
        for (int q = 0; q < 4; q++) acc[nt][q] = 0.f;

    gemm_bf3(aH, aL, b1H, b1L, lane, rbase, acc);   // GEMM2: m @ xw1

    // epilogue 2: W = silu(D + xb1) . xw2 + xb2  (warp-local rows)
    {
        float Wv0 = 0.f, Wv1 = 0.f;
#pragma unroll
        for (int nt = 0; nt < 8; nt++) {
            int col = nt * 8 + gc * 2;
            Wv0 += silu_f(acc[nt][0] + sxb1[col]) * sxw2[col]
                 + silu_f(acc[nt][1] + sxb1[col + 1]) * sxw2[col + 1];
            Wv1 += silu_f(acc[nt][2] + sxb1[col]) * sxw2[col]
                 + silu_f(acc[nt][3] + sxb1[col + 1]) * sxw2[col + 1];
        }
#pragma unroll
        for (int off = 1; off <= 2; off <<= 1) {
            Wv0 += __shfl_xor_sync(0xffffffffu, Wv0, off);
            Wv1 += __shfl_xor_sync(0xffffffffu, Wv1, off);
        }
        if (gc == 0) {
            float xb2v = __ldg(xb2);
            srwe[rbase + gr]     = Wv0 + xb2v;
            srwe[rbase + gr + 8] = Wv1 + xb2v;
        }
    }
    __syncwarp();      // W for own rows visible within warp

    // dx scatter: lanes 0..15 handle own rows (x_diff from registers)
    if (lane < 16 && my_d >= 0) {
        float W = srwe[rbase + lane];
        atomicAdd(&g_dx[my_d * 3 + 0], W * xd0);
        atomicAdd(&g_dx[my_d * 3 + 1], W * xd1);
        atomicAdd(&g_dx[my_d * 3 + 2], W * xd2);
    }
}

#define EDGE_DYN_BYTES ((2 * ET * LW + 4 * 64 * LW) * 4)

// ---------------------------------------------------------------------------
// Fused node_update + node_pre(next layer). Zeroes m/dx after reading.
__global__ __launch_bounds__(NT)
void update_pre_kernel(const float* __restrict__ hw1, const float* __restrict__ hb1,
                       const float* __restrict__ hw2, const float* __restrict__ hb2,
                       const float* __restrict__ ew1n, int N) {
    __shared__ float sA[TS * LDA];
    __shared__ float sW[4096];
    int tid = threadIdx.x;
    int n0 = blockIdx.x * TS;
    int tx = tid & 15, ty = tid >> 4;

    for (int p = tid; p < TS * 16; p += NT) {
        int i = p >> 4, j = (p & 15) * 4;
        int n = n0 + i;
        float4 v = make_float4(0.f, 0.f, 0.f, 0.f);
        if (n < N) v = *(const float4*)&g_h[n * 64 + j];
        *(float4*)&sA[i * LDA + j] = v;
    }
    for (int p = tid; p < 1024; p += NT)
        *(float4*)&sW[p * 4] = *(const float4*)&hw1[p * 4];
    __syncthreads();

    u64 acc[4][2];
    ZERO_ACC(acc);
    gemm_t(sA, sW, tx, ty, acc);
    __syncthreads();

    for (int p = tid; p < TS * 16; p += NT) {
        int i = p >> 4, j = (p & 15) * 4;
        int n = n0 + i;
        float4 v = make_float4(0.f, 0.f, 0.f, 0.f);
        if (n < N) {
            v = *(const float4*)&g_m[n * 64 + j];
            *(float4*)&g_m[n * 64 + j] = make_float4(0.f, 0.f, 0.f, 0.f);
        }
        *(float4*)&sA[i * LDA + j] = v;
    }
    for (int p = tid; p < 1024; p += NT)
        *(float4*)&sW[p * 4] = *(const float4*)&hw1[4096 + p * 4];
    __syncthreads();
    gemm_t(sA, sW, tx, ty, acc);
    __syncthreads();

#pragma unroll
    for (int i = 0; i < 4; i++) {
        int e = ty * 4 + i;
        float c[4]; UNPACK_ROW(acc[i], c);
#pragma unroll
        for (int q = 0; q < 4; q++) c[q] = silu_f(c[q] + hb1[tx * 4 + q]);
        *(float4*)&sA[e * LDA + tx * 4] = make_float4(c[0], c[1], c[2], c[3]);
    }
    for (int p = tid; p < 1024; p += NT)
        *(float4*)&sW[p * 4] = *(const float4*)&hw2[p * 4];
    __syncthreads();

    ZERO_ACC(acc);
    gemm_t(sA, sW, tx, ty, acc);
    __syncthreads();

#pragma unroll
    for (int i = 0; i < 4; i++) {
        int n = n0 + ty * 4 + i;
        if (n < N) {
            float c[4]; UNPACK_ROW(acc[i], c);
            float4 o = *(const float4*)&g_h[n * 64 + tx * 4];
            o.x += c[0] + hb2[tx * 4 + 0];
            o.y += c[1] + hb2[tx * 4 + 1];
            o.z += c[2] + hb2[tx * 4 + 2];
            o.w += c[3] + hb2[tx * 4 + 3];
            *(float4*)&g_h[n * 64 + tx * 4] = o;
            *(float4*)&sA[(ty * 4 + i) * LDA + tx * 4] = o;
        } else {
            *(float4*)&sA[(ty * 4 + i) * LDA + tx * 4] = make_float4(0.f, 0.f, 0.f, 0.f);
        }
    }
    if (tid < TS * 3) {
        int idx = n0 * 3 + tid;
        if (idx < N * 3) {
            g_x[idx] = g_x[idx] + g_dx[idx];
            g_dx[idx] = 0.f;
        }
    }
    for (int p = tid; p < 1024; p += NT)
        *(float4*)&sW[p * 4] = *(const float4*)&ew1n[p * 4];
    __syncthreads();

    ZERO_ACC(acc);
    gemm_t(sA, sW, tx, ty, acc);
#pragma unroll
    for (int i = 0; i < 4; i++) {
        int n = n0 + ty * 4 + i;
        if (n < N) {
            float c[4]; UNPACK_ROW(acc[i], c);
            *(float4*)&g_Ad[n * 64 + tx * 4] = make_float4(c[0], c[1], c[2], c[3]);
        }
    }
    __syncthreads();
    for (int p = tid; p < 1024; p += NT)
        *(float4*)&sW[p * 4] = *(const float4*)&ew1n[4096 + p * 4];
    __syncthreads();
    ZERO_ACC(acc);
    gemm_t(sA, sW, tx, ty, acc);
#pragma unroll
    for (int i = 0; i < 4; i++) {
        int n = n0 + ty * 4 + i;
        if (n < N) {
            float c[4]; UNPACK_ROW(acc[i], c);
            *(float4*)&g_As[n * 64 + tx * 4] = make_float4(c[0], c[1], c[2], c[3]);
        }
    }
}

// ---------------------------------------------------------------------------
__global__ __launch_bounds__(NT)
void final_update_kernel(const float* __restrict__ hw1, const float* __restrict__ hb1,
                         const float* __restrict__ hw2, const float* __restrict__ hb2,
                         float* __restrict__ outh, float* __restrict__ outx, int N) {
    __shared__ float sA[TS * LDA];
    __shared__ float sW[4096];
    int tid = threadIdx.x;
    int n0 = blockIdx.x * TS;
    int tx = tid & 15, ty = tid >> 4;

    for (int p = tid; p < TS * 16; p += NT) {
        int i = p >> 4, j = (p & 15) * 4;
        int n = n0 + i;
        float4 v = make_float4(0.f, 0.f, 0.f, 0.f);
        if (n < N) v = *(const float4*)&g_h[n * 64 + j];
        *(float4*)&sA[i * LDA + j] = v;
    }
    for (int p = tid; p < 1024; p += NT)
        *(float4*)&sW[p * 4] = *(const float4*)&hw1[p * 4];
    __syncthreads();

    u64 acc[4][2];
    ZERO_ACC(acc);
    gemm_t(sA, sW, tx, ty, acc);
    __syncthreads();

    for (int p = tid; p < TS * 16; p += NT) {
        int i = p >> 4, j = (p & 15) * 4;
        int n = n0 + i;
        float4 v = make_float4(0.f, 0.f, 0.f, 0.f);
        if (n < N) v = *(const float4*)&g_m[n * 64 + j];
        *(float4*)&sA[i * LDA + j] = v;
    }
    for (int p = tid; p < 1024; p += NT)
        *(float4*)&sW[p * 4] = *(const float4*)&hw1[4096 + p * 4];
    __syncthreads();
    gemm_t(sA, sW, tx, ty, acc);
    __syncthreads();

#pragma unroll
    for (int i = 0; i < 4; i++) {
        int e = ty * 4 + i;
        float c[4]; UNPACK_ROW(acc[i], c);
#pragma unroll
        for (int q = 0; q < 4; q++) c[q] = silu_f(c[q] + hb1[tx * 4 + q]);
        *(float4*)&sA[e * LDA + tx * 4] = make_float4(c[0], c[1], c[2], c[3]);
    }
    for (int p = tid; p < 1024; p += NT)
        *(float4*)&sW[p * 4] = *(const float4*)&hw2[p * 4];
    __syncthreads();

    ZERO_ACC(acc);
    gemm_t(sA, sW, tx, ty, acc);

#pragma unroll
    for (int i = 0; i < 4; i++) {
        int n = n0 + ty * 4 + i;
        if (n < N) {
            float c[4]; UNPACK_ROW(acc[i], c);
            float4 o = *(const float4*)&g_h[n * 64 + tx * 4];
            o.x += c[0] + hb2[tx * 4 + 0];
            o.y += c[1] + hb2[tx * 4 + 1];
            o.z += c[2] + hb2[tx * 4 + 2];
            o.w += c[3] + hb2[tx * 4 + 3];
            *(float4*)&outh[n * 64 + tx * 4] = o;
        }
    }
    if (tid < TS * 3) {
        int idx = n0 * 3 + tid;
        if (idx < N * 3) outx[idx] = g_x[idx] + g_dx[idx];
    }
}

// ---------------------------------------------------------------------------
extern "C" void kernel_launch(void* const* d_in, const int* in_sizes, int n_in,
                              void* d_out, int out_size) {
    const int*   an   = (const int*)d_in[0];
    const float* pos  = (const float*)d_in[1];
    const int*   eidx = (const int*)d_in[2];
    // d_in[3] = edge_attr (unused by reference)
    const float* emb  = (const float*)d_in[4];
    const float* e_w1 = (const float*)d_in[5];
    const float* e_b1 = (const float*)d_in[6];
    const float* e_w2 = (const float*)d_in[7];
    const float* e_b2 = (const float*)d_in[8];
    const float* h_w1 = (const float*)d_in[9];
    const float* h_b1 = (const float*)d_in[10];
    const float* h_w2 = (const float*)d_in[11];
    const float* h_b2 = (const float*)d_in[12];
    const float* x_w1 = (const float*)d_in[13];
    const float* x_b1 = (const float*)d_in[14];
    const float* x_w2 = (const float*)d_in[15];
    const float* x_b2 = (const float*)d_in[16];

    int N = in_sizes[0];
    int E = in_sizes[2] / 2;
    float* out = (float*)d_out;

    cudaFuncSetAttribute(edge_kernel_bf3,
                         cudaFuncAttributeMaxDynamicSharedMemorySize,
                         EDGE_DYN_BYTES);

    int nodeBlocks = (N + TS - 1) / TS;
    int edgeBlocks = (E + ET - 1) / ET;

    init_pre_kernel<<<nodeBlocks, NT>>>(an, emb, pos, e_w1, N);

    edge_kernel_bf3<<<edgeBlocks, ENT, EDGE_DYN_BYTES>>>(
        eidx, eidx + E,
        e_w1 + 128 * 64, e_b1,
        e_w2, e_b2,
        x_w1, x_b1,
        x_w2, x_b2, E);

    update_pre_kernel<<<nodeBlocks, NT>>>(
        h_w1, h_b1, h_w2, h_b2,
        e_w1 + 129 * 64, N);

    edge_kernel_bf3<<<edgeBlocks, ENT, EDGE_DYN_BYTES>>>(
        eidx, eidx + E,
        e_w1 + 129 * 64 + 128 * 64, e_b1 + 64,
        e_w2 + 4096, e_b2 + 64,
        x_w1 + 4096, x_b1 + 64,
        x_w2 + 64, x_b2 + 1, E);

    final_update_kernel<<<nodeBlocks, NT>>>(
        h_w1 + 128 * 64, h_b1 + 64,
        h_w2 + 4096, h_b2 + 64,
        out, out + (size_t)N * 64, N);
}

// round 16
// speedup vs baseline: 2.7540x; 1.0941x over previous
#include <cuda_runtime.h>
#include <cuda_bf16.h>
#include <cstdint>

#define ET 224          // edge tile (edges per block)
#define ENT 448         // edge kernel threads (14 warps x 16 rows)
#define NTS 128         // node tile (nodes per block)
#define NNT 256         // node kernel threads (8 warps x 16 rows)
#define LW 36           // smem row stride in u32 (72 bf16)

typedef unsigned long long u64;

__device__ float g_h [50048 * 64];
__device__ float g_x [50048 * 3];
__device__ float g_Ad[50048 * 64];   // h @ e_w1[0:64]   (dst part)
__device__ float g_As[50048 * 64];   // h @ e_w1[64:128] (src part)
__device__ float g_m [50048 * 64];   // segment-sum of m_ij
__device__ float g_dx[50048 * 3];    // segment-sum of W_ij * x_diff

__device__ __forceinline__ float silu_f(float v) {
    return __fdividef(v, 1.0f + __expf(-v));
}
__device__ __forceinline__ void red_add_v4(float* p, float a, float b, float c, float d) {
    asm volatile("red.global.add.v4.f32 [%0], {%1, %2, %3, %4};"
                 :: "l"(p), "f"(a), "f"(b), "f"(c), "f"(d) : "memory");
}
// single-instruction pack: {lo, hi} -> bf16x2
__device__ __forceinline__ uint32_t pbf2(float lo, float hi) {
    uint32_t r;
    asm("cvt.rn.bf16x2.f32 %0, %1, %2;" : "=r"(r) : "f"(hi), "f"(lo));
    return r;
}
__device__ __forceinline__ float bfhi(float x) {
    return __bfloat162float(__float2bfloat16_rn(x));
}
__device__ __forceinline__ uint32_t smem_u32p(const void* p) {
    uint32_t a;
    asm("{ .reg .u64 t; cvta.to.shared.u64 t, %1; cvt.u32.u64 %0, t; }"
        : "=r"(a) : "l"(p));
    return a;
}
// D(16x8,f32) += A(16x16,bf16,row) * B(16x8,bf16,col)
__device__ __forceinline__ void mma_bf16(float c[4], const uint32_t a[4],
                                         uint32_t b0, uint32_t b1) {
    asm volatile(
        "mma.sync.aligned.m16n8k16.row.col.f32.bf16.bf16.f32 "
        "{%0,%1,%2,%3}, {%4,%5,%6,%7}, {%8,%9}, {%0,%1,%2,%3};"
        : "+f"(c[0]), "+f"(c[1]), "+f"(c[2]), "+f"(c[3])
        : "r"(a[0]), "r"(a[1]), "r"(a[2]), "r"(a[3]), "r"(b0), "r"(b1));
}
__device__ __forceinline__ void ldsm_x4(uint32_t r[4], uint32_t addr) {
    asm volatile("ldmatrix.sync.aligned.m8n8.x4.shared.b16 {%0,%1,%2,%3}, [%4];"
                 : "=r"(r[0]), "=r"(r[1]), "=r"(r[2]), "=r"(r[3]) : "r"(addr));
}

// 3-term bf16 split GEMM via ldmatrix. Warp owns 16 rows rbase..rbase+15.
__device__ __forceinline__ void gemm_bf3(uint32_t aH, uint32_t aL,
                                         uint32_t bH, uint32_t bL,
                                         int lane, int rbase,
                                         float acc[8][4]) {
    int l7 = lane & 7;
    int aRow = l7 + ((lane >> 3) & 1) * 8;
    int aColU = ((lane >> 4) & 1) * 4;
    int bRow = ((lane >> 4) << 3) + l7;
    int bColU = ((lane >> 3) & 1) * 4;
#pragma unroll
    for (int c = 0; c < 4; c++) {
        int kc = c * 8;
        uint32_t ah[4], al[4];
        uint32_t off = (uint32_t)((rbase + aRow) * LW + kc + aColU) * 4u;
        ldsm_x4(ah, aH + off);
        ldsm_x4(al, aL + off);
#pragma unroll
        for (int ntp = 0; ntp < 4; ntp++) {
            uint32_t boff = (uint32_t)((ntp * 16 + bRow) * LW + kc + bColU) * 4u;
            uint32_t bh[4], bl[4];
            ldsm_x4(bh, bH + boff);
            ldsm_x4(bl, bL + boff);
            int n0 = 2 * ntp, n1 = 2 * ntp + 1;
            mma_bf16(acc[n0], ah, bh[0], bh[1]);
            mma_bf16(acc[n1], ah, bh[2], bh[3]);
            mma_bf16(acc[n0], ah, bl[0], bl[1]);
            mma_bf16(acc[n1], ah, bl[2], bl[3]);
            mma_bf16(acc[n0], al, bh[0], bh[1]);
            mma_bf16(acc[n1], al, bh[2], bh[3]);
        }
    }
}

#define ZACC(acc) \
    _Pragma("unroll") for (int nt_ = 0; nt_ < 8; nt_++) \
    _Pragma("unroll") for (int q_ = 0; q_ < 4; q_++) (acc)[nt_][q_] = 0.f;

// stage one 64x64 fp32 weight (k-major) into n-major bf16 hi/lo buffers
__device__ __forceinline__ void stage_w(uint32_t* dh, uint32_t* dl,
                                        const float* __restrict__ w,
                                        int tid, int nthr) {
    for (int p = tid; p < 2048; p += nthr) {
        int k2 = p >> 6, n = p & 63;
        float a0 = w[(k2 * 2) * 64 + n];
        float a1 = w[(k2 * 2 + 1) * 64 + n];
        float h0 = bfhi(a0), h1 = bfhi(a1);
        dh[n * LW + k2] = pbf2(h0, h1);
        dl[n * LW + k2] = pbf2(a0 - h0, a1 - h1);
    }
}

// stage warp-owned 16 rows of a fp32 [*,64] array into sAh/sAl (hi/lo bf16)
__device__ __forceinline__ void stage_A(uint32_t* sAh, uint32_t* sAl,
                                        const float* __restrict__ src,
                                        int n0, int N, int rbase, int lane) {
#pragma unroll
    for (int it = 0; it < 8; it++) {
        int i = it * 32 + lane;
        int row = rbase + (i >> 4);
        int j = (i & 15) * 4;
        int n = n0 + row;
        float4 v = make_float4(0.f, 0.f, 0.f, 0.f);
        if (n < N) v = *(const float4*)&src[n * 64 + j];
        float h0 = bfhi(v.x), h1 = bfhi(v.y), h2 = bfhi(v.z), h3 = bfhi(v.w);
        int o = row * LW + (j >> 1);
        sAh[o]     = pbf2(h0, h1);
        sAh[o + 1] = pbf2(h2, h3);
        sAl[o]     = pbf2(v.x - h0, v.y - h1);
        sAl[o + 1] = pbf2(v.z - h2, v.w - h3);
    }
}

#define NODE_DYN_BYTES ((2 * NTS * LW + 4 * 64 * LW) * 4)
#define EDGE_DYN_BYTES ((2 * ET * LW + 4 * 64 * LW) * 4)

// ---------------------------------------------------------------------------
// Fused init + node_pre (layer 0): tensor path, 128 nodes/block.
__global__ __launch_bounds__(NNT)
void init_pre_kernel(const int* __restrict__ an, const float* __restrict__ emb,
                     const float* __restrict__ pos, const float* __restrict__ w1,
                     int N) {
    extern __shared__ uint32_t dynu[];
    uint32_t* sAh  = dynu;
    uint32_t* sAl  = sAh + NTS * LW;
    uint32_t* sB0h = sAl + NTS * LW;
    uint32_t* sB0l = sB0h + 64 * LW;
    uint32_t* sB1h = sB0l + 64 * LW;
    uint32_t* sB1l = sB1h + 64 * LW;
    __shared__ int san[NTS];

    int tid = threadIdx.x;
    int lane = tid & 31, warp = tid >> 5;
    int gr = lane >> 2, gc = lane & 3;
    int n0 = blockIdx.x * NTS;
    int rbase = warp * 16;
    uint32_t aH = smem_u32p(sAh), aL = smem_u32p(sAl);
    uint32_t b0H = smem_u32p(sB0h), b0L = smem_u32p(sB0l);
    uint32_t b1H = smem_u32p(sB1h), b1L = smem_u32p(sB1l);

    if (lane < 16) {
        int row = rbase + lane;
        int n = n0 + row;
        san[row] = (n < N) ? an[n] * 64 : 0;
    }
    for (int p = tid; p < NTS * 3; p += NNT) {
        int idx = n0 * 3 + p;
        if (idx < N * 3) { g_x[idx] = pos[idx]; g_dx[idx] = 0.f; }
    }
    stage_w(sB0h, sB0l, w1, tid, NNT);
    stage_w(sB1h, sB1l, w1 + 4096, tid, NNT);
    __syncthreads();

    // stage A = emb[an] rows; write g_h, zero g_m
#pragma unroll
    for (int it = 0; it < 8; it++) {
        int i = it * 32 + lane;
        int row = rbase + (i >> 4);
        int j = (i & 15) * 4;
        int n = n0 + row;
        float4 v = make_float4(0.f, 0.f, 0.f, 0.f);
        if (n < N) {
            v = *(const float4*)&emb[san[row] + j];
            *(float4*)&g_h[n * 64 + j] = v;
            *(float4*)&g_m[n * 64 + j] = make_float4(0.f, 0.f, 0.f, 0.f);
        }
        float h0 = bfhi(v.x), h1 = bfhi(v.y), h2 = bfhi(v.z), h3 = bfhi(v.w);
        int o = row * LW + (j >> 1);
        sAh[o]     = pbf2(h0, h1);
        sAh[o + 1] = pbf2(h2, h3);
        sAl[o]     = pbf2(v.x - h0, v.y - h1);
        sAl[o + 1] = pbf2(v.z - h2, v.w - h3);
    }
    __syncwarp();

    float acc[8][4];
    int ra = rbase + gr, rb = ra + 8;
    int na = n0 + ra, nb = n0 + rb;

    ZACC(acc);
    gemm_bf3(aH, aL, b0H, b0L, lane, rbase, acc);
#pragma unroll
    for (int nt = 0; nt < 8; nt++) {
        int col = nt * 8 + gc * 2;
        if (na < N) *(float2*)&g_Ad[na * 64 + col] = make_float2(acc[nt][0], acc[nt][1]);
        if (nb < N) *(float2*)&g_Ad[nb * 64 + col] = make_float2(acc[nt][2], acc[nt][3]);
    }
    ZACC(acc);
    gemm_bf3(aH, aL, b1H, b1L, lane, rbase, acc);
#pragma unroll
    for (int nt = 0; nt < 8; nt++) {
        int col = nt * 8 + gc * 2;
        if (na < N) *(float2*)&g_As[na * 64 + col] = make_float2(acc[nt][0], acc[nt][1]);
        if (nb < N) *(float2*)&g_As[nb * 64 + col] = make_float2(acc[nt][2], acc[nt][3]);
    }
}

// ---------------------------------------------------------------------------
// 3xBF16 edge kernel (unchanged from R15).
__global__ __launch_bounds__(ENT, 2)
void edge_kernel_bf3(const int* __restrict__ src, const int* __restrict__ dst,
                     const float* __restrict__ w1r, const float* __restrict__ b1,
                     const float* __restrict__ w2,  const float* __restrict__ b2,
                     const float* __restrict__ xw1, const float* __restrict__ xb1,
                     const float* __restrict__ xw2, const float* __restrict__ xb2,
                     int E) {
    extern __shared__ uint32_t dynu[];
    uint32_t* sAh  = dynu;
    uint32_t* sAl  = sAh + ET * LW;
    uint32_t* sB0h = sAl + ET * LW;
    uint32_t* sB0l = sB0h + 64 * LW;
    uint32_t* sB1h = sB0l + 64 * LW;
    uint32_t* sB1l = sB1h + 64 * LW;
    __shared__ int   sdst[ET], ssrc[ET];
    __shared__ float srwe[ET];
    __shared__ float sw1r[64], sb1v[64], sb2v[64], sxb1[64], sxw2[64];

    int tid = threadIdx.x;
    int lane = tid & 31, warp = tid >> 5;
    int gr = lane >> 2, gc = lane & 3;
    int e0 = blockIdx.x * ET;
    int rbase = warp * 16;

    uint32_t aH = smem_u32p(sAh), aL = smem_u32p(sAl);
    uint32_t b0H = smem_u32p(sB0h), b0L = smem_u32p(sB0l);
    uint32_t b1H = smem_u32p(sB1h), b1L = smem_u32p(sB1l);

    int my_d = -1;
    float xd0 = 0.f, xd1 = 0.f, xd2 = 0.f;
    if (lane < 16) {
        int row = rbase + lane;
        int eg = e0 + row;
        int s = 0;
        if (eg < E) {
            s = src[eg]; my_d = dst[eg];
            xd0 = g_x[s * 3 + 0] - g_x[my_d * 3 + 0];
            xd1 = g_x[s * 3 + 1] - g_x[my_d * 3 + 1];
            xd2 = g_x[s * 3 + 2] - g_x[my_d * 3 + 2];
        }
        ssrc[row] = s; sdst[row] = my_d;
        srwe[row] = sqrtf(xd0 * xd0 + xd1 * xd1 + xd2 * xd2);
    }
    if (tid >= 256 && tid < 320) {
        int j = tid - 256;
        sw1r[j] = w1r[j]; sb1v[j] = b1[j]; sb2v[j] = b2[j];
        sxb1[j] = xb1[j]; sxw2[j] = xw2[j];
    }
    stage_w(sB0h, sB0l, w2, tid, ENT);
    stage_w(sB1h, sB1l, xw1, tid, ENT);
    __syncthreads();

#pragma unroll
    for (int it = 0; it < 8; it++) {
        int i = it * 32 + lane;
        int row = rbase + (i >> 4);
        int j = (i & 15) * 4;
        int d = sdst[row];
        int dd = d < 0 ? 0 : d;
        int s  = ssrc[row];
        float4 ad = *(const float4*)&g_Ad[dd * 64 + j];
        float4 as = *(const float4*)&g_As[s * 64 + j];
        float r = srwe[row];
        float t0 = silu_f(ad.x + as.x + r * sw1r[j + 0] + sb1v[j + 0]);
        float t1 = silu_f(ad.y + as.y + r * sw1r[j + 1] + sb1v[j + 1]);
        float t2 = silu_f(ad.z + as.z + r * sw1r[j + 2] + sb1v[j + 2]);
        float t3 = silu_f(ad.w + as.w + r * sw1r[j + 3] + sb1v[j + 3]);
        float h0 = bfhi(t0), h1 = bfhi(t1), h2 = bfhi(t2), h3 = bfhi(t3);
        int o = row * LW + (j >> 1);
        sAh[o]     = pbf2(h0, h1);
        sAh[o + 1] = pbf2(h2, h3);
        sAl[o]     = pbf2(t0 - h0, t1 - h1);
        sAl[o + 1] = pbf2(t2 - h2, t3 - h3);
    }
    __syncwarp();

    float acc[8][4];
    ZACC(acc);
    gemm_bf3(aH, aL, b0H, b0L, lane, rbase, acc);

    {
        int ra = rbase + gr, rb = ra + 8;
        int da = sdst[ra], db = sdst[rb];
#pragma unroll
        for (int nt = 0; nt < 8; nt++) {
            int col = nt * 8 + gc * 2;
            float m00 = silu_f(acc[nt][0] + sb2v[col]);
            float m01 = silu_f(acc[nt][1] + sb2v[col + 1]);
            float m10 = silu_f(acc[nt][2] + sb2v[col]);
            float m11 = silu_f(acc[nt][3] + sb2v[col + 1]);
            float p00 = __shfl_xor_sync(0xffffffffu, m00, 1);
            float p01 = __shfl_xor_sync(0xffffffffu, m01, 1);
            float p10 = __shfl_xor_sync(0xffffffffu, m10, 1);
            float p11 = __shfl_xor_sync(0xffffffffu, m11, 1);
            if ((gc & 1) == 0) {
                if (da >= 0) red_add_v4(&g_m[da * 64 + col], m00, m01, p00, p01);
                if (db >= 0) red_add_v4(&g_m[db * 64 + col], m10, m11, p10, p11);
            }
            float h00 = bfhi(m00), h01 = bfhi(m01);
            float h10 = bfhi(m10), h11 = bfhi(m11);
            int oa = ra * LW + nt * 4 + gc, ob = rb * LW + nt * 4 + gc;
            sAh[oa] = pbf2(h00, h01);
            sAl[oa] = pbf2(m00 - h00, m01 - h01);
            sAh[ob] = pbf2(h10, h11);
            sAl[ob] = pbf2(m10 - h10, m11 - h11);
        }
    }
    __syncwarp();

    ZACC(acc);
    gemm_bf3(aH, aL, b1H, b1L, lane, rbase, acc);

    {
        float Wv0 = 0.f, Wv1 = 0.f;
#pragma unroll
        for (int nt = 0; nt < 8; nt++) {
            int col = nt * 8 + gc * 2;
            Wv0 += silu_f(acc[nt][0] + sxb1[col]) * sxw2[col]
                 + silu_f(acc[nt][1] + sxb1[col + 1]) * sxw2[col + 1];
            Wv1 += silu_f(acc[nt][2] + sxb1[col]) * sxw2[col]
                 + silu_f(acc[nt][3] + sxb1[col + 1]) * sxw2[col + 1];
        }
#pragma unroll
        for (int off = 1; off <= 2; off <<= 1) {
            Wv0 += __shfl_xor_sync(0xffffffffu, Wv0, off);
            Wv1 += __shfl_xor_sync(0xffffffffu, Wv1, off);
        }
        if (gc == 0) {
            float xb2v = __ldg(xb2);
            srwe[rbase + gr]     = Wv0 + xb2v;
            srwe[rbase + gr + 8] = Wv1 + xb2v;
        }
    }
    __syncwarp();

    if (lane < 16 && my_d >= 0) {
        float W = srwe[rbase + lane];
        atomicAdd(&g_dx[my_d * 3 + 0], W * xd0);
        atomicAdd(&g_dx[my_d * 3 + 1], W * xd1);
        atomicAdd(&g_dx[my_d * 3 + 2], W * xd2);
    }
}

// ---------------------------------------------------------------------------
// Fused node_update + node_pre(next layer), tensor path. Zeroes m/dx.
__global__ __launch_bounds__(NNT)
void update_pre_kernel(const float* __restrict__ hw1, const float* __restrict__ hb1,
                       const float* __restrict__ hw2, const float* __restrict__ hb2,
                       const float* __restrict__ ew1n, int N) {
    extern __shared__ uint32_t dynu[];
    uint32_t* sAh  = dynu;
    uint32_t* sAl  = sAh + NTS * LW;
    uint32_t* sB0h = sAl + NTS * LW;
    uint32_t* sB0l = sB0h + 64 * LW;
    uint32_t* sB1h = sB0l + 64 * LW;
    uint32_t* sB1l = sB1h + 64 * LW;
    __shared__ float shb1[64], shb2[64];

    int tid = threadIdx.x;
    int lane = tid & 31, warp = tid >> 5;
    int gr = lane >> 2, gc = lane & 3;
    int n0 = blockIdx.x * NTS;
    int rbase = warp * 16;
    uint32_t aH = smem_u32p(sAh), aL = smem_u32p(sAl);
    uint32_t b0H = smem_u32p(sB0h), b0L = smem_u32p(sB0l);
    uint32_t b1H = smem_u32p(sB1h), b1L = smem_u32p(sB1l);

    if (tid < 64) { shb1[tid] = hb1[tid]; shb2[tid] = hb2[tid]; }
    stage_w(sB0h, sB0l, hw1, tid, NNT);
    stage_w(sB1h, sB1l, hw1 + 4096, tid, NNT);
    __syncthreads();

    float acc[8][4];
    int ra = rbase + gr, rb = ra + 8;
    int na = n0 + ra, nb = n0 + rb;

    // GEMM1: h @ hw1a
    stage_A(sAh, sAl, g_h, n0, N, rbase, lane);
    __syncwarp();
    ZACC(acc);
    gemm_bf3(aH, aL, b0H, b0L, lane, rbase, acc);
    __syncwarp();

    // GEMM2: m @ hw1b (accumulate); read + zero m
#pragma unroll
    for (int it = 0; it < 8; it++) {
        int i = it * 32 + lane;
        int row = rbase + (i >> 4);
        int j = (i & 15) * 4;
        int n = n0 + row;
        float4 v = make_float4(0.f, 0.f, 0.f, 0.f);
        if (n < N) {
            v = *(const float4*)&g_m[n * 64 + j];
            *(float4*)&g_m[n * 64 + j] = make_float4(0.f, 0.f, 0.f, 0.f);
        }
        float h0 = bfhi(v.x), h1 = bfhi(v.y), h2 = bfhi(v.z), h3 = bfhi(v.w);
        int o = row * LW + (j >> 1);
        sAh[o]     = pbf2(h0, h1);
        sAh[o + 1] = pbf2(h2, h3);
        sAl[o]     = pbf2(v.x - h0, v.y - h1);
        sAl[o + 1] = pbf2(v.z - h2, v.w - h3);
    }
    __syncwarp();
    gemm_bf3(aH, aL, b1H, b1L, lane, rbase, acc);

    // epilogue: t = silu(acc + hb1) -> stage own rows
#pragma unroll
    for (int nt = 0; nt < 8; nt++) {
        int col = nt * 8 + gc * 2;
        float t00 = silu_f(acc[nt][0] + shb1[col]);
        float t01 = silu_f(acc[nt][1] + shb1[col + 1]);
        float t10 = silu_f(acc[nt][2] + shb1[col]);
        float t11 = silu_f(acc[nt][3] + shb1[col + 1]);
        float h00 = bfhi(t00), h01 = bfhi(t01);
        float h10 = bfhi(t10), h11 = bfhi(t11);
        int oa = ra * LW + nt * 4 + gc, ob = rb * LW + nt * 4 + gc;
        sAh[oa] = pbf2(h00, h01);
        sAl[oa] = pbf2(t00 - h00, t01 - h01);
        sAh[ob] = pbf2(h10, h11);
        sAl[ob] = pbf2(t10 - h10, t11 - h11);
    }
    __syncthreads();               // all warps done with hw1a/hw1b
    stage_w(sB0h, sB0l, hw2, tid, NNT);
    stage_w(sB1h, sB1l, ew1n, tid, NNT);
    __syncthreads();

    // GEMM3: t @ hw2
    ZACC(acc);
    gemm_bf3(aH, aL, b0H, b0L, lane, rbase, acc);

    // epilogue: h_new = h_old + acc + hb2 -> g_h, stage for GEMM4/5
#pragma unroll
    for (int nt = 0; nt < 8; nt++) {
        int col = nt * 8 + gc * 2;
        float h00 = 0.f, h01 = 0.f, h10 = 0.f, h11 = 0.f;
        if (na < N) {
            float2 o = *(const float2*)&g_h[na * 64 + col];
            h00 = o.x + acc[nt][0] + shb2[col];
            h01 = o.y + acc[nt][1] + shb2[col + 1];
            *(float2*)&g_h[na * 64 + col] = make_float2(h00, h01);
        }
        if (nb < N) {
            float2 o = *(const float2*)&g_h[nb * 64 + col];
            h10 = o.x + acc[nt][2] + shb2[col];
            h11 = o.y + acc[nt][3] + shb2[col + 1];
            *(float2*)&g_h[nb * 64 + col] = make_float2(h10, h11);
        }
        float q00 = bfhi(h00), q01 = bfhi(h01);
        float q10 = bfhi(h10), q11 = bfhi(h11);
        int oa = ra * LW + nt * 4 + gc, ob = rb * LW + nt * 4 + gc;
        sAh[oa] = pbf2(q00, q01);
        sAl[oa] = pbf2(h00 - q00, h01 - q01);
        sAh[ob] = pbf2(q10, q11);
        sAl[ob] = pbf2(h10 - q10, h11 - q11);
    }
    // x update (block-owned rows)
    for (int p = tid; p < NTS * 3; p += NNT) {
        int idx = n0 * 3 + p;
        if (idx < N * 3) {
            g_x[idx] = g_x[idx] + g_dx[idx];
            g_dx[idx] = 0.f;
        }
    }
    __syncthreads();               // hw2 reads done
    stage_w(sB0h, sB0l, ew1n + 4096, tid, NNT);

    // GEMM4: h_new @ ew1a -> g_Ad  (B1 staged earlier)
    ZACC(acc);
    gemm_bf3(aH, aL, b1H, b1L, lane, rbase, acc);
#pragma unroll
    for (int nt = 0; nt < 8; nt++) {
        int col = nt * 8 + gc * 2;
        if (na < N) *(float2*)&g_Ad[na * 64 + col] = make_float2(acc[nt][0], acc[nt][1]);
        if (nb < N) *(float2*)&g_Ad[nb * 64 + col] = make_float2(acc[nt][2], acc[nt][3]);
    }
    __syncthreads();               // B0 restage (ew1b) visible

    // GEMM5: h_new @ ew1b -> g_As
    ZACC(acc);
    gemm_bf3(aH, aL, b0H, b0L, lane, rbase, acc);
#pragma unroll
    for (int nt = 0; nt < 8; nt++) {
        int col = nt * 8 + gc * 2;
        if (na < N) *(float2*)&g_As[na * 64 + col] = make_float2(acc[nt][0], acc[nt][1]);
        if (nb < N) *(float2*)&g_As[nb * 64 + col] = make_float2(acc[nt][2], acc[nt][3]);
    }
}

// ---------------------------------------------------------------------------
// Final node update (tensor path): writes h, x into output buffer.
__global__ __launch_bounds__(NNT)
void final_update_kernel(const float* __restrict__ hw1, const float* __restrict__ hb1,
                         const float* __restrict__ hw2, const float* __restrict__ hb2,
                         float* __restrict__ outh, float* __restrict__ outx, int N) {
    extern __shared__ uint32_t dynu[];
    uint32_t* sAh  = dynu;
    uint32_t* sAl  = sAh + NTS * LW;
    uint32_t* sB0h = sAl + NTS * LW;
    uint32_t* sB0l = sB0h + 64 * LW;
    uint32_t* sB1h = sB0l + 64 * LW;
    uint32_t* sB1l = sB1h + 64 * LW;
    __shared__ float shb1[64], shb2[64];

    int tid = threadIdx.x;
    int lane = tid & 31, warp = tid >> 5;
    int gr = lane >> 2, gc = lane & 3;
    int n0 = blockIdx.x * NTS;
    int rbase = warp * 16;
    uint32_t aH = smem_u32p(sAh), aL = smem_u32p(sAl);
    uint32_t b0H = smem_u32p(sB0h), b0L = smem_u32p(sB0l);
    uint32_t b1H = smem_u32p(sB1h), b1L = smem_u32p(sB1l);

    if (tid < 64) { shb1[tid] = hb1[tid]; shb2[tid] = hb2[tid]; }
    stage_w(sB0h, sB0l, hw1, tid, NNT);
    stage_w(sB1h, sB1l, hw1 + 4096, tid, NNT);
    __syncthreads();

    float acc[8][4];
    int ra = rbase + gr, rb = ra + 8;
    int na = n0 + ra, nb = n0 + rb;

    stage_A(sAh, sAl, g_h, n0, N, rbase, lane);
    __syncwarp();
    ZACC(acc);
    gemm_bf3(aH, aL, b0H, b0L, lane, rbase, acc);
    __syncwarp();

    stage_A(sAh, sAl, g_m, n0, N, rbase, lane);
    __syncwarp();
    gemm_bf3(aH, aL, b1H, b1L, lane, rbase, acc);

#pragma unroll
    for (int nt = 0; nt < 8; nt++) {
        int col = nt * 8 + gc * 2;
        float t00 = silu_f(acc[nt][0] + shb1[col]);
        float t01 = silu_f(acc[nt][1] + shb1[col + 1]);
        float t10 = silu_f(acc[nt][2] + shb1[col]);
        float t11 = silu_f(acc[nt][3] + shb1[col + 1]);
        float h00 = bfhi(t00), h01 = bfhi(t01);
        float h10 = bfhi(t10), h11 = bfhi(t11);
        int oa = ra * LW + nt * 4 + gc, ob = rb * LW + nt * 4 + gc;
        sAh[oa] = pbf2(h00, h01);
        sAl[oa] = pbf2(t00 - h00, t01 - h01);
        sAh[ob] = pbf2(h10, h11);
        sAl[ob] = pbf2(t10 - h10, t11 - h11);
    }
    __syncthreads();
    stage_w(sB0h, sB0l, hw2, tid, NNT);
    __syncthreads();

    ZACC(acc);
    gemm_bf3(aH, aL, b0H, b0L, lane, rbase, acc);

#pragma unroll
    for (int nt = 0; nt < 8; nt++) {
        int col = nt * 8 + gc * 2;
        if (na < N) {
            float2 o = *(const float2*)&g_h[na * 64 + col];
            *(float2*)&outh[na * 64 + col] =
                make_float2(o.x + acc[nt][0] + shb2[col],
                            o.y + acc[nt][1] + shb2[col + 1]);
        }
        if (nb < N) {
            float2 o = *(const float2*)&g_h[nb * 64 + col];
            *(float2*)&outh[nb * 64 + col] =
                make_float2(o.x + acc[nt][2] + shb2[col],
                            o.y + acc[nt][3] + shb2[col + 1]);
        }
    }
    for (int p = tid; p < NTS * 3; p += NNT) {
        int idx = n0 * 3 + p;
        if (idx < N * 3) outx[idx] = g_x[idx] + g_dx[idx];
    }
}

// ---------------------------------------------------------------------------
extern "C" void kernel_launch(void* const* d_in, const int* in_sizes, int n_in,
                              void* d_out, int out_size) {
    const int*   an   = (const int*)d_in[0];
    const float* pos  = (const float*)d_in[1];
    const int*   eidx = (const int*)d_in[2];
    // d_in[3] = edge_attr (unused by reference)
    const float* emb  = (const float*)d_in[4];
    const float* e_w1 = (const float*)d_in[5];
    const float* e_b1 = (const float*)d_in[6];
    const float* e_w2 = (const float*)d_in[7];
    const float* e_b2 = (const float*)d_in[8];
    const float* h_w1 = (const float*)d_in[9];
    const float* h_b1 = (const float*)d_in[10];
    const float* h_w2 = (const float*)d_in[11];
    const float* h_b2 = (const float*)d_in[12];
    const float* x_w1 = (const float*)d_in[13];
    const float* x_b1 = (const float*)d_in[14];
    const float* x_w2 = (const float*)d_in[15];
    const float* x_b2 = (const float*)d_in[16];

    int N = in_sizes[0];
    int E = in_sizes[2] / 2;
    float* out = (float*)d_out;

    cudaFuncSetAttribute(edge_kernel_bf3,
                         cudaFuncAttributeMaxDynamicSharedMemorySize, EDGE_DYN_BYTES);
    cudaFuncSetAttribute(init_pre_kernel,
                         cudaFuncAttributeMaxDynamicSharedMemorySize, NODE_DYN_BYTES);
    cudaFuncSetAttribute(update_pre_kernel,
                         cudaFuncAttributeMaxDynamicSharedMemorySize, NODE_DYN_BYTES);
    cudaFuncSetAttribute(final_update_kernel,
                         cudaFuncAttributeMaxDynamicSharedMemorySize, NODE_DYN_BYTES);

    int nodeBlocks = (N + NTS - 1) / NTS;
    int edgeBlocks = (E + ET - 1) / ET;

    init_pre_kernel<<<nodeBlocks, NNT, NODE_DYN_BYTES>>>(an, emb, pos, e_w1, N);

    edge_kernel_bf3<<<edgeBlocks, ENT, EDGE_DYN_BYTES>>>(
        eidx, eidx + E,
        e_w1 + 128 * 64, e_b1,
        e_w2, e_b2,
        x_w1, x_b1,
        x_w2, x_b2, E);

    update_pre_kernel<<<nodeBlocks, NNT, NODE_DYN_BYTES>>>(
        h_w1, h_b1, h_w2, h_b2,
        e_w1 + 129 * 64, N);

    edge_kernel_bf3<<<edgeBlocks, ENT, EDGE_DYN_BYTES>>>(
        eidx, eidx + E,
        e_w1 + 129 * 64 + 128 * 64, e_b1 + 64,
        e_w2 + 4096, e_b2 + 64,
        x_w1 + 4096, x_b1 + 64,
        x_w2 + 64, x_b2 + 1, E);

    final_update_kernel<<<nodeBlocks, NNT, NODE_DYN_BYTES>>>(
        h_w1 + 128 * 64, h_b1 + 64,
        h_w2 + 4096, h_b2 + 64,
        out, out + (size_t)N * 64, N);
}

// round 17
// speedup vs baseline: 2.7575x; 1.0012x over previous
#include <cuda_runtime.h>
#include <cuda_bf16.h>
#include <cstdint>

#define ET 224          // edge tile (edges per block)
#define ENT 448         // edge kernel threads (14 warps x 16 rows)
#define NTS 128         // node tile (nodes per block)
#define NNT 256         // node kernel threads (8 warps x 16 rows)
#define LW 36           // smem row stride in u32 (72 bf16)

typedef unsigned long long u64;

__device__ float g_h [50048 * 64];
__device__ float g_x [50048 * 3];
__device__ float g_Ad[50048 * 64];   // h @ e_w1[0:64]   (dst part)
__device__ float g_As[50048 * 64];   // h @ e_w1[64:128] (src part)
__device__ float g_m [50048 * 64];   // segment-sum of m_ij
__device__ float g_dx[50048 * 3];    // segment-sum of W_ij * x_diff

__device__ __forceinline__ float silu_f(float v) {
    return __fdividef(v, 1.0f + __expf(-v));
}
__device__ __forceinline__ void red_add_v4(float* p, float a, float b, float c, float d) {
    asm volatile("red.global.add.v4.f32 [%0], {%1, %2, %3, %4};"
                 :: "l"(p), "f"(a), "f"(b), "f"(c), "f"(d) : "memory");
}
__device__ __forceinline__ void red_add_v2(float* p, float a, float b) {
    asm volatile("red.global.add.v2.f32 [%0], {%1, %2};"
                 :: "l"(p), "f"(a), "f"(b) : "memory");
}
// single-instruction pack: {lo, hi} -> bf16x2 (lo in low 16 bits)
__device__ __forceinline__ uint32_t pbf2(float lo, float hi) {
    uint32_t r;
    asm("cvt.rn.bf16x2.f32 %0, %1, %2;" : "=r"(r) : "f"(hi), "f"(lo));
    return r;
}
// split pair (a,b) into packed bf16 hi + packed bf16 lo; hi floats derived
// from the pack bits (saves the cvt round-trips).
__device__ __forceinline__ void split2(float a, float b,
                                       uint32_t& hi_pk, uint32_t& lo_pk) {
    uint32_t h = pbf2(a, b);
    float ha = __uint_as_float(h << 16);
    float hb = __uint_as_float(h & 0xFFFF0000u);
    lo_pk = pbf2(a - ha, b - hb);
    hi_pk = h;
}
__device__ __forceinline__ uint32_t smem_u32p(const void* p) {
    uint32_t a;
    asm("{ .reg .u64 t; cvta.to.shared.u64 t, %1; cvt.u32.u64 %0, t; }"
        : "=r"(a) : "l"(p));
    return a;
}
// D(16x8,f32) += A(16x16,bf16,row) * B(16x8,bf16,col)
__device__ __forceinline__ void mma_bf16(float c[4], const uint32_t a[4],
                                         uint32_t b0, uint32_t b1) {
    asm volatile(
        "mma.sync.aligned.m16n8k16.row.col.f32.bf16.bf16.f32 "
        "{%0,%1,%2,%3}, {%4,%5,%6,%7}, {%8,%9}, {%0,%1,%2,%3};"
        : "+f"(c[0]), "+f"(c[1]), "+f"(c[2]), "+f"(c[3])
        : "r"(a[0]), "r"(a[1]), "r"(a[2]), "r"(a[3]), "r"(b0), "r"(b1));
}
__device__ __forceinline__ void ldsm_x4(uint32_t r[4], uint32_t addr) {
    asm volatile("ldmatrix.sync.aligned.m8n8.x4.shared.b16 {%0,%1,%2,%3}, [%4];"
                 : "=r"(r[0]), "=r"(r[1]), "=r"(r[2]), "=r"(r[3]) : "r"(addr));
}

// 3-term bf16 split GEMM via ldmatrix. Warp owns 16 rows rbase..rbase+15.
__device__ __forceinline__ void gemm_bf3(uint32_t aH, uint32_t aL,
                                         uint32_t bH, uint32_t bL,
                                         int lane, int rbase,
                                         float acc[8][4]) {
    int l7 = lane & 7;
    int aRow = l7 + ((lane >> 3) & 1) * 8;
    int aColU = ((lane >> 4) & 1) * 4;
    int bRow = ((lane >> 4) << 3) + l7;
    int bColU = ((lane >> 3) & 1) * 4;
#pragma unroll
    for (int c = 0; c < 4; c++) {
        int kc = c * 8;
        uint32_t ah[4], al[4];
        uint32_t off = (uint32_t)((rbase + aRow) * LW + kc + aColU) * 4u;
        ldsm_x4(ah, aH + off);
        ldsm_x4(al, aL + off);
#pragma unroll
        for (int ntp = 0; ntp < 4; ntp++) {
            uint32_t boff = (uint32_t)((ntp * 16 + bRow) * LW + kc + bColU) * 4u;
            uint32_t bh[4], bl[4];
            ldsm_x4(bh, bH + boff);
            ldsm_x4(bl, bL + boff);
            int n0 = 2 * ntp, n1 = 2 * ntp + 1;
            mma_bf16(acc[n0], ah, bh[0], bh[1]);
            mma_bf16(acc[n1], ah, bh[2], bh[3]);
            mma_bf16(acc[n0], ah, bl[0], bl[1]);
            mma_bf16(acc[n1], ah, bl[2], bl[3]);
            mma_bf16(acc[n0], al, bh[0], bh[1]);
            mma_bf16(acc[n1], al, bh[2], bh[3]);
        }
    }
}

#define ZACC(acc) \
    _Pragma("unroll") for (int nt_ = 0; nt_ < 8; nt_++) \
    _Pragma("unroll") for (int q_ = 0; q_ < 4; q_++) (acc)[nt_][q_] = 0.f;

// stage one 64x64 fp32 weight (k-major) into n-major bf16 hi/lo buffers
__device__ __forceinline__ void stage_w(uint32_t* dh, uint32_t* dl,
                                        const float* __restrict__ w,
                                        int tid, int nthr) {
    for (int p = tid; p < 2048; p += nthr) {
        int k2 = p >> 6, n = p & 63;
        float a0 = w[(k2 * 2) * 64 + n];
        float a1 = w[(k2 * 2 + 1) * 64 + n];
        uint32_t hp, lp;
        split2(a0, a1, hp, lp);
        dh[n * LW + k2] = hp;
        dl[n * LW + k2] = lp;
    }
}

// stage warp-owned 16 rows of a fp32 [*,64] array into sAh/sAl (hi/lo bf16)
__device__ __forceinline__ void stage_A(uint32_t* sAh, uint32_t* sAl,
                                        const float* __restrict__ src,
                                        int n0, int N, int rbase, int lane) {
#pragma unroll
    for (int it = 0; it < 8; it++) {
        int i = it * 32 + lane;
        int row = rbase + (i >> 4);
        int j = (i & 15) * 4;
        int n = n0 + row;
        float4 v = make_float4(0.f, 0.f, 0.f, 0.f);
        if (n < N) v = *(const float4*)&src[n * 64 + j];
        int o = row * LW + (j >> 1);
        uint32_t h0, l0, h1, l1;
        split2(v.x, v.y, h0, l0);
        split2(v.z, v.w, h1, l1);
        sAh[o] = h0; sAh[o + 1] = h1;
        sAl[o] = l0; sAl[o + 1] = l1;
    }
}

#define NODE_DYN_BYTES ((2 * NTS * LW + 4 * 64 * LW) * 4)
#define EDGE_DYN_BYTES ((2 * ET * LW + 4 * 64 * LW) * 4)

// ---------------------------------------------------------------------------
// Fused init + node_pre (layer 0): tensor path, 128 nodes/block.
__global__ __launch_bounds__(NNT)
void init_pre_kernel(const int* __restrict__ an, const float* __restrict__ emb,
                     const float* __restrict__ pos, const float* __restrict__ w1,
                     int N) {
    extern __shared__ uint32_t dynu[];
    uint32_t* sAh  = dynu;
    uint32_t* sAl  = sAh + NTS * LW;
    uint32_t* sB0h = sAl + NTS * LW;
    uint32_t* sB0l = sB0h + 64 * LW;
    uint32_t* sB1h = sB0l + 64 * LW;
    uint32_t* sB1l = sB1h + 64 * LW;
    __shared__ int san[NTS];

    int tid = threadIdx.x;
    int lane = tid & 31, warp = tid >> 5;
    int gr = lane >> 2, gc = lane & 3;
    int n0 = blockIdx.x * NTS;
    int rbase = warp * 16;
    uint32_t aH = smem_u32p(sAh), aL = smem_u32p(sAl);
    uint32_t b0H = smem_u32p(sB0h), b0L = smem_u32p(sB0l);
    uint32_t b1H = smem_u32p(sB1h), b1L = smem_u32p(sB1l);

    if (lane < 16) {
        int row = rbase + lane;
        int n = n0 + row;
        san[row] = (n < N) ? an[n] * 64 : 0;
    }
    for (int p = tid; p < NTS * 3; p += NNT) {
        int idx = n0 * 3 + p;
        if (idx < N * 3) { g_x[idx] = pos[idx]; g_dx[idx] = 0.f; }
    }
    stage_w(sB0h, sB0l, w1, tid, NNT);
    stage_w(sB1h, sB1l, w1 + 4096, tid, NNT);
    __syncthreads();

    // stage A = emb[an] rows; write g_h, zero g_m
#pragma unroll
    for (int it = 0; it < 8; it++) {
        int i = it * 32 + lane;
        int row = rbase + (i >> 4);
        int j = (i & 15) * 4;
        int n = n0 + row;
        float4 v = make_float4(0.f, 0.f, 0.f, 0.f);
        if (n < N) {
            v = *(const float4*)&emb[san[row] + j];
            *(float4*)&g_h[n * 64 + j] = v;
            *(float4*)&g_m[n * 64 + j] = make_float4(0.f, 0.f, 0.f, 0.f);
        }
        int o = row * LW + (j >> 1);
        uint32_t h0, l0, h1, l1;
        split2(v.x, v.y, h0, l0);
        split2(v.z, v.w, h1, l1);
        sAh[o] = h0; sAh[o + 1] = h1;
        sAl[o] = l0; sAl[o + 1] = l1;
    }
    __syncwarp();

    float acc[8][4];
    int ra = rbase + gr, rb = ra + 8;
    int na = n0 + ra, nb = n0 + rb;

    ZACC(acc);
    gemm_bf3(aH, aL, b0H, b0L, lane, rbase, acc);
#pragma unroll
    for (int nt = 0; nt < 8; nt++) {
        int col = nt * 8 + gc * 2;
        if (na < N) *(float2*)&g_Ad[na * 64 + col] = make_float2(acc[nt][0], acc[nt][1]);
        if (nb < N) *(float2*)&g_Ad[nb * 64 + col] = make_float2(acc[nt][2], acc[nt][3]);
    }
    ZACC(acc);
    gemm_bf3(aH, aL, b1H, b1L, lane, rbase, acc);
#pragma unroll
    for (int nt = 0; nt < 8; nt++) {
        int col = nt * 8 + gc * 2;
        if (na < N) *(float2*)&g_As[na * 64 + col] = make_float2(acc[nt][0], acc[nt][1]);
        if (nb < N) *(float2*)&g_As[nb * 64 + col] = make_float2(acc[nt][2], acc[nt][3]);
    }
}

// ---------------------------------------------------------------------------
// 3xBF16 edge kernel: ET=224 edges/block, 448 threads (14 warps x 16 rows).
__global__ __launch_bounds__(ENT, 2)
void edge_kernel_bf3(const int* __restrict__ src, const int* __restrict__ dst,
                     const float* __restrict__ w1r, const float* __restrict__ b1,
                     const float* __restrict__ w2,  const float* __restrict__ b2,
                     const float* __restrict__ xw1, const float* __restrict__ xb1,
                     const float* __restrict__ xw2, const float* __restrict__ xb2,
                     int E) {
    extern __shared__ uint32_t dynu[];
    uint32_t* sAh  = dynu;
    uint32_t* sAl  = sAh + ET * LW;
    uint32_t* sB0h = sAl + ET * LW;
    uint32_t* sB0l = sB0h + 64 * LW;
    uint32_t* sB1h = sB0l + 64 * LW;
    uint32_t* sB1l = sB1h + 64 * LW;
    __shared__ int   sdst[ET], ssrc[ET];
    __shared__ float sr[ET];
    __shared__ float sw1r[64], sb1v[64], sb2v[64], sxb1[64], sxw2[64];

    int tid = threadIdx.x;
    int lane = tid & 31, warp = tid >> 5;
    int gr = lane >> 2, gc = lane & 3;
    int e0 = blockIdx.x * ET;
    int rbase = warp * 16;

    uint32_t aH = smem_u32p(sAh), aL = smem_u32p(sAl);
    uint32_t b0H = smem_u32p(sB0h), b0L = smem_u32p(sB0l);
    uint32_t b1H = smem_u32p(sB1h), b1L = smem_u32p(sB1l);

    int my_d = -1;
    float xd0 = 0.f, xd1 = 0.f, xd2 = 0.f;
    if (lane < 16) {
        int row = rbase + lane;
        int eg = e0 + row;
        int s = 0;
        if (eg < E) {
            s = src[eg]; my_d = dst[eg];
            xd0 = g_x[s * 3 + 0] - g_x[my_d * 3 + 0];
            xd1 = g_x[s * 3 + 1] - g_x[my_d * 3 + 1];
            xd2 = g_x[s * 3 + 2] - g_x[my_d * 3 + 2];
        }
        ssrc[row] = s; sdst[row] = my_d;
        sr[row] = sqrtf(xd0 * xd0 + xd1 * xd1 + xd2 * xd2);
    }
    if (tid >= 256 && tid < 320) {
        int j = tid - 256;
        sw1r[j] = w1r[j]; sb1v[j] = b1[j]; sb2v[j] = b2[j];
        sxb1[j] = xb1[j]; sxw2[j] = xw2[j];
    }
    stage_w(sB0h, sB0l, w2, tid, ENT);
    stage_w(sB1h, sB1l, xw1, tid, ENT);
    __syncthreads();   // the ONLY block barrier

    // warp-local t1 staging
#pragma unroll
    for (int it = 0; it < 8; it++) {
        int i = it * 32 + lane;
        int row = rbase + (i >> 4);
        int j = (i & 15) * 4;
        int d = sdst[row];
        int dd = d < 0 ? 0 : d;
        int s  = ssrc[row];
        float4 ad = *(const float4*)&g_Ad[dd * 64 + j];
        float4 as = *(const float4*)&g_As[s * 64 + j];
        float r = sr[row];
        float t0 = silu_f(ad.x + as.x + r * sw1r[j + 0] + sb1v[j + 0]);
        float t1 = silu_f(ad.y + as.y + r * sw1r[j + 1] + sb1v[j + 1]);
        float t2 = silu_f(ad.z + as.z + r * sw1r[j + 2] + sb1v[j + 2]);
        float t3 = silu_f(ad.w + as.w + r * sw1r[j + 3] + sb1v[j + 3]);
        int o = row * LW + (j >> 1);
        uint32_t h0, l0, h1, l1;
        split2(t0, t1, h0, l0);
        split2(t2, t3, h1, l1);
        sAh[o] = h0; sAh[o + 1] = h1;
        sAl[o] = l0; sAl[o + 1] = l1;
    }
    __syncwarp();

    float acc[8][4];
    ZACC(acc);
    gemm_bf3(aH, aL, b0H, b0L, lane, rbase, acc);   // GEMM1: t1 @ w2

    // epilogue 1: m = silu(D + b2); direct red.v2 scatter; rewrite own A rows
    {
        int ra = rbase + gr, rb = ra + 8;
        int da = sdst[ra], db = sdst[rb];
#pragma unroll
        for (int nt = 0; nt < 8; nt++) {
            int col = nt * 8 + gc * 2;
            float m00 = silu_f(acc[nt][0] + sb2v[col]);
            float m01 = silu_f(acc[nt][1] + sb2v[col + 1]);
            float m10 = silu_f(acc[nt][2] + sb2v[col]);
            float m11 = silu_f(acc[nt][3] + sb2v[col + 1]);
            if (da >= 0) red_add_v2(&g_m[da * 64 + col], m00, m01);
            if (db >= 0) red_add_v2(&g_m[db * 64 + col], m10, m11);
            int oa = ra * LW + nt * 4 + gc, ob = rb * LW + nt * 4 + gc;
            uint32_t hA, lA, hB, lB;
            split2(m00, m01, hA, lA);
            split2(m10, m11, hB, lB);
            sAh[oa] = hA; sAl[oa] = lA;
            sAh[ob] = hB; sAl[ob] = lB;
        }
    }
    __syncwarp();

    ZACC(acc);
    gemm_bf3(aH, aL, b1H, b1L, lane, rbase, acc);   // GEMM2: m @ xw1

    // epilogue 2: W = silu(D + xb1) . xw2 + xb2 ; broadcast via shfl
    {
        float Wv0 = 0.f, Wv1 = 0.f;
#pragma unroll
        for (int nt = 0; nt < 8; nt++) {
            int col = nt * 8 + gc * 2;
            Wv0 += silu_f(acc[nt][0] + sxb1[col]) * sxw2[col]
                 + silu_f(acc[nt][1] + sxb1[col + 1]) * sxw2[col + 1];
            Wv1 += silu_f(acc[nt][2] + sxb1[col]) * sxw2[col]
                 + silu_f(acc[nt][3] + sxb1[col + 1]) * sxw2[col + 1];
        }
#pragma unroll
        for (int off = 1; off <= 2; off <<= 1) {
            Wv0 += __shfl_xor_sync(0xffffffffu, Wv0, off);
            Wv1 += __shfl_xor_sync(0xffffffffu, Wv1, off);
        }
        // row l (<8) W is in lane 4l (Wv0); row l>=8 in lane 4(l-8) (Wv1)
        int srcl = (lane & 7) << 2;
        float W0 = __shfl_sync(0xffffffffu, Wv0, srcl);
        float W1 = __shfl_sync(0xffffffffu, Wv1, srcl);
        if (lane < 16 && my_d >= 0) {
            float W = ((lane < 8) ? W0 : W1) + __ldg(xb2);
            atomicAdd(&g_dx[my_d * 3 + 0], W * xd0);
            atomicAdd(&g_dx[my_d * 3 + 1], W * xd1);
            atomicAdd(&g_dx[my_d * 3 + 2], W * xd2);
        }
    }
}

// ---------------------------------------------------------------------------
// Fused node_update + node_pre(next layer), tensor path. Zeroes m/dx.
__global__ __launch_bounds__(NNT)
void update_pre_kernel(const float* __restrict__ hw1, const float* __restrict__ hb1,
                       const float* __restrict__ hw2, const float* __restrict__ hb2,
                       const float* __restrict__ ew1n, int N) {
    extern __shared__ uint32_t dynu[];
    uint32_t* sAh  = dynu;
    uint32_t* sAl  = sAh + NTS * LW;
    uint32_t* sB0h = sAl + NTS * LW;
    uint32_t* sB0l = sB0h + 64 * LW;
    uint32_t* sB1h = sB0l + 64 * LW;
    uint32_t* sB1l = sB1h + 64 * LW;
    __shared__ float shb1[64], shb2[64];

    int tid = threadIdx.x;
    int lane = tid & 31, warp = tid >> 5;
    int gr = lane >> 2, gc = lane & 3;
    int n0 = blockIdx.x * NTS;
    int rbase = warp * 16;
    uint32_t aH = smem_u32p(sAh), aL = smem_u32p(sAl);
    uint32_t b0H = smem_u32p(sB0h), b0L = smem_u32p(sB0l);
    uint32_t b1H = smem_u32p(sB1h), b1L = smem_u32p(sB1l);

    if (tid < 64) { shb1[tid] = hb1[tid]; shb2[tid] = hb2[tid]; }
    stage_w(sB0h, sB0l, hw1, tid, NNT);
    stage_w(sB1h, sB1l, hw1 + 4096, tid, NNT);
    __syncthreads();

    float acc[8][4];
    int ra = rbase + gr, rb = ra + 8;
    int na = n0 + ra, nb = n0 + rb;

    // GEMM1: h @ hw1a
    stage_A(sAh, sAl, g_h, n0, N, rbase, lane);
    __syncwarp();
    ZACC(acc);
    gemm_bf3(aH, aL, b0H, b0L, lane, rbase, acc);
    __syncwarp();

    // GEMM2: m @ hw1b (accumulate); read + zero m
#pragma unroll
    for (int it = 0; it < 8; it++) {
        int i = it * 32 + lane;
        int row = rbase + (i >> 4);
        int j = (i & 15) * 4;
        int n = n0 + row;
        float4 v = make_float4(0.f, 0.f, 0.f, 0.f);
        if (n < N) {
            v = *(const float4*)&g_m[n * 64 + j];
            *(float4*)&g_m[n * 64 + j] = make_float4(0.f, 0.f, 0.f, 0.f);
        }
        int o = row * LW + (j >> 1);
        uint32_t h0, l0, h1, l1;
        split2(v.x, v.y, h0, l0);
        split2(v.z, v.w, h1, l1);
        sAh[o] = h0; sAh[o + 1] = h1;
        sAl[o] = l0; sAl[o + 1] = l1;
    }
    __syncwarp();
    gemm_bf3(aH, aL, b1H, b1L, lane, rbase, acc);

    // epilogue: t = silu(acc + hb1) -> stage own rows
#pragma unroll
    for (int nt = 0; nt < 8; nt++) {
        int col = nt * 8 + gc * 2;
        float t00 = silu_f(acc[nt][0] + shb1[col]);
        float t01 = silu_f(acc[nt][1] + shb1[col + 1]);
        float t10 = silu_f(acc[nt][2] + shb1[col]);
        float t11 = silu_f(acc[nt][3] + shb1[col + 1]);
        int oa = ra * LW + nt * 4 + gc, ob = rb * LW + nt * 4 + gc;
        uint32_t hA, lA, hB, lB;
        split2(t00, t01, hA, lA);
        split2(t10, t11, hB, lB);
        sAh[oa] = hA; sAl[oa] = lA;
        sAh[ob] = hB; sAl[ob] = lB;
    }
    __syncthreads();               // all warps done with hw1a/hw1b
    stage_w(sB0h, sB0l, hw2, tid, NNT);
    stage_w(sB1h, sB1l, ew1n, tid, NNT);
    __syncthreads();

    // GEMM3: t @ hw2
    ZACC(acc);
    gemm_bf3(aH, aL, b0H, b0L, lane, rbase, acc);

    // epilogue: h_new = h_old + acc + hb2 -> g_h, stage for GEMM4/5
#pragma unroll
    for (int nt = 0; nt < 8; nt++) {
        int col = nt * 8 + gc * 2;
        float h00 = 0.f, h01 = 0.f, h10 = 0.f, h11 = 0.f;
        if (na < N) {
            float2 o = *(const float2*)&g_h[na * 64 + col];
            h00 = o.x + acc[nt][0] + shb2[col];
            h01 = o.y + acc[nt][1] + shb2[col + 1];
            *(float2*)&g_h[na * 64 + col] = make_float2(h00, h01);
        }
        if (nb < N) {
            float2 o = *(const float2*)&g_h[nb * 64 + col];
            h10 = o.x + acc[nt][2] + shb2[col];
            h11 = o.y + acc[nt][3] + shb2[col + 1];
            *(float2*)&g_h[nb * 64 + col] = make_float2(h10, h11);
        }
        int oa = ra * LW + nt * 4 + gc, ob = rb * LW + nt * 4 + gc;
        uint32_t hA, lA, hB, lB;
        split2(h00, h01, hA, lA);
        split2(h10, h11, hB, lB);
        sAh[oa] = hA; sAl[oa] = lA;
        sAh[ob] = hB; sAl[ob] = lB;
    }
    // x update (block-owned rows)
    for (int p = tid; p < NTS * 3; p += NNT) {
        int idx = n0 * 3 + p;
        if (idx < N * 3) {
            g_x[idx] = g_x[idx] + g_dx[idx];
            g_dx[idx] = 0.f;
        }
    }
    __syncthreads();               // hw2 reads done
    stage_w(sB0h, sB0l, ew1n + 4096, tid, NNT);

    // GEMM4: h_new @ ew1a -> g_Ad  (B1 staged earlier)
    ZACC(acc);
    gemm_bf3(aH, aL, b1H, b1L, lane, rbase, acc);
#pragma unroll
    for (int nt = 0; nt < 8; nt++) {
        int col = nt * 8 + gc * 2;
        if (na < N) *(float2*)&g_Ad[na * 64 + col] = make_float2(acc[nt][0], acc[nt][1]);
        if (nb < N) *(float2*)&g_Ad[nb * 64 + col] = make_float2(acc[nt][2], acc[nt][3]);
    }
    __syncthreads();               // B0 restage (ew1b) visible

    // GEMM5: h_new @ ew1b -> g_As
    ZACC(acc);
    gemm_bf3(aH, aL, b0H, b0L, lane, rbase, acc);
#pragma unroll
    for (int nt = 0; nt < 8; nt++) {
        int col = nt * 8 + gc * 2;
        if (na < N) *(float2*)&g_As[na * 64 + col] = make_float2(acc[nt][0], acc[nt][1]);
        if (nb < N) *(float2*)&g_As[nb * 64 + col] = make_float2(acc[nt][2], acc[nt][3]);
    }
}

// ---------------------------------------------------------------------------
// Final node update (tensor path): writes h, x into output buffer.
__global__ __launch_bounds__(NNT)
void final_update_kernel(const float* __restrict__ hw1, const float* __restrict__ hb1,
                         const float* __restrict__ hw2, const float* __restrict__ hb2,
                         float* __restrict__ outh, float* __restrict__ outx, int N) {
    extern __shared__ uint32_t dynu[];
    uint32_t* sAh  = dynu;
    uint32_t* sAl  = sAh + NTS * LW;
    uint32_t* sB0h = sAl + NTS * LW;
    uint32_t* sB0l = sB0h + 64 * LW;
    uint32_t* sB1h = sB0l + 64 * LW;
    uint32_t* sB1l = sB1h + 64 * LW;
    __shared__ float shb1[64], shb2[64];

    int tid = threadIdx.x;
    int lane = tid & 31, warp = tid >> 5;
    int gr = lane >> 2, gc = lane & 3;
    int n0 = blockIdx.x * NTS;
    int rbase = warp * 16;
    uint32_t aH = smem_u32p(sAh), aL = smem_u32p(sAl);
    uint32_t b0H = smem_u32p(sB0h), b0L = smem_u32p(sB0l);
    uint32_t b1H = smem_u32p(sB1h), b1L = smem_u32p(sB1l);

    if (tid < 64) { shb1[tid] = hb1[tid]; shb2[tid] = hb2[tid]; }
    stage_w(sB0h, sB0l, hw1, tid, NNT);
    stage_w(sB1h, sB1l, hw1 + 4096, tid, NNT);
    __syncthreads();

    float acc[8][4];
    int ra = rbase + gr, rb = ra + 8;
    int na = n0 + ra, nb = n0 + rb;

    stage_A(sAh, sAl, g_h, n0, N, rbase, lane);
    __syncwarp();
    ZACC(acc);
    gemm_bf3(aH, aL, b0H, b0L, lane, rbase, acc);
    __syncwarp();

    stage_A(sAh, sAl, g_m, n0, N, rbase, lane);
    __syncwarp();
    gemm_bf3(aH, aL, b1H, b1L, lane, rbase, acc);

#pragma unroll
    for (int nt = 0; nt < 8; nt++) {
        int col = nt * 8 + gc * 2;
        float t00 = silu_f(acc[nt][0] + shb1[col]);
        float t01 = silu_f(acc[nt][1] + shb1[col + 1]);
        float t10 = silu_f(acc[nt][2] + shb1[col]);
        float t11 = silu_f(acc[nt][3] + shb1[col + 1]);
        int oa = ra * LW + nt * 4 + gc, ob = rb * LW + nt * 4 + gc;
        uint32_t hA, lA, hB, lB;
        split2(t00, t01, hA, lA);
        split2(t10, t11, hB, lB);
        sAh[oa] = hA; sAl[oa] = lA;
        sAh[ob] = hB; sAl[ob] = lB;
    }
    __syncthreads();
    stage_w(sB0h, sB0l, hw2, tid, NNT);
    __syncthreads();

    ZACC(acc);
    gemm_bf3(aH, aL, b0H, b0L, lane, rbase, acc);

#pragma unroll
    for (int nt = 0; nt < 8; nt++) {
        int col = nt * 8 + gc * 2;
        if (na < N) {
            float2 o = *(const float2*)&g_h[na * 64 + col];
            *(float2*)&outh[na * 64 + col] =
                make_float2(o.x + acc[nt][0] + shb2[col],
                            o.y + acc[nt][1] + shb2[col + 1]);
        }
        if (nb < N) {
            float2 o = *(const float2*)&g_h[nb * 64 + col];
            *(float2*)&outh[nb * 64 + col] =
                make_float2(o.x + acc[nt][2] + shb2[col],
                            o.y + acc[nt][3] + shb2[col + 1]);
        }
    }
    for (int p = tid; p < NTS * 3; p += NNT) {
        int idx = n0 * 3 + p;
        if (idx < N * 3) outx[idx] = g_x[idx] + g_dx[idx];
    }
}

// ---------------------------------------------------------------------------
extern "C" void kernel_launch(void* const* d_in, const int* in_sizes, int n_in,
                              void* d_out, int out_size) {
    const int*   an   = (const int*)d_in[0];
    const float* pos  = (const float*)d_in[1];
    const int*   eidx = (const int*)d_in[2];
    // d_in[3] = edge_attr (unused by reference)
    const float* emb  = (const float*)d_in[4];
    const float* e_w1 = (const float*)d_in[5];
    const float* e_b1 = (const float*)d_in[6];
    const float* e_w2 = (const float*)d_in[7];
    const float* e_b2 = (const float*)d_in[8];
    const float* h_w1 = (const float*)d_in[9];
    const float* h_b1 = (const float*)d_in[10];
    const float* h_w2 = (const float*)d_in[11];
    const float* h_b2 = (const float*)d_in[12];
    const float* x_w1 = (const float*)d_in[13];
    const float* x_b1 = (const float*)d_in[14];
    const float* x_w2 = (const float*)d_in[15];
    const float* x_b2 = (const float*)d_in[16];

    int N = in_sizes[0];
    int E = in_sizes[2] / 2;
    float* out = (float*)d_out;

    cudaFuncSetAttribute(edge_kernel_bf3,
                         cudaFuncAttributeMaxDynamicSharedMemorySize, EDGE_DYN_BYTES);
    cudaFuncSetAttribute(init_pre_kernel,
                         cudaFuncAttributeMaxDynamicSharedMemorySize, NODE_DYN_BYTES);
    cudaFuncSetAttribute(update_pre_kernel,
                         cudaFuncAttributeMaxDynamicSharedMemorySize, NODE_DYN_BYTES);
    cudaFuncSetAttribute(final_update_kernel,
                         cudaFuncAttributeMaxDynamicSharedMemorySize, NODE_DYN_BYTES);

    int nodeBlocks = (N + NTS - 1) / NTS;
    int edgeBlocks = (E + ET - 1) / ET;

    init_pre_kernel<<<nodeBlocks, NNT, NODE_DYN_BYTES>>>(an, emb, pos, e_w1, N);

    edge_kernel_bf3<<<edgeBlocks, ENT, EDGE_DYN_BYTES>>>(
        eidx, eidx + E,
        e_w1 + 128 * 64, e_b1,
        e_w2, e_b2,
        x_w1, x_b1,
        x_w2, x_b2, E);

    update_pre_kernel<<<nodeBlocks, NNT, NODE_DYN_BYTES>>>(
        h_w1, h_b1, h_w2, h_b2,
        e_w1 + 129 * 64, N);

    edge_kernel_bf3<<<edgeBlocks, ENT, EDGE_DYN_BYTES>>>(
        eidx, eidx + E,
        e_w1 + 129 * 64 + 128 * 64, e_b1 + 64,
        e_w2 + 4096, e_b2 + 64,
        x_w1 + 4096, x_b1 + 64,
        x_w2 + 64, x_b2 + 1, E);

    final_update_kernel<<<nodeBlocks, NNT, NODE_DYN_BYTES>>>(
        h_w1 + 128 * 64, h_b1 + 64,
        h_w2 + 4096, h_b2 + 64,
        out, out + (size_t)N * 64, N);
}